// round 3
// baseline (speedup 1.0000x reference)
#include <cuda_runtime.h>
#include <cstdint>

// ---------------- scratch (static device globals; no allocation) ----------------
__device__ float g_Q[128 * 8 * 128 * 64];    // (bs,H,nq,hd)   32 MB
__device__ float g_K[128 * 8 * 512 * 64];    // (bs,H,ne,hd)  128 MB
__device__ float g_V[128 * 8 * 512 * 64];    // (bs,H,ne,hd)  128 MB
__device__ float g_Att[128 * 128 * 512];     // (bs,nq,E)      32 MB
__device__ int   g_mask_kind;                // 0=int32, 1=uint8, 2=float32

// ---------------- mask dtype handling ----------------
__device__ __forceinline__ bool mask_true(const void* p, size_t i, int kind) {
    if (kind == 1) return ((const unsigned char*)p)[i] != 0;
    if (kind == 0) return ((const int*)p)[i] != 0;
    return ((const float*)p)[i] != 0.0f;
}

__global__ void detect_mask_kernel(const unsigned int* __restrict__ pm) {
    if (threadIdx.x == 0) {
        bool is_i32 = true, is_f32 = true;
        for (int i = 0; i < 64; i++) {
            unsigned int w = pm[i];
            if (w != 0u && w != 1u) is_i32 = false;
            if (w != 0u && w != 0x3F800000u) is_f32 = false;
        }
        g_mask_kind = is_i32 ? 0 : (is_f32 ? 2 : 1);
    }
}

// ---------------- K1: QKV projection GEMM ----------------
// MODE 0: Q   — M=16384 (rows b*512+q, q<128), N=512,  W pre-offset 0
// MODE 1: K/V — M=65536,                        N=1024, W pre-offset 512 rows
template <int MODE>
__global__ __launch_bounds__(256) void qkv_gemm(const float* __restrict__ A,
                                                const float* __restrict__ W) {
    __shared__ float As[16][128];
    __shared__ float Bs[16][128];
    const int tid = threadIdx.x;
    const int bm = blockIdx.y << 7;
    const int bn = blockIdx.x << 7;
    const int tm = (tid >> 4) << 3;
    const int tn = (tid & 15) << 3;

    float acc[8][8];
#pragma unroll
    for (int i = 0; i < 8; i++)
#pragma unroll
        for (int j = 0; j < 8; j++) acc[i][j] = 0.f;

    const int r = tid >> 1;             // tile row this thread loads
    int arow = bm + r;
    if (MODE == 0) arow = ((arow >> 7) << 9) | (arow & 127);  // b*512 + q
    const float* Aptr = A + (size_t)arow * 512;
    const float* Wptr = W + (size_t)(bn + r) * 512;
    const int c0 = (tid & 1) << 3;

    for (int k0 = 0; k0 < 512; k0 += 16) {
#pragma unroll
        for (int i = 0; i < 2; i++) {
            const int c = c0 + (i << 2);
            float4 va = *(const float4*)(Aptr + k0 + c);
            As[c + 0][r] = va.x; As[c + 1][r] = va.y;
            As[c + 2][r] = va.z; As[c + 3][r] = va.w;
            float4 vb = *(const float4*)(Wptr + k0 + c);
            Bs[c + 0][r] = vb.x; Bs[c + 1][r] = vb.y;
            Bs[c + 2][r] = vb.z; Bs[c + 3][r] = vb.w;
        }
        __syncthreads();
#pragma unroll
        for (int kk = 0; kk < 16; kk++) {
            float a[8], bvec[8];
            *(float4*)&a[0]    = *(const float4*)&As[kk][tm];
            *(float4*)&a[4]    = *(const float4*)&As[kk][tm + 4];
            *(float4*)&bvec[0] = *(const float4*)&Bs[kk][tn];
            *(float4*)&bvec[4] = *(const float4*)&Bs[kk][tn + 4];
#pragma unroll
            for (int i = 0; i < 8; i++)
#pragma unroll
                for (int j = 0; j < 8; j++) acc[i][j] += a[i] * bvec[j];
        }
        __syncthreads();
    }

    const int n0 = bn + tn;
    if (MODE == 0) {
        const int h = n0 >> 6, d = n0 & 63;
#pragma unroll
        for (int i = 0; i < 8; i++) {
            const int m = bm + tm + i;
            const int b = m >> 7, e = m & 127;
            float* dst = g_Q + (size_t)((((b << 3) + h) << 7) + e) * 64 + d;
            *(float4*)dst = make_float4(acc[i][0] * 0.125f, acc[i][1] * 0.125f,
                                        acc[i][2] * 0.125f, acc[i][3] * 0.125f);
            *(float4*)(dst + 4) = make_float4(acc[i][4] * 0.125f, acc[i][5] * 0.125f,
                                              acc[i][6] * 0.125f, acc[i][7] * 0.125f);
        }
    } else {
        float* base = (n0 & 512) ? g_V : g_K;
        const int h = (n0 >> 6) & 7, d = n0 & 63;
#pragma unroll
        for (int i = 0; i < 8; i++) {
            const int m = bm + tm + i;
            const int b = m >> 9, e = m & 511;
            float* dst = base + (size_t)((((b << 3) + h) << 9) + e) * 64 + d;
            *(float4*)dst       = make_float4(acc[i][0], acc[i][1], acc[i][2], acc[i][3]);
            *(float4*)(dst + 4) = make_float4(acc[i][4], acc[i][5], acc[i][6], acc[i][7]);
        }
    }
}

// ---------------- K2: attention per (b, h, 32-query chunk) ----------------
#define ATT_SMEM_FLOATS (32 * 68 + 512 * 68 + 32 * 516)
#define ATT_SMEM_BYTES  (ATT_SMEM_FLOATS * 4)

__global__ __launch_bounds__(256) void attn_kernel(const void* __restrict__ pre_mask,
                                                   const float* __restrict__ diff_mask) {
    extern __shared__ float sm[];
    float* Qs = sm;                        // [32][68]
    float* KV = sm + 32 * 68;              // [512][68]  (K, then reused for V)
    float* Ss = sm + 32 * 68 + 512 * 68;   // [32][516]

    const int tid = threadIdx.x;
    const int qc = blockIdx.x, h = blockIdx.y, b = blockIdx.z;
    const int bh = (b << 3) + h;
    const float* Qg = g_Q + ((size_t)bh * 128 + qc * 32) * 64;
    const float* Kg = g_K + (size_t)bh * 512 * 64;
    const float* Vg = g_V + (size_t)bh * 512 * 64;
    const int kind = g_mask_kind;
    const size_t mrow_base = ((size_t)b * 128 + qc * 32) * 512;
    const float NEG_INF = __int_as_float(0xff800000u);

    // load Q (32x64) and K (512x64), d-contiguous
#pragma unroll
    for (int i = 0; i < 2; i++) {
        const int f = (tid << 1) + i;
        const int q = f >> 4, d = (f & 15) << 2;
        *(float4*)&Qs[q * 68 + d] = *(const float4*)(Qg + (q << 6) + d);
    }
#pragma unroll
    for (int i = 0; i < 32; i++) {
        const int f = (i << 8) + tid;
        const int key = f >> 4, d = (f & 15) << 2;
        *(float4*)&KV[key * 68 + d] = *(const float4*)(Kg + (key << 6) + d);
    }
    __syncthreads();

    // S = Q @ K^T (32x512), 8x8 per thread, dot over d
    {
        const int q0 = (tid >> 6) << 3;
        const int j0 = (tid & 63) << 3;
        float acc[8][8];
#pragma unroll
        for (int i = 0; i < 8; i++)
#pragma unroll
            for (int j = 0; j < 8; j++) acc[i][j] = 0.f;
#pragma unroll 8
        for (int dd = 0; dd < 64; dd += 2) {
            float2 av[8], bv[8];
#pragma unroll
            for (int i = 0; i < 8; i++) av[i] = *(const float2*)&Qs[(q0 + i) * 68 + dd];
#pragma unroll
            for (int j = 0; j < 8; j++) bv[j] = *(const float2*)&KV[(j0 + j) * 68 + dd];
#pragma unroll
            for (int i = 0; i < 8; i++)
#pragma unroll
                for (int j = 0; j < 8; j++)
                    acc[i][j] += av[i].x * bv[j].x + av[i].y * bv[j].y;
        }
#pragma unroll
        for (int i = 0; i < 8; i++) {
            const int q = q0 + i;
            const size_t mb = mrow_base + (size_t)q * 512 + j0;
#pragma unroll
            for (int j = 0; j < 8; j++) {
                const bool pm = mask_true(pre_mask, mb + j, kind);
                Ss[q * 516 + j0 + j] = pm ? NEG_INF : acc[i][j];
            }
        }
    }
    __syncthreads();

    // softmax + diff-mask renorm: w = e*dm / (sum(e*dm) + 1e-8*sum(e)); all-masked -> 0
    {
        const int q = tid >> 3;
        const int l8 = tid & 7;
        float* row = Ss + q * 516;
        const float* drow = diff_mask + mrow_base + (size_t)q * 512;
        float m = NEG_INF;
#pragma unroll 8
        for (int i = 0; i < 64; i++) m = fmaxf(m, row[l8 + (i << 3)]);
#pragma unroll
        for (int o = 4; o > 0; o >>= 1) m = fmaxf(m, __shfl_xor_sync(0xffffffffu, m, o));
        float E = 0.f, D = 0.f;
#pragma unroll 8
        for (int i = 0; i < 64; i++) {
            const int j = l8 + (i << 3);
            const float s = row[j];
            const float e = (s == NEG_INF) ? 0.f : __expf(s - m);
            const float wd = e * drow[j];
            E += e; D += wd;
            row[j] = wd;
        }
#pragma unroll
        for (int o = 4; o > 0; o >>= 1) {
            E += __shfl_xor_sync(0xffffffffu, E, o);
            D += __shfl_xor_sync(0xffffffffu, D, o);
        }
        const float inv = (E > 0.f) ? 1.f / (D + 1e-8f * E) : 0.f;
#pragma unroll 8
        for (int i = 0; i < 64; i++) row[l8 + (i << 3)] *= inv;
    }
    __syncthreads();

    // load V over K's smem
#pragma unroll
    for (int i = 0; i < 32; i++) {
        const int f = (i << 8) + tid;
        const int key = f >> 4, d = (f & 15) << 2;
        *(float4*)&KV[key * 68 + d] = *(const float4*)(Vg + (key << 6) + d);
    }
    __syncthreads();

    // O = W @ V (32x64): each thread 2 q-rows x 4 d-cols
    {
        const int qp = (tid >> 4) << 1;
        const int d0 = (tid & 15) << 2;
        float a0 = 0, a1 = 0, a2 = 0, a3 = 0, b0 = 0, b1 = 0, b2 = 0, b3 = 0;
        const float* s0p = Ss + qp * 516;
        const float* s1p = s0p + 516;
#pragma unroll 4
        for (int j = 0; j < 512; j++) {
            const float s0 = s0p[j], s1 = s1p[j];
            const float4 v = *(const float4*)&KV[j * 68 + d0];
            a0 += s0 * v.x; a1 += s0 * v.y; a2 += s0 * v.z; a3 += s0 * v.w;
            b0 += s1 * v.x; b1 += s1 * v.y; b2 += s1 * v.z; b3 += s1 * v.w;
        }
        const size_t ob = ((size_t)b * 128 + qc * 32 + qp) * 512 + (h << 6) + d0;
        *(float4*)&g_Att[ob]       = make_float4(a0, a1, a2, a3);
        *(float4*)&g_Att[ob + 512] = make_float4(b0, b1, b2, b3);
    }
}

// ---------------- K3: output projection + bias + post-mask ----------------
__global__ __launch_bounds__(256) void out_gemm(const float* __restrict__ W,
                                                const float* __restrict__ bias,
                                                const void* __restrict__ post_mask,
                                                float* __restrict__ out) {
    __shared__ float As[16][128];
    __shared__ float Bs[16][128];
    const int tid = threadIdx.x;
    const int bm = blockIdx.y << 7;
    const int bn = blockIdx.x << 7;
    const int tm = (tid >> 4) << 3;
    const int tn = (tid & 15) << 3;

    float acc[8][8];
#pragma unroll
    for (int i = 0; i < 8; i++)
#pragma unroll
        for (int j = 0; j < 8; j++) acc[i][j] = 0.f;

    const int r = tid >> 1;
    const float* Aptr = g_Att + (size_t)(bm + r) * 512;
    const float* Wptr = W + (size_t)(bn + r) * 512;
    const int c0 = (tid & 1) << 3;

    for (int k0 = 0; k0 < 512; k0 += 16) {
#pragma unroll
        for (int i = 0; i < 2; i++) {
            const int c = c0 + (i << 2);
            float4 va = *(const float4*)(Aptr + k0 + c);
            As[c + 0][r] = va.x; As[c + 1][r] = va.y;
            As[c + 2][r] = va.z; As[c + 3][r] = va.w;
            float4 vb = *(const float4*)(Wptr + k0 + c);
            Bs[c + 0][r] = vb.x; Bs[c + 1][r] = vb.y;
            Bs[c + 2][r] = vb.z; Bs[c + 3][r] = vb.w;
        }
        __syncthreads();
#pragma unroll
        for (int kk = 0; kk < 16; kk++) {
            float a[8], bvec[8];
            *(float4*)&a[0]    = *(const float4*)&As[kk][tm];
            *(float4*)&a[4]    = *(const float4*)&As[kk][tm + 4];
            *(float4*)&bvec[0] = *(const float4*)&Bs[kk][tn];
            *(float4*)&bvec[4] = *(const float4*)&Bs[kk][tn + 4];
#pragma unroll
            for (int i = 0; i < 8; i++)
#pragma unroll
                for (int j = 0; j < 8; j++) acc[i][j] += a[i] * bvec[j];
        }
        __syncthreads();
    }

    const int kind = g_mask_kind;
    float bb[8];
#pragma unroll
    for (int j = 0; j < 8; j++) bb[j] = __ldg(&bias[bn + tn + j]);
#pragma unroll
    for (int i = 0; i < 8; i++) {
        const int m = bm + tm + i;
        const bool pm = mask_true(post_mask, m, kind);   // index b*128+q == m
        float* dst = out + (size_t)m * 512 + bn + tn;
        if (pm) {
            *(float4*)dst       = make_float4(0.f, 0.f, 0.f, 0.f);
            *(float4*)(dst + 4) = make_float4(0.f, 0.f, 0.f, 0.f);
        } else {
            *(float4*)dst = make_float4(acc[i][0] + bb[0], acc[i][1] + bb[1],
                                        acc[i][2] + bb[2], acc[i][3] + bb[3]);
            *(float4*)(dst + 4) = make_float4(acc[i][4] + bb[4], acc[i][5] + bb[5],
                                              acc[i][6] + bb[6], acc[i][7] + bb[7]);
        }
    }
}

// ---------------- launcher ----------------
extern "C" void kernel_launch(void* const* d_in, const int* in_sizes, int n_in,
                              void* d_out, int out_size) {
    (void)in_sizes; (void)n_in; (void)out_size;
    const float* entities  = (const float*)d_in[0];
    const void*  pre_mask  = d_in[1];
    const float* diff_mask = (const float*)d_in[2];
    const void*  post_mask = d_in[3];
    const float* W_in      = (const float*)d_in[4];
    const float* W_out     = (const float*)d_in[5];
    const float* b_out     = (const float*)d_in[6];
    float* out = (float*)d_out;

    cudaFuncSetAttribute(attn_kernel, cudaFuncAttributeMaxDynamicSharedMemorySize,
                         ATT_SMEM_BYTES);

    detect_mask_kernel<<<1, 32>>>((const unsigned int*)pre_mask);
    qkv_gemm<0><<<dim3(4, 128), 256>>>(entities, W_in);                 // Q
    qkv_gemm<1><<<dim3(8, 512), 256>>>(entities, W_in + 512 * 512);     // K,V
    attn_kernel<<<dim3(4, 8, 128), 256, ATT_SMEM_BYTES>>>(pre_mask, diff_mask);
    out_gemm<<<dim3(4, 128), 256>>>(W_out, b_out, post_mask, out);
}

// round 4
// speedup vs baseline: 1.5291x; 1.5291x over previous
#include <cuda_runtime.h>
#include <cstdint>

// ---------------- scratch (static device globals; no allocation) ----------------
__device__ float g_Q[128 * 8 * 128 * 64];    // (bs,H,nq,hd)   32 MB
__device__ float g_K[128 * 8 * 512 * 64];    // (bs,H,ne,hd)  128 MB
__device__ float g_V[128 * 8 * 512 * 64];    // (bs,H,ne,hd)  128 MB
__device__ float g_Att[128 * 128 * 512];     // (bs,nq,E)      32 MB
__device__ int   g_mask_kind;                // 0=int32, 1=uint8, 2=float32

// ---------------- mask dtype handling ----------------
__device__ __forceinline__ bool mask_true(const void* p, size_t i, int kind) {
    if (kind == 1) return ((const unsigned char*)p)[i] != 0;
    if (kind == 0) return ((const int*)p)[i] != 0;
    return ((const float*)p)[i] != 0.0f;
}

__global__ void detect_mask_kernel(const unsigned int* __restrict__ pm) {
    if (threadIdx.x == 0) {
        bool is_i32 = true, is_f32 = true;
        for (int i = 0; i < 64; i++) {
            unsigned int w = pm[i];
            if (w != 0u && w != 1u) is_i32 = false;
            if (w != 0u && w != 0x3F800000u) is_f32 = false;
        }
        g_mask_kind = is_i32 ? 0 : (is_f32 ? 2 : 1);
    }
}

// ---------------- tf32 helpers ----------------
__device__ __forceinline__ uint32_t f2tf32(float f) {
    uint32_t r;
    asm("cvt.rna.tf32.f32 %0, %1;" : "=r"(r) : "f"(f));
    return r;
}

__device__ __forceinline__ void mma_tf32(float* c, const uint32_t* a,
                                         uint32_t b0, uint32_t b1) {
    asm volatile(
        "mma.sync.aligned.m16n8k8.row.col.f32.tf32.tf32.f32 "
        "{%0,%1,%2,%3}, {%4,%5,%6,%7}, {%8,%9}, {%0,%1,%2,%3};"
        : "+f"(c[0]), "+f"(c[1]), "+f"(c[2]), "+f"(c[3])
        : "r"(a[0]), "r"(a[1]), "r"(a[2]), "r"(a[3]), "r"(b0), "r"(b1));
}

// ---------------- tensor-core GEMM:  C[M][N] = A[M][512] @ W[N][512]^T ----------------
// MODE 0: Q projection   (M=16384 logical rows b*128+q, A rows b*512+q; N=512; -> g_Q, x0.125)
// MODE 1: K/V projection (M=65536; N=1024; -> g_K / g_V)
// MODE 2: out projection (M=16384, A = g_Att; N=512; -> out, +bias, post-mask)
// Block 128x128, 256 threads = 8 warps (4 along M x 2 along N), warp tile 32x64.
#define KPAD 20

template <int MODE>
__global__ __launch_bounds__(256) void gemm_tf32(const float* __restrict__ Ain,
                                                 const float* __restrict__ W,
                                                 const float* __restrict__ bias,
                                                 const void* __restrict__ post_mask,
                                                 float* __restrict__ out) {
    __shared__ uint32_t As[128 * KPAD];
    __shared__ uint32_t Bs[128 * KPAD];

    const int tid  = threadIdx.x;
    const int lane = tid & 31;
    const int wid  = tid >> 5;
    const int g    = lane >> 2;        // groupID
    const int t    = lane & 3;         // threadID_in_group
    const int wm   = (wid >> 1) << 5;  // warp M offset (0/32/64/96)
    const int wn   = (wid & 1) << 6;   // warp N offset (0/64)
    const int bm   = blockIdx.y << 7;
    const int bn   = blockIdx.x << 7;

    // staging: thread loads row r, k-cols [c0, c0+8)
    const int r  = tid >> 1;
    const int c0 = (tid & 1) << 3;
    int arow = bm + r;
    if (MODE == 0) arow = ((arow >> 7) << 9) | (arow & 127);  // b*512 + q
    const float* Aptr = (MODE == 2 ? g_Att : Ain) + (size_t)arow * 512;
    const float* Wptr = W + (size_t)(bn + r) * 512;

    float c[2][8][4];
#pragma unroll
    for (int mt = 0; mt < 2; mt++)
#pragma unroll
        for (int nt = 0; nt < 8; nt++)
#pragma unroll
            for (int i = 0; i < 4; i++) c[mt][nt][i] = 0.f;

    // prefetch k-tile 0
    float4 fa0 = *(const float4*)(Aptr + c0);
    float4 fa1 = *(const float4*)(Aptr + c0 + 4);
    float4 fb0 = *(const float4*)(Wptr + c0);
    float4 fb1 = *(const float4*)(Wptr + c0 + 4);

    for (int k0 = 0; k0 < 512; k0 += 16) {
        // store prefetched tile to smem (convert to tf32)
        {
            uint4 u;
            u.x = f2tf32(fa0.x); u.y = f2tf32(fa0.y); u.z = f2tf32(fa0.z); u.w = f2tf32(fa0.w);
            *(uint4*)&As[r * KPAD + c0] = u;
            u.x = f2tf32(fa1.x); u.y = f2tf32(fa1.y); u.z = f2tf32(fa1.z); u.w = f2tf32(fa1.w);
            *(uint4*)&As[r * KPAD + c0 + 4] = u;
            u.x = f2tf32(fb0.x); u.y = f2tf32(fb0.y); u.z = f2tf32(fb0.z); u.w = f2tf32(fb0.w);
            *(uint4*)&Bs[r * KPAD + c0] = u;
            u.x = f2tf32(fb1.x); u.y = f2tf32(fb1.y); u.z = f2tf32(fb1.z); u.w = f2tf32(fb1.w);
            *(uint4*)&Bs[r * KPAD + c0 + 4] = u;
        }
        __syncthreads();

        // issue next tile's global loads (complete during compute)
        if (k0 + 16 < 512) {
            fa0 = *(const float4*)(Aptr + k0 + 16 + c0);
            fa1 = *(const float4*)(Aptr + k0 + 16 + c0 + 4);
            fb0 = *(const float4*)(Wptr + k0 + 16 + c0);
            fb1 = *(const float4*)(Wptr + k0 + 16 + c0 + 4);
        }

        // compute: two k=8 steps
#pragma unroll
        for (int kt = 0; kt < 2; kt++) {
            uint32_t afr[2][4];
#pragma unroll
            for (int mt = 0; mt < 2; mt++) {
                const uint32_t* ap = As + (wm + (mt << 4) + g) * KPAD + (kt << 3) + t;
                afr[mt][0] = ap[0];
                afr[mt][1] = ap[8 * KPAD];
                afr[mt][2] = ap[4];
                afr[mt][3] = ap[8 * KPAD + 4];
            }
#pragma unroll
            for (int nt = 0; nt < 8; nt++) {
                const uint32_t* bp = Bs + (wn + (nt << 3) + g) * KPAD + (kt << 3) + t;
                const uint32_t b0 = bp[0], b1 = bp[4];
                mma_tf32(c[0][nt], afr[0], b0, b1);
                mma_tf32(c[1][nt], afr[1], b0, b1);
            }
        }
        __syncthreads();
    }

    // ---------------- epilogue ----------------
    if (MODE == 0) {
        const int h = (bn + wn) >> 6;
#pragma unroll
        for (int mt = 0; mt < 2; mt++) {
            const int m0 = bm + wm + (mt << 4) + g;
            const int m1 = m0 + 8;
            float* p0 = g_Q + (size_t)(((((m0 >> 7) << 3) + h) << 7) + (m0 & 127)) * 64;
            float* p1 = g_Q + (size_t)(((((m1 >> 7) << 3) + h) << 7) + (m1 & 127)) * 64;
#pragma unroll
            for (int nt = 0; nt < 8; nt++) {
                const int d = (nt << 3) + (t << 1);
                *(float2*)(p0 + d) = make_float2(c[mt][nt][0] * 0.125f, c[mt][nt][1] * 0.125f);
                *(float2*)(p1 + d) = make_float2(c[mt][nt][2] * 0.125f, c[mt][nt][3] * 0.125f);
            }
        }
    } else if (MODE == 1) {
        float* base = (bn >= 512) ? g_V : g_K;
        const int h = ((bn + wn) >> 6) & 7;
#pragma unroll
        for (int mt = 0; mt < 2; mt++) {
            const int m0 = bm + wm + (mt << 4) + g;
            const int m1 = m0 + 8;
            float* p0 = base + (size_t)(((((m0 >> 9) << 3) + h) << 9) + (m0 & 511)) * 64;
            float* p1 = base + (size_t)(((((m1 >> 9) << 3) + h) << 9) + (m1 & 511)) * 64;
#pragma unroll
            for (int nt = 0; nt < 8; nt++) {
                const int d = (nt << 3) + (t << 1);
                *(float2*)(p0 + d) = make_float2(c[mt][nt][0], c[mt][nt][1]);
                *(float2*)(p1 + d) = make_float2(c[mt][nt][2], c[mt][nt][3]);
            }
        }
    } else {
        const int kind = g_mask_kind;
#pragma unroll
        for (int mt = 0; mt < 2; mt++) {
            const int m0 = bm + wm + (mt << 4) + g;
            const int m1 = m0 + 8;
            const bool pm0 = mask_true(post_mask, m0, kind);
            const bool pm1 = mask_true(post_mask, m1, kind);
            float* p0 = out + (size_t)m0 * 512 + bn + wn;
            float* p1 = out + (size_t)m1 * 512 + bn + wn;
#pragma unroll
            for (int nt = 0; nt < 8; nt++) {
                const int d = (nt << 3) + (t << 1);
                const float2 bb = *(const float2*)&bias[bn + wn + d];
                *(float2*)(p0 + d) = pm0 ? make_float2(0.f, 0.f)
                                         : make_float2(c[mt][nt][0] + bb.x, c[mt][nt][1] + bb.y);
                *(float2*)(p1 + d) = pm1 ? make_float2(0.f, 0.f)
                                         : make_float2(c[mt][nt][2] + bb.x, c[mt][nt][3] + bb.y);
            }
        }
    }
}

// ---------------- K2: attention per (b, h, 32-query chunk) ----------------
#define ATT_SMEM_FLOATS (32 * 68 + 512 * 68 + 32 * 516)
#define ATT_SMEM_BYTES  (ATT_SMEM_FLOATS * 4)

__global__ __launch_bounds__(256) void attn_kernel(const void* __restrict__ pre_mask,
                                                   const float* __restrict__ diff_mask) {
    extern __shared__ float sm[];
    float* Qs = sm;                        // [32][68]
    float* KV = sm + 32 * 68;              // [512][68]  (K, then reused for V)
    float* Ss = sm + 32 * 68 + 512 * 68;   // [32][516]

    const int tid = threadIdx.x;
    const int qc = blockIdx.x, h = blockIdx.y, b = blockIdx.z;
    const int bh = (b << 3) + h;
    const float* Qg = g_Q + ((size_t)bh * 128 + qc * 32) * 64;
    const float* Kg = g_K + (size_t)bh * 512 * 64;
    const float* Vg = g_V + (size_t)bh * 512 * 64;
    const int kind = g_mask_kind;
    const size_t mrow_base = ((size_t)b * 128 + qc * 32) * 512;
    const float NEG_INF = __int_as_float(0xff800000u);

    // load Q (32x64) and K (512x64), d-contiguous
#pragma unroll
    for (int i = 0; i < 2; i++) {
        const int f = (tid << 1) + i;
        const int q = f >> 4, d = (f & 15) << 2;
        *(float4*)&Qs[q * 68 + d] = *(const float4*)(Qg + (q << 6) + d);
    }
#pragma unroll
    for (int i = 0; i < 32; i++) {
        const int f = (i << 8) + tid;
        const int key = f >> 4, d = (f & 15) << 2;
        *(float4*)&KV[key * 68 + d] = *(const float4*)(Kg + (key << 6) + d);
    }
    __syncthreads();

    // S = Q @ K^T (32x512), 8x8 per thread, dot over d
    {
        const int q0 = (tid >> 6) << 3;
        const int j0 = (tid & 63) << 3;
        float acc[8][8];
#pragma unroll
        for (int i = 0; i < 8; i++)
#pragma unroll
            for (int j = 0; j < 8; j++) acc[i][j] = 0.f;
#pragma unroll 8
        for (int dd = 0; dd < 64; dd += 2) {
            float2 av[8], bv[8];
#pragma unroll
            for (int i = 0; i < 8; i++) av[i] = *(const float2*)&Qs[(q0 + i) * 68 + dd];
#pragma unroll
            for (int j = 0; j < 8; j++) bv[j] = *(const float2*)&KV[(j0 + j) * 68 + dd];
#pragma unroll
            for (int i = 0; i < 8; i++)
#pragma unroll
                for (int j = 0; j < 8; j++)
                    acc[i][j] += av[i].x * bv[j].x + av[i].y * bv[j].y;
        }
#pragma unroll
        for (int i = 0; i < 8; i++) {
            const int q = q0 + i;
            const size_t mb = mrow_base + (size_t)q * 512 + j0;
#pragma unroll
            for (int j = 0; j < 8; j++) {
                const bool pm = mask_true(pre_mask, mb + j, kind);
                Ss[q * 516 + j0 + j] = pm ? NEG_INF : acc[i][j];
            }
        }
    }
    __syncthreads();

    // softmax + diff-mask renorm: w = e*dm / (sum(e*dm) + 1e-8*sum(e)); all-masked -> 0
    {
        const int q = tid >> 3;
        const int l8 = tid & 7;
        float* row = Ss + q * 516;
        const float* drow = diff_mask + mrow_base + (size_t)q * 512;
        float m = NEG_INF;
#pragma unroll 8
        for (int i = 0; i < 64; i++) m = fmaxf(m, row[l8 + (i << 3)]);
#pragma unroll
        for (int o = 4; o > 0; o >>= 1) m = fmaxf(m, __shfl_xor_sync(0xffffffffu, m, o));
        float E = 0.f, D = 0.f;
#pragma unroll 8
        for (int i = 0; i < 64; i++) {
            const int j = l8 + (i << 3);
            const float s = row[j];
            const float e = (s == NEG_INF) ? 0.f : __expf(s - m);
            const float wd = e * drow[j];
            E += e; D += wd;
            row[j] = wd;
        }
#pragma unroll
        for (int o = 4; o > 0; o >>= 1) {
            E += __shfl_xor_sync(0xffffffffu, E, o);
            D += __shfl_xor_sync(0xffffffffu, D, o);
        }
        const float inv = (E > 0.f) ? 1.f / (D + 1e-8f * E) : 0.f;
#pragma unroll 8
        for (int i = 0; i < 64; i++) row[l8 + (i << 3)] *= inv;
    }
    __syncthreads();

    // load V over K's smem
#pragma unroll
    for (int i = 0; i < 32; i++) {
        const int f = (i << 8) + tid;
        const int key = f >> 4, d = (f & 15) << 2;
        *(float4*)&KV[key * 68 + d] = *(const float4*)(Vg + (key << 6) + d);
    }
    __syncthreads();

    // O = W @ V (32x64): each thread 2 q-rows x 4 d-cols
    {
        const int qp = (tid >> 4) << 1;
        const int d0 = (tid & 15) << 2;
        float a0 = 0, a1 = 0, a2 = 0, a3 = 0, b0 = 0, b1 = 0, b2 = 0, b3 = 0;
        const float* s0p = Ss + qp * 516;
        const float* s1p = s0p + 516;
#pragma unroll 4
        for (int j = 0; j < 512; j++) {
            const float s0 = s0p[j], s1 = s1p[j];
            const float4 v = *(const float4*)&KV[j * 68 + d0];
            a0 += s0 * v.x; a1 += s0 * v.y; a2 += s0 * v.z; a3 += s0 * v.w;
            b0 += s1 * v.x; b1 += s1 * v.y; b2 += s1 * v.z; b3 += s1 * v.w;
        }
        const size_t ob = ((size_t)b * 128 + qc * 32 + qp) * 512 + (h << 6) + d0;
        *(float4*)&g_Att[ob]       = make_float4(a0, a1, a2, a3);
        *(float4*)&g_Att[ob + 512] = make_float4(b0, b1, b2, b3);
    }
}

// ---------------- launcher ----------------
extern "C" void kernel_launch(void* const* d_in, const int* in_sizes, int n_in,
                              void* d_out, int out_size) {
    (void)in_sizes; (void)n_in; (void)out_size;
    const float* entities  = (const float*)d_in[0];
    const void*  pre_mask  = d_in[1];
    const float* diff_mask = (const float*)d_in[2];
    const void*  post_mask = d_in[3];
    const float* W_in      = (const float*)d_in[4];
    const float* W_out     = (const float*)d_in[5];
    const float* b_out     = (const float*)d_in[6];
    float* out = (float*)d_out;

    cudaFuncSetAttribute(attn_kernel, cudaFuncAttributeMaxDynamicSharedMemorySize,
                         ATT_SMEM_BYTES);

    detect_mask_kernel<<<1, 32>>>((const unsigned int*)pre_mask);
    gemm_tf32<0><<<dim3(4, 128), 256>>>(entities, W_in, nullptr, nullptr, nullptr);              // Q
    gemm_tf32<1><<<dim3(8, 512), 256>>>(entities, W_in + 512 * 512, nullptr, nullptr, nullptr);  // K,V
    attn_kernel<<<dim3(4, 8, 128), 256, ATT_SMEM_BYTES>>>(pre_mask, diff_mask);
    gemm_tf32<2><<<dim3(4, 128), 256>>>(nullptr, W_out, b_out, post_mask, out);                  // out
}

// round 5
// speedup vs baseline: 2.2725x; 1.4862x over previous
#include <cuda_runtime.h>
#include <cstdint>

// ---------------- scratch (static device globals; no allocation) ----------------
__device__ float g_Q[128 * 8 * 128 * 64];    // (bs,H,nq,hd)   32 MB
__device__ float g_K[128 * 8 * 512 * 64];    // (bs,H,ne,hd)  128 MB
__device__ float g_V[128 * 8 * 512 * 64];    // (bs,H,ne,hd)  128 MB
__device__ float g_Att[128 * 128 * 512];     // (bs,nq,E)      32 MB
__device__ int   g_mask_kind;                // 0=int32, 1=uint8, 2=float32

// ---------------- mask dtype handling ----------------
__device__ __forceinline__ bool mask_true(const void* p, size_t i, int kind) {
    if (kind == 1) return ((const unsigned char*)p)[i] != 0;
    if (kind == 0) return ((const int*)p)[i] != 0;
    return ((const float*)p)[i] != 0.0f;
}

__global__ void detect_mask_kernel(const unsigned int* __restrict__ pm) {
    if (threadIdx.x == 0) {
        bool is_i32 = true, is_f32 = true;
        for (int i = 0; i < 64; i++) {
            unsigned int w = pm[i];
            if (w != 0u && w != 1u) is_i32 = false;
            if (w != 0u && w != 0x3F800000u) is_f32 = false;
        }
        g_mask_kind = is_i32 ? 0 : (is_f32 ? 2 : 1);
    }
}

// ---------------- tf32 helpers ----------------
__device__ __forceinline__ uint32_t f2tf32(float f) {
    uint32_t r;
    asm("cvt.rna.tf32.f32 %0, %1;" : "=r"(r) : "f"(f));
    return r;
}

__device__ __forceinline__ void mma_tf32(float* c, const uint32_t* a,
                                         uint32_t b0, uint32_t b1) {
    asm volatile(
        "mma.sync.aligned.m16n8k8.row.col.f32.tf32.tf32.f32 "
        "{%0,%1,%2,%3}, {%4,%5,%6,%7}, {%8,%9}, {%0,%1,%2,%3};"
        : "+f"(c[0]), "+f"(c[1]), "+f"(c[2]), "+f"(c[3])
        : "r"(a[0]), "r"(a[1]), "r"(a[2]), "r"(a[3]), "r"(b0), "r"(b1));
}

// ---------------- tensor-core GEMM:  C[M][N] = A[M][512] @ W[N][512]^T ----------------
// MODE 0: Q projection   (M=16384 logical rows b*128+q, A rows b*512+q; N=512; -> g_Q, x0.125)
// MODE 1: K/V projection (M=65536; N=1024; -> g_K / g_V)
// MODE 2: out projection (M=16384, A = g_Att; N=512; -> out, +bias, post-mask)
// Block 128x128, 256 threads = 8 warps (4 along M x 2 along N), warp tile 32x64.
#define KPAD 20

template <int MODE>
__global__ __launch_bounds__(256) void gemm_tf32(const float* __restrict__ Ain,
                                                 const float* __restrict__ W,
                                                 const float* __restrict__ bias,
                                                 const void* __restrict__ post_mask,
                                                 float* __restrict__ out) {
    __shared__ uint32_t As[128 * KPAD];
    __shared__ uint32_t Bs[128 * KPAD];

    const int tid  = threadIdx.x;
    const int lane = tid & 31;
    const int wid  = tid >> 5;
    const int g    = lane >> 2;        // groupID
    const int t    = lane & 3;         // threadID_in_group
    const int wm   = (wid >> 1) << 5;  // warp M offset (0/32/64/96)
    const int wn   = (wid & 1) << 6;   // warp N offset (0/64)
    const int bm   = blockIdx.y << 7;
    const int bn   = blockIdx.x << 7;

    // staging: thread loads row r, k-cols [c0, c0+8)
    const int r  = tid >> 1;
    const int c0 = (tid & 1) << 3;
    int arow = bm + r;
    if (MODE == 0) arow = ((arow >> 7) << 9) | (arow & 127);  // b*512 + q
    const float* Aptr = (MODE == 2 ? g_Att : Ain) + (size_t)arow * 512;
    const float* Wptr = W + (size_t)(bn + r) * 512;

    float c[2][8][4];
#pragma unroll
    for (int mt = 0; mt < 2; mt++)
#pragma unroll
        for (int nt = 0; nt < 8; nt++)
#pragma unroll
            for (int i = 0; i < 4; i++) c[mt][nt][i] = 0.f;

    // prefetch k-tile 0
    float4 fa0 = *(const float4*)(Aptr + c0);
    float4 fa1 = *(const float4*)(Aptr + c0 + 4);
    float4 fb0 = *(const float4*)(Wptr + c0);
    float4 fb1 = *(const float4*)(Wptr + c0 + 4);

    for (int k0 = 0; k0 < 512; k0 += 16) {
        // store prefetched tile to smem (convert to tf32)
        {
            uint4 u;
            u.x = f2tf32(fa0.x); u.y = f2tf32(fa0.y); u.z = f2tf32(fa0.z); u.w = f2tf32(fa0.w);
            *(uint4*)&As[r * KPAD + c0] = u;
            u.x = f2tf32(fa1.x); u.y = f2tf32(fa1.y); u.z = f2tf32(fa1.z); u.w = f2tf32(fa1.w);
            *(uint4*)&As[r * KPAD + c0 + 4] = u;
            u.x = f2tf32(fb0.x); u.y = f2tf32(fb0.y); u.z = f2tf32(fb0.z); u.w = f2tf32(fb0.w);
            *(uint4*)&Bs[r * KPAD + c0] = u;
            u.x = f2tf32(fb1.x); u.y = f2tf32(fb1.y); u.z = f2tf32(fb1.z); u.w = f2tf32(fb1.w);
            *(uint4*)&Bs[r * KPAD + c0 + 4] = u;
        }
        __syncthreads();

        // issue next tile's global loads (complete during compute)
        if (k0 + 16 < 512) {
            fa0 = *(const float4*)(Aptr + k0 + 16 + c0);
            fa1 = *(const float4*)(Aptr + k0 + 16 + c0 + 4);
            fb0 = *(const float4*)(Wptr + k0 + 16 + c0);
            fb1 = *(const float4*)(Wptr + k0 + 16 + c0 + 4);
        }

        // compute: two k=8 steps
#pragma unroll
        for (int kt = 0; kt < 2; kt++) {
            uint32_t afr[2][4];
#pragma unroll
            for (int mt = 0; mt < 2; mt++) {
                const uint32_t* ap = As + (wm + (mt << 4) + g) * KPAD + (kt << 3) + t;
                afr[mt][0] = ap[0];
                afr[mt][1] = ap[8 * KPAD];
                afr[mt][2] = ap[4];
                afr[mt][3] = ap[8 * KPAD + 4];
            }
#pragma unroll
            for (int nt = 0; nt < 8; nt++) {
                const uint32_t* bp = Bs + (wn + (nt << 3) + g) * KPAD + (kt << 3) + t;
                const uint32_t b0 = bp[0], b1 = bp[4];
                mma_tf32(c[0][nt], afr[0], b0, b1);
                mma_tf32(c[1][nt], afr[1], b0, b1);
            }
        }
        __syncthreads();
    }

    // ---------------- epilogue ----------------
    if (MODE == 0) {
        const int h = (bn + wn) >> 6;
#pragma unroll
        for (int mt = 0; mt < 2; mt++) {
            const int m0 = bm + wm + (mt << 4) + g;
            const int m1 = m0 + 8;
            float* p0 = g_Q + (size_t)(((((m0 >> 7) << 3) + h) << 7) + (m0 & 127)) * 64;
            float* p1 = g_Q + (size_t)(((((m1 >> 7) << 3) + h) << 7) + (m1 & 127)) * 64;
#pragma unroll
            for (int nt = 0; nt < 8; nt++) {
                const int d = (nt << 3) + (t << 1);
                *(float2*)(p0 + d) = make_float2(c[mt][nt][0] * 0.125f, c[mt][nt][1] * 0.125f);
                *(float2*)(p1 + d) = make_float2(c[mt][nt][2] * 0.125f, c[mt][nt][3] * 0.125f);
            }
        }
    } else if (MODE == 1) {
        float* base = (bn >= 512) ? g_V : g_K;
        const int h = ((bn + wn) >> 6) & 7;
#pragma unroll
        for (int mt = 0; mt < 2; mt++) {
            const int m0 = bm + wm + (mt << 4) + g;
            const int m1 = m0 + 8;
            float* p0 = base + (size_t)(((((m0 >> 9) << 3) + h) << 9) + (m0 & 511)) * 64;
            float* p1 = base + (size_t)(((((m1 >> 9) << 3) + h) << 9) + (m1 & 511)) * 64;
#pragma unroll
            for (int nt = 0; nt < 8; nt++) {
                const int d = (nt << 3) + (t << 1);
                *(float2*)(p0 + d) = make_float2(c[mt][nt][0], c[mt][nt][1]);
                *(float2*)(p1 + d) = make_float2(c[mt][nt][2], c[mt][nt][3]);
            }
        }
    } else {
        const int kind = g_mask_kind;
#pragma unroll
        for (int mt = 0; mt < 2; mt++) {
            const int m0 = bm + wm + (mt << 4) + g;
            const int m1 = m0 + 8;
            const bool pm0 = mask_true(post_mask, m0, kind);
            const bool pm1 = mask_true(post_mask, m1, kind);
            float* p0 = out + (size_t)m0 * 512 + bn + wn;
            float* p1 = out + (size_t)m1 * 512 + bn + wn;
#pragma unroll
            for (int nt = 0; nt < 8; nt++) {
                const int d = (nt << 3) + (t << 1);
                const float2 bb = *(const float2*)&bias[bn + wn + d];
                *(float2*)(p0 + d) = pm0 ? make_float2(0.f, 0.f)
                                         : make_float2(c[mt][nt][0] + bb.x, c[mt][nt][1] + bb.y);
                *(float2*)(p1 + d) = pm1 ? make_float2(0.f, 0.f)
                                         : make_float2(c[mt][nt][2] + bb.x, c[mt][nt][3] + bb.y);
            }
        }
    }
}

// ---------------- K2: tensor-core attention per (b, h, 32-query chunk) ----------------
// smem layout (words):
//   Qs  (tf32): [32][68]              2176
//   KVs (tf32): [512][68]            34816   (K for S-phase, then V for O-phase,
//                                             then fp32 scratch[8][32][68] for O reduce)
//   Ss  (f32):  [32][516]            16512
#define QS_OFF   0
#define KV_OFF   2176
#define SS_OFF   (2176 + 34816)
#define ATT_SMEM_FLOATS (2176 + 34816 + 16512)
#define ATT_SMEM_BYTES  (ATT_SMEM_FLOATS * 4)

__global__ __launch_bounds__(256) void attn_kernel(const void* __restrict__ pre_mask,
                                                   const float* __restrict__ diff_mask) {
    extern __shared__ uint32_t sm[];
    uint32_t* Qs  = sm + QS_OFF;
    uint32_t* KVs = sm + KV_OFF;
    float*    Ss  = (float*)(sm + SS_OFF);

    const int tid  = threadIdx.x;
    const int lane = tid & 31;
    const int w    = tid >> 5;          // warp 0..7
    const int g    = lane >> 2;
    const int t    = lane & 3;
    const int j0   = w << 6;            // this warp's 64-key slice

    const int qc = blockIdx.x, h = blockIdx.y, b = blockIdx.z;
    const int bh = (b << 3) + h;
    const float* Qg = g_Q + ((size_t)bh * 128 + qc * 32) * 64;
    const float* Kg = g_K + (size_t)bh * 512 * 64;
    const float* Vg = g_V + (size_t)bh * 512 * 64;
    const int kind = g_mask_kind;
    const size_t mrow_base = ((size_t)b * 128 + qc * 32) * 512;
    const float NEG_INF = __int_as_float(0xff800000u);

    // ---- load Q (32x64) and K (512x64) as tf32 ----
    {
        const int q = tid >> 3, d = (tid & 7) << 3;
        const float4 v0 = *(const float4*)(Qg + (q << 6) + d);
        const float4 v1 = *(const float4*)(Qg + (q << 6) + d + 4);
        uint4 u;
        u.x = f2tf32(v0.x); u.y = f2tf32(v0.y); u.z = f2tf32(v0.z); u.w = f2tf32(v0.w);
        *(uint4*)&Qs[q * 68 + d] = u;
        u.x = f2tf32(v1.x); u.y = f2tf32(v1.y); u.z = f2tf32(v1.z); u.w = f2tf32(v1.w);
        *(uint4*)&Qs[q * 68 + d + 4] = u;
    }
#pragma unroll
    for (int i = 0; i < 32; i++) {
        const int f = (i << 8) + tid;
        const int key = f >> 4, d = (f & 15) << 2;
        const float4 v = *(const float4*)(Kg + (key << 6) + d);
        uint4 u;
        u.x = f2tf32(v.x); u.y = f2tf32(v.y); u.z = f2tf32(v.z); u.w = f2tf32(v.w);
        *(uint4*)&KVs[key * 68 + d] = u;
    }
    __syncthreads();

    // ---- S = Q @ K^T (32x512); warp w: keys [j0, j0+64) ----
    {
        float c[2][8][4];
#pragma unroll
        for (int mt = 0; mt < 2; mt++)
#pragma unroll
            for (int nt = 0; nt < 8; nt++)
#pragma unroll
                for (int i = 0; i < 4; i++) c[mt][nt][i] = 0.f;

#pragma unroll
        for (int ks = 0; ks < 8; ks++) {
            uint32_t afr[2][4];
#pragma unroll
            for (int mt = 0; mt < 2; mt++) {
                const uint32_t* ap = Qs + ((mt << 4) + g) * 68 + (ks << 3) + t;
                afr[mt][0] = ap[0];
                afr[mt][1] = ap[8 * 68];
                afr[mt][2] = ap[4];
                afr[mt][3] = ap[8 * 68 + 4];
            }
#pragma unroll
            for (int nt = 0; nt < 8; nt++) {
                const uint32_t* bp = KVs + (j0 + (nt << 3) + g) * 68 + (ks << 3) + t;
                const uint32_t b0 = bp[0], b1 = bp[4];
                mma_tf32(c[0][nt], afr[0], b0, b1);
                mma_tf32(c[1][nt], afr[1], b0, b1);
            }
        }

        // epilogue: pre-mask + write to Ss (fp32)
#pragma unroll
        for (int mt = 0; mt < 2; mt++) {
            const int q = (mt << 4) + g;
#pragma unroll
            for (int nt = 0; nt < 8; nt++) {
                const int j = j0 + (nt << 3) + (t << 1);
                const size_t mi0 = mrow_base + (size_t)q * 512 + j;
                const size_t mi1 = mrow_base + (size_t)(q + 8) * 512 + j;
                Ss[q * 516 + j]           = mask_true(pre_mask, mi0,     kind) ? NEG_INF : c[mt][nt][0];
                Ss[q * 516 + j + 1]       = mask_true(pre_mask, mi0 + 1, kind) ? NEG_INF : c[mt][nt][1];
                Ss[(q + 8) * 516 + j]     = mask_true(pre_mask, mi1,     kind) ? NEG_INF : c[mt][nt][2];
                Ss[(q + 8) * 516 + j + 1] = mask_true(pre_mask, mi1 + 1, kind) ? NEG_INF : c[mt][nt][3];
            }
        }
    }
    __syncthreads();

    // ---- load V over K's smem (as tf32); independent of softmax below ----
#pragma unroll
    for (int i = 0; i < 32; i++) {
        const int f = (i << 8) + tid;
        const int key = f >> 4, d = (f & 15) << 2;
        const float4 v = *(const float4*)(Vg + (key << 6) + d);
        uint4 u;
        u.x = f2tf32(v.x); u.y = f2tf32(v.y); u.z = f2tf32(v.z); u.w = f2tf32(v.w);
        *(uint4*)&KVs[key * 68 + d] = u;
    }

    // ---- softmax + diff-mask renorm: w = e*dm / (sum(e*dm)+1e-8*sum(e)) ----
    {
        const int q = tid >> 3;
        const int l8 = tid & 7;
        float* row = Ss + q * 516;
        const float* drow = diff_mask + mrow_base + (size_t)q * 512;
        float m = NEG_INF;
#pragma unroll 8
        for (int i = 0; i < 64; i++) m = fmaxf(m, row[l8 + (i << 3)]);
#pragma unroll
        for (int o = 4; o > 0; o >>= 1) m = fmaxf(m, __shfl_xor_sync(0xffffffffu, m, o));
        float E = 0.f, D = 0.f;
#pragma unroll 8
        for (int i = 0; i < 64; i++) {
            const int j = l8 + (i << 3);
            const float s = row[j];
            const float e = (s == NEG_INF) ? 0.f : __expf(s - m);
            const float wd = e * drow[j];
            E += e; D += wd;
            row[j] = wd;
        }
#pragma unroll
        for (int o = 4; o > 0; o >>= 1) {
            E += __shfl_xor_sync(0xffffffffu, E, o);
            D += __shfl_xor_sync(0xffffffffu, D, o);
        }
        const float inv = (E > 0.f) ? 1.f / (D + 1e-8f * E) : 0.f;
#pragma unroll 8
        for (int i = 0; i < 64; i++) row[l8 + (i << 3)] *= inv;
    }
    __syncthreads();

    // ---- O = w @ V (32x64); warp w accumulates partial over keys [j0, j0+64) ----
    float o[2][8][4];
#pragma unroll
    for (int mt = 0; mt < 2; mt++)
#pragma unroll
        for (int nt = 0; nt < 8; nt++)
#pragma unroll
            for (int i = 0; i < 4; i++) o[mt][nt][i] = 0.f;

#pragma unroll
    for (int ks = 0; ks < 8; ks++) {
        uint32_t afr[2][4];
#pragma unroll
        for (int mt = 0; mt < 2; mt++) {
            const float* ap = Ss + ((mt << 4) + g) * 516 + j0 + (ks << 3) + t;
            afr[mt][0] = f2tf32(ap[0]);
            afr[mt][1] = f2tf32(ap[8 * 516]);
            afr[mt][2] = f2tf32(ap[4]);
            afr[mt][3] = f2tf32(ap[8 * 516 + 4]);
        }
#pragma unroll
        for (int nt = 0; nt < 8; nt++) {
            const uint32_t* bp = KVs + (j0 + (ks << 3) + t) * 68 + (nt << 3) + g;
            const uint32_t b0 = bp[0], b1 = bp[4 * 68];
            mma_tf32(o[0][nt], afr[0], b0, b1);
            mma_tf32(o[1][nt], afr[1], b0, b1);
        }
    }
    __syncthreads();   // all warps done reading V -> KVs becomes reduce scratch

    // ---- cross-warp reduction of partial O through smem ----
    {
        float* scratch = (float*)KVs;      // [8][32][68]
        float* wp = scratch + w * 2176;
#pragma unroll
        for (int mt = 0; mt < 2; mt++) {
            const int q = (mt << 4) + g;
#pragma unroll
            for (int nt = 0; nt < 8; nt++) {
                const int d = (nt << 3) + (t << 1);
                *(float2*)&wp[q * 68 + d]       = make_float2(o[mt][nt][0], o[mt][nt][1]);
                *(float2*)&wp[(q + 8) * 68 + d] = make_float2(o[mt][nt][2], o[mt][nt][3]);
            }
        }
        __syncthreads();

        const int q = tid >> 3, d0 = (tid & 7) << 3;
        float4 s0 = make_float4(0.f, 0.f, 0.f, 0.f);
        float4 s1 = make_float4(0.f, 0.f, 0.f, 0.f);
#pragma unroll
        for (int ww = 0; ww < 8; ww++) {
            const float* p = scratch + ww * 2176 + q * 68 + d0;
            const float4 x = *(const float4*)p;
            const float4 y = *(const float4*)(p + 4);
            s0.x += x.x; s0.y += x.y; s0.z += x.z; s0.w += x.w;
            s1.x += y.x; s1.y += y.y; s1.z += y.z; s1.w += y.w;
        }
        const size_t ob = ((size_t)b * 128 + qc * 32 + q) * 512 + (h << 6) + d0;
        *(float4*)&g_Att[ob]     = s0;
        *(float4*)&g_Att[ob + 4] = s1;
    }
}

// ---------------- launcher ----------------
extern "C" void kernel_launch(void* const* d_in, const int* in_sizes, int n_in,
                              void* d_out, int out_size) {
    (void)in_sizes; (void)n_in; (void)out_size;
    const float* entities  = (const float*)d_in[0];
    const void*  pre_mask  = d_in[1];
    const float* diff_mask = (const float*)d_in[2];
    const void*  post_mask = d_in[3];
    const float* W_in      = (const float*)d_in[4];
    const float* W_out     = (const float*)d_in[5];
    const float* b_out     = (const float*)d_in[6];
    float* out = (float*)d_out;

    cudaFuncSetAttribute(attn_kernel, cudaFuncAttributeMaxDynamicSharedMemorySize,
                         ATT_SMEM_BYTES);

    detect_mask_kernel<<<1, 32>>>((const unsigned int*)pre_mask);
    gemm_tf32<0><<<dim3(4, 128), 256>>>(entities, W_in, nullptr, nullptr, nullptr);              // Q
    gemm_tf32<1><<<dim3(8, 512), 256>>>(entities, W_in + 512 * 512, nullptr, nullptr, nullptr);  // K,V
    attn_kernel<<<dim3(4, 8, 128), 256, ATT_SMEM_BYTES>>>(pre_mask, diff_mask);
    gemm_tf32<2><<<dim3(4, 128), 256>>>(nullptr, W_out, b_out, post_mask, out);                  // out
}

// round 7
// speedup vs baseline: 2.8295x; 1.2451x over previous
#include <cuda_runtime.h>
#include <cstdint>

// ---------------- scratch (static device globals; no allocation) ----------------
__device__ float g_Q[128 * 8 * 128 * 64];    // (bs,H,nq,hd)   32 MB
__device__ float g_K[128 * 8 * 512 * 64];    // (bs,H,ne,hd)  128 MB
__device__ float g_V[128 * 8 * 512 * 64];    // (bs,H,ne,hd)  128 MB
__device__ float g_Att[128 * 128 * 512];     // (bs,nq,E)      32 MB
__device__ int   g_mask_kind;                // 0=int32, 1=uint8, 2=float32

// ---------------- mask dtype handling ----------------
__device__ __forceinline__ bool mask_true(const void* p, size_t i, int kind) {
    if (kind == 1) return ((const unsigned char*)p)[i] != 0;
    if (kind == 0) return ((const int*)p)[i] != 0;
    return ((const float*)p)[i] != 0.0f;
}

__global__ void detect_mask_kernel(const unsigned int* __restrict__ pm) {
    if (threadIdx.x == 0) {
        bool is_i32 = true, is_f32 = true;
        for (int i = 0; i < 64; i++) {
            unsigned int w = pm[i];
            if (w != 0u && w != 1u) is_i32 = false;
            if (w != 0u && w != 0x3F800000u) is_f32 = false;
        }
        g_mask_kind = is_i32 ? 0 : (is_f32 ? 2 : 1);
    }
}

// ---------------- tf32 helpers ----------------
__device__ __forceinline__ uint32_t f2tf32(float f) {
    uint32_t r;
    asm("cvt.rna.tf32.f32 %0, %1;" : "=r"(r) : "f"(f));
    return r;
}

__device__ __forceinline__ void mma_tf32(float* c, const uint32_t* a,
                                         uint32_t b0, uint32_t b1) {
    asm volatile(
        "mma.sync.aligned.m16n8k8.row.col.f32.tf32.tf32.f32 "
        "{%0,%1,%2,%3}, {%4,%5,%6,%7}, {%8,%9}, {%0,%1,%2,%3};"
        : "+f"(c[0]), "+f"(c[1]), "+f"(c[2]), "+f"(c[3])
        : "r"(a[0]), "r"(a[1]), "r"(a[2]), "r"(a[3]), "r"(b0), "r"(b1));
}

// ---------------- tensor-core GEMM:  C[M][N] = A[M][512] @ W[N][512]^T ----------------
// MODE 0: Q projection   (M=16384 logical rows b*128+q, A rows b*512+q; N=512; -> g_Q, x0.125)
// MODE 1: K/V projection (M=65536; N=1024; -> g_K / g_V)
// MODE 2: out projection (M=16384, A = g_Att; N=512; -> out, +bias, post-mask)
#define KPAD 20

template <int MODE>
__global__ __launch_bounds__(256) void gemm_tf32(const float* __restrict__ Ain,
                                                 const float* __restrict__ W,
                                                 const float* __restrict__ bias,
                                                 const void* __restrict__ post_mask,
                                                 float* __restrict__ out) {
    __shared__ uint32_t As[128 * KPAD];
    __shared__ uint32_t Bs[128 * KPAD];

    const int tid  = threadIdx.x;
    const int lane = tid & 31;
    const int wid  = tid >> 5;
    const int g    = lane >> 2;
    const int t    = lane & 3;
    const int wm   = (wid >> 1) << 5;
    const int wn   = (wid & 1) << 6;
    const int bm   = blockIdx.y << 7;
    const int bn   = blockIdx.x << 7;

    const int r  = tid >> 1;
    const int c0 = (tid & 1) << 3;
    int arow = bm + r;
    if (MODE == 0) arow = ((arow >> 7) << 9) | (arow & 127);
    const float* Aptr = (MODE == 2 ? g_Att : Ain) + (size_t)arow * 512;
    const float* Wptr = W + (size_t)(bn + r) * 512;

    float c[2][8][4];
#pragma unroll
    for (int mt = 0; mt < 2; mt++)
#pragma unroll
        for (int nt = 0; nt < 8; nt++)
#pragma unroll
            for (int i = 0; i < 4; i++) c[mt][nt][i] = 0.f;

    float4 fa0 = *(const float4*)(Aptr + c0);
    float4 fa1 = *(const float4*)(Aptr + c0 + 4);
    float4 fb0 = *(const float4*)(Wptr + c0);
    float4 fb1 = *(const float4*)(Wptr + c0 + 4);

    for (int k0 = 0; k0 < 512; k0 += 16) {
        {
            uint4 u;
            u.x = f2tf32(fa0.x); u.y = f2tf32(fa0.y); u.z = f2tf32(fa0.z); u.w = f2tf32(fa0.w);
            *(uint4*)&As[r * KPAD + c0] = u;
            u.x = f2tf32(fa1.x); u.y = f2tf32(fa1.y); u.z = f2tf32(fa1.z); u.w = f2tf32(fa1.w);
            *(uint4*)&As[r * KPAD + c0 + 4] = u;
            u.x = f2tf32(fb0.x); u.y = f2tf32(fb0.y); u.z = f2tf32(fb0.z); u.w = f2tf32(fb0.w);
            *(uint4*)&Bs[r * KPAD + c0] = u;
            u.x = f2tf32(fb1.x); u.y = f2tf32(fb1.y); u.z = f2tf32(fb1.z); u.w = f2tf32(fb1.w);
            *(uint4*)&Bs[r * KPAD + c0 + 4] = u;
        }
        __syncthreads();

        if (k0 + 16 < 512) {
            fa0 = *(const float4*)(Aptr + k0 + 16 + c0);
            fa1 = *(const float4*)(Aptr + k0 + 16 + c0 + 4);
            fb0 = *(const float4*)(Wptr + k0 + 16 + c0);
            fb1 = *(const float4*)(Wptr + k0 + 16 + c0 + 4);
        }

#pragma unroll
        for (int kt = 0; kt < 2; kt++) {
            uint32_t afr[2][4];
#pragma unroll
            for (int mt = 0; mt < 2; mt++) {
                const uint32_t* ap = As + (wm + (mt << 4) + g) * KPAD + (kt << 3) + t;
                afr[mt][0] = ap[0];
                afr[mt][1] = ap[8 * KPAD];
                afr[mt][2] = ap[4];
                afr[mt][3] = ap[8 * KPAD + 4];
            }
#pragma unroll
            for (int nt = 0; nt < 8; nt++) {
                const uint32_t* bp = Bs + (wn + (nt << 3) + g) * KPAD + (kt << 3) + t;
                const uint32_t b0 = bp[0], b1 = bp[4];
                mma_tf32(c[0][nt], afr[0], b0, b1);
                mma_tf32(c[1][nt], afr[1], b0, b1);
            }
        }
        __syncthreads();
    }

    if (MODE == 0) {
        const int h = (bn + wn) >> 6;
#pragma unroll
        for (int mt = 0; mt < 2; mt++) {
            const int m0 = bm + wm + (mt << 4) + g;
            const int m1 = m0 + 8;
            float* p0 = g_Q + (size_t)(((((m0 >> 7) << 3) + h) << 7) + (m0 & 127)) * 64;
            float* p1 = g_Q + (size_t)(((((m1 >> 7) << 3) + h) << 7) + (m1 & 127)) * 64;
#pragma unroll
            for (int nt = 0; nt < 8; nt++) {
                const int d = (nt << 3) + (t << 1);
                *(float2*)(p0 + d) = make_float2(c[mt][nt][0] * 0.125f, c[mt][nt][1] * 0.125f);
                *(float2*)(p1 + d) = make_float2(c[mt][nt][2] * 0.125f, c[mt][nt][3] * 0.125f);
            }
        }
    } else if (MODE == 1) {
        float* base = (bn >= 512) ? g_V : g_K;
        const int h = ((bn + wn) >> 6) & 7;
#pragma unroll
        for (int mt = 0; mt < 2; mt++) {
            const int m0 = bm + wm + (mt << 4) + g;
            const int m1 = m0 + 8;
            float* p0 = base + (size_t)(((((m0 >> 9) << 3) + h) << 9) + (m0 & 511)) * 64;
            float* p1 = base + (size_t)(((((m1 >> 9) << 3) + h) << 9) + (m1 & 511)) * 64;
#pragma unroll
            for (int nt = 0; nt < 8; nt++) {
                const int d = (nt << 3) + (t << 1);
                *(float2*)(p0 + d) = make_float2(c[mt][nt][0], c[mt][nt][1]);
                *(float2*)(p1 + d) = make_float2(c[mt][nt][2], c[mt][nt][3]);
            }
        }
    } else {
        const int kind = g_mask_kind;
#pragma unroll
        for (int mt = 0; mt < 2; mt++) {
            const int m0 = bm + wm + (mt << 4) + g;
            const int m1 = m0 + 8;
            const bool pm0 = mask_true(post_mask, m0, kind);
            const bool pm1 = mask_true(post_mask, m1, kind);
            float* p0 = out + (size_t)m0 * 512 + bn + wn;
            float* p1 = out + (size_t)m1 * 512 + bn + wn;
#pragma unroll
            for (int nt = 0; nt < 8; nt++) {
                const int d = (nt << 3) + (t << 1);
                const float2 bb = *(const float2*)&bias[bn + wn + d];
                *(float2*)(p0 + d) = pm0 ? make_float2(0.f, 0.f)
                                         : make_float2(c[mt][nt][0] + bb.x, c[mt][nt][1] + bb.y);
                *(float2*)(p1 + d) = pm1 ? make_float2(0.f, 0.f)
                                         : make_float2(c[mt][nt][2] + bb.x, c[mt][nt][3] + bb.y);
            }
        }
    }
}

// ---------------- K2: flash-style attention, one CTA per (b,h) ----------------
// smem (words):
//   Qs    [128][68] tf32                      8704
//   stats [8 warps][32 rows][4] f32           1024
//   KVbuf [2 bufs][K,V][128][68] raw f32     34816
#define SM_STATS_W 8704
#define SM_KV_W    9728
#define ATT_SMEM_WORDS (9728 + 4 * 8704)
#define ATT_SMEM_BYTES (ATT_SMEM_WORDS * 4)

__global__ __launch_bounds__(256) void attn_kernel(const void* __restrict__ pre_mask,
                                                   const float* __restrict__ diff_mask) {
    extern __shared__ uint32_t smw[];
    uint32_t* Qs    = smw;
    float*    stats = (float*)(smw + SM_STATS_W);
    float*    KVbuf = (float*)(smw + SM_KV_W);

    const int tid  = threadIdx.x;
    const int lane = tid & 31;
    const int w    = tid >> 5;
    const int g    = lane >> 2;
    const int t    = lane & 3;
    const int wm   = (w >> 1) << 5;   // query offset: 0/32/64/96
    const int wn   = (w & 1) << 6;    // key offset within 128-key tile: 0/64
    const bool odd = (t & 1);

    const int head = blockIdx.x, b = blockIdx.y;
    const int bh = (b << 3) + head;
    const float* Qg = g_Q + (size_t)bh * 128 * 64;
    const float* Kg = g_K + (size_t)bh * 512 * 64;
    const float* Vg = g_V + (size_t)bh * 512 * 64;
    const int kind = g_mask_kind;
    const size_t qrow0 = (size_t)b * 128;
    const float NEG_INF = __int_as_float(0xff800000u);

    // ---- prologue: issue K/V tile 0 via cp.async ----
    {
        float* Kb = KVbuf;
        float* Vb = KVbuf + 8704;
#pragma unroll
        for (int i = 0; i < 8; i++) {
            const int idx = (i << 8) + tid;
            const int key = idx >> 4, d = (idx & 15) << 2;
            uint32_t sK = (uint32_t)__cvta_generic_to_shared(Kb + key * 68 + d);
            uint32_t sV = (uint32_t)__cvta_generic_to_shared(Vb + key * 68 + d);
            asm volatile("cp.async.cg.shared.global [%0], [%1], 16;" :: "r"(sK), "l"(Kg + (key << 6) + d));
            asm volatile("cp.async.cg.shared.global [%0], [%1], 16;" :: "r"(sV), "l"(Vg + (key << 6) + d));
        }
        asm volatile("cp.async.commit_group;");
    }

    // ---- stage Q (tf32, pitch 68) ----
#pragma unroll
    for (int i = 0; i < 8; i++) {
        const int idx = (i << 8) + tid;
        const int q = idx >> 4, d = (idx & 15) << 2;
        const float4 v = *(const float4*)(Qg + (q << 6) + d);
        uint4 u;
        u.x = f2tf32(v.x); u.y = f2tf32(v.y); u.z = f2tf32(v.z); u.w = f2tf32(v.w);
        *(uint4*)&Qs[q * 68 + d] = u;
    }

    // ---- running state ----
    float m[4], E[4], D[4];
#pragma unroll
    for (int r = 0; r < 4; r++) { m[r] = NEG_INF; E[r] = 0.f; D[r] = 0.f; }
    float o[2][8][4];
#pragma unroll
    for (int mt = 0; mt < 2; mt++)
#pragma unroll
        for (int dn = 0; dn < 8; dn++)
#pragma unroll
            for (int i = 0; i < 4; i++) o[mt][dn][i] = 0.f;

    for (int tile = 0; tile < 4; tile++) {
        // issue next tile into the other buffer (prev compute on it finished at
        // the trailing __syncthreads of the previous iteration)
        if (tile < 3) {
            const int nb = (tile + 1) & 1;
            float* Kb = KVbuf + (size_t)(nb * 2 + 0) * 8704;
            float* Vb = KVbuf + (size_t)(nb * 2 + 1) * 8704;
            const float* Kgt = Kg + (size_t)((tile + 1) << 7) * 64;
            const float* Vgt = Vg + (size_t)((tile + 1) << 7) * 64;
#pragma unroll
            for (int i = 0; i < 8; i++) {
                const int idx = (i << 8) + tid;
                const int key = idx >> 4, d = (idx & 15) << 2;
                uint32_t sK = (uint32_t)__cvta_generic_to_shared(Kb + key * 68 + d);
                uint32_t sV = (uint32_t)__cvta_generic_to_shared(Vb + key * 68 + d);
                asm volatile("cp.async.cg.shared.global [%0], [%1], 16;" :: "r"(sK), "l"(Kgt + (key << 6) + d));
                asm volatile("cp.async.cg.shared.global [%0], [%1], 16;" :: "r"(sV), "l"(Vgt + (key << 6) + d));
            }
            asm volatile("cp.async.commit_group;");
            asm volatile("cp.async.wait_group 1;");
        } else {
            asm volatile("cp.async.wait_group 0;");
        }
        __syncthreads();

        const float* Kb = KVbuf + (size_t)((tile & 1) * 2 + 0) * 8704;
        const float* Vb = KVbuf + (size_t)((tile & 1) * 2 + 1) * 8704;

        // ---- preload diff-mask/pre-mask, fold: dmx<0 <=> masked ----
        float2 dmx[4][8];
#pragma unroll
        for (int mt = 0; mt < 2; mt++)
#pragma unroll
            for (int hh = 0; hh < 2; hh++) {
                const int r = mt * 2 + hh;
                const size_t row = qrow0 + wm + (mt << 4) + (hh << 3) + g;
                const size_t base = row * 512 + (tile << 7) + wn + (t << 1);
#pragma unroll
                for (int nt = 0; nt < 8; nt++) {
                    const size_t ix = base + (nt << 3);
                    const float2 d2 = *(const float2*)(diff_mask + ix);
                    bool p0, p1;
                    if (kind == 1) {
                        const uchar2 u = *(const uchar2*)((const unsigned char*)pre_mask + ix);
                        p0 = u.x != 0; p1 = u.y != 0;
                    } else if (kind == 0) {
                        const int2 u = *(const int2*)((const int*)pre_mask + ix);
                        p0 = u.x != 0; p1 = u.y != 0;
                    } else {
                        const float2 u = *(const float2*)((const float*)pre_mask + ix);
                        p0 = u.x != 0.f; p1 = u.y != 0.f;
                    }
                    dmx[r][nt] = make_float2(p0 ? -1.f : d2.x, p1 ? -1.f : d2.y);
                }
            }

        // ---- S = Q @ K^T for this tile (warp: 32 q x 64 keys) ----
        float c[2][8][4];
#pragma unroll
        for (int mt = 0; mt < 2; mt++)
#pragma unroll
            for (int nt = 0; nt < 8; nt++)
#pragma unroll
                for (int i = 0; i < 4; i++) c[mt][nt][i] = 0.f;

#pragma unroll
        for (int ks = 0; ks < 8; ks++) {
            uint32_t afr[2][4];
#pragma unroll
            for (int mt = 0; mt < 2; mt++) {
                const uint32_t* ap = Qs + (wm + (mt << 4) + g) * 68 + (ks << 3) + t;
                afr[mt][0] = ap[0];
                afr[mt][1] = ap[8 * 68];
                afr[mt][2] = ap[4];
                afr[mt][3] = ap[8 * 68 + 4];
            }
#pragma unroll
            for (int nt = 0; nt < 8; nt++) {
                const float* kp = Kb + (wn + (nt << 3) + g) * 68 + (ks << 3) + t;
                const uint32_t b0 = f2tf32(kp[0]), b1 = f2tf32(kp[4]);
                mma_tf32(c[0][nt], afr[0], b0, b1);
                mma_tf32(c[1][nt], afr[1], b0, b1);
            }
        }

        // ---- online softmax update (per row; rows owned by g, shared by t-group) ----
#pragma unroll
        for (int mt = 0; mt < 2; mt++)
#pragma unroll
            for (int hh = 0; hh < 2; hh++) {
                const int r = mt * 2 + hh;
                const int s0i = hh * 2, s1i = hh * 2 + 1;
                float tmax = NEG_INF;
#pragma unroll
                for (int nt = 0; nt < 8; nt++) {
                    const float2 dmv = dmx[r][nt];
                    float s0 = (dmv.x < 0.f) ? NEG_INF : c[mt][nt][s0i];
                    float s1 = (dmv.y < 0.f) ? NEG_INF : c[mt][nt][s1i];
                    c[mt][nt][s0i] = s0; c[mt][nt][s1i] = s1;
                    tmax = fmaxf(tmax, fmaxf(s0, s1));
                }
                tmax = fmaxf(tmax, __shfl_xor_sync(0xffffffffu, tmax, 1));
                tmax = fmaxf(tmax, __shfl_xor_sync(0xffffffffu, tmax, 2));
                const float mnew = fmaxf(m[r], tmax);
                const float sc = (m[r] == NEG_INF) ? 0.f : __expf(m[r] - mnew);
                m[r] = mnew;
                E[r] *= sc; D[r] *= sc;
#pragma unroll
                for (int dn = 0; dn < 8; dn++) { o[mt][dn][s0i] *= sc; o[mt][dn][s1i] *= sc; }
                float eacc = 0.f, dacc = 0.f;
#pragma unroll
                for (int nt = 0; nt < 8; nt++) {
                    const float2 dmv = dmx[r][nt];
                    const float s0 = c[mt][nt][s0i], s1 = c[mt][nt][s1i];
                    const float e0 = (s0 == NEG_INF) ? 0.f : __expf(s0 - mnew);
                    const float e1 = (s1 == NEG_INF) ? 0.f : __expf(s1 - mnew);
                    const float w0 = e0 * dmv.x, w1 = e1 * dmv.y;  // masked => e=0 => w=+-0
                    eacc += e0 + e1; dacc += w0 + w1;
                    c[mt][nt][s0i] = w0; c[mt][nt][s1i] = w1;
                }
                E[r] += eacc; D[r] += dacc;
            }

        // ---- O += wd @ V : shuffle-transpose wd into A-fragment layout ----
        const int lo = (lane & ~3) | (t >> 1);
        const int hi = lo + 2;
#pragma unroll
        for (int ks = 0; ks < 8; ks++) {
            uint32_t af2[2][4];
#pragma unroll
            for (int mt = 0; mt < 2; mt++) {
                const float s0 = c[mt][ks][0], s1 = c[mt][ks][1];
                const float s2 = c[mt][ks][2], s3 = c[mt][ks][3];
                const float x0 = __shfl_sync(0xffffffffu, s0, lo);
                const float x1 = __shfl_sync(0xffffffffu, s1, lo);
                const float x2 = __shfl_sync(0xffffffffu, s2, lo);
                const float x3 = __shfl_sync(0xffffffffu, s3, lo);
                const float y0 = __shfl_sync(0xffffffffu, s0, hi);
                const float y1 = __shfl_sync(0xffffffffu, s1, hi);
                const float y2 = __shfl_sync(0xffffffffu, s2, hi);
                const float y3 = __shfl_sync(0xffffffffu, s3, hi);
                af2[mt][0] = f2tf32(odd ? x1 : x0);   // wd[g][ks*8+t]
                af2[mt][1] = f2tf32(odd ? x3 : x2);   // wd[g+8][ks*8+t]
                af2[mt][2] = f2tf32(odd ? y1 : y0);   // wd[g][ks*8+t+4]
                af2[mt][3] = f2tf32(odd ? y3 : y2);   // wd[g+8][ks*8+t+4]
            }
#pragma unroll
            for (int dn = 0; dn < 8; dn++) {
                const uint32_t b0 = f2tf32(Vb[(wn + (ks << 3) + t) * 68 + (dn << 3) + g]);
                const uint32_t b1 = f2tf32(Vb[(wn + (ks << 3) + t + 4) * 68 + (dn << 3) + g]);
                mma_tf32(o[0][dn], af2[0], b0, b1);
                mma_tf32(o[1][dn], af2[1], b0, b1);
            }
        }
        __syncthreads();   // all warps done with this tile's buffers
    }

    // ---- merge stats across the two warp columns ----
#pragma unroll
    for (int r = 0; r < 4; r++) {
        E[r] += __shfl_xor_sync(0xffffffffu, E[r], 1);
        E[r] += __shfl_xor_sync(0xffffffffu, E[r], 2);
        D[r] += __shfl_xor_sync(0xffffffffu, D[r], 1);
        D[r] += __shfl_xor_sync(0xffffffffu, D[r], 2);
    }
    if (t == 0) {
#pragma unroll
        for (int mt = 0; mt < 2; mt++)
#pragma unroll
            for (int hh = 0; hh < 2; hh++) {
                const int r = mt * 2 + hh;
                float* sp = stats + ((w << 5) + (mt << 4) + (hh << 3) + g) * 4;
                sp[0] = m[r]; sp[1] = E[r]; sp[2] = D[r];
            }
    }
    __syncthreads();

    float fac[4];
#pragma unroll
    for (int mt = 0; mt < 2; mt++)
#pragma unroll
        for (int hh = 0; hh < 2; hh++) {
            const int r = mt * 2 + hh;
            const float* sp = stats + (((w ^ 1) << 5) + (mt << 4) + (hh << 3) + g) * 4;
            const float pm_ = sp[0], pE = sp[1], pD = sp[2];
            const float mt_ = fmaxf(m[r], pm_);
            const float ss = (m[r] == NEG_INF) ? 0.f : __expf(m[r] - mt_);
            const float sq = (pm_ == NEG_INF) ? 0.f : __expf(pm_ - mt_);
            const float Et = ss * E[r] + sq * pE;
            const float Dt = ss * D[r] + sq * pD;
            const float inv = (Et > 0.f) ? 1.f / (Dt + 1e-8f * Et) : 0.f;
            fac[r] = inv * ss;
        }
#pragma unroll
    for (int mt = 0; mt < 2; mt++)
#pragma unroll
        for (int dn = 0; dn < 8; dn++) {
            o[mt][dn][0] *= fac[mt * 2];     o[mt][dn][1] *= fac[mt * 2];
            o[mt][dn][2] *= fac[mt * 2 + 1]; o[mt][dn][3] *= fac[mt * 2 + 1];
        }

    // ---- reduce O across the warp-column pair and write g_Att ----
    float* Ored = KVbuf;   // [128][68], safe to reuse now
    if (w & 1) {
#pragma unroll
        for (int mt = 0; mt < 2; mt++) {
            const int q0 = wm + (mt << 4) + g;
#pragma unroll
            for (int dn = 0; dn < 8; dn++) {
                const int d = (dn << 3) + (t << 1);
                *(float2*)&Ored[q0 * 68 + d]       = make_float2(o[mt][dn][0], o[mt][dn][1]);
                *(float2*)&Ored[(q0 + 8) * 68 + d] = make_float2(o[mt][dn][2], o[mt][dn][3]);
            }
        }
    }
    __syncthreads();
    if (!(w & 1)) {
#pragma unroll
        for (int mt = 0; mt < 2; mt++) {
            const int q0 = wm + (mt << 4) + g;
#pragma unroll
            for (int dn = 0; dn < 8; dn++) {
                const int d = (dn << 3) + (t << 1);
                const float2 p0 = *(const float2*)&Ored[q0 * 68 + d];
                const float2 p1 = *(const float2*)&Ored[(q0 + 8) * 68 + d];
                const size_t ob = (qrow0 + q0) * 512 + (head << 6) + d;
                *(float2*)&g_Att[ob]             = make_float2(o[mt][dn][0] + p0.x, o[mt][dn][1] + p0.y);
                *(float2*)&g_Att[ob + 8 * 512]   = make_float2(o[mt][dn][2] + p1.x, o[mt][dn][3] + p1.y);
            }
        }
    }
}

// ---------------- launcher ----------------
extern "C" void kernel_launch(void* const* d_in, const int* in_sizes, int n_in,
                              void* d_out, int out_size) {
    (void)in_sizes; (void)n_in; (void)out_size;
    const float* entities  = (const float*)d_in[0];
    const void*  pre_mask  = d_in[1];
    const float* diff_mask = (const float*)d_in[2];
    const void*  post_mask = d_in[3];
    const float* W_in      = (const float*)d_in[4];
    const float* W_out     = (const float*)d_in[5];
    const float* b_out     = (const float*)d_in[6];
    float* out = (float*)d_out;

    cudaFuncSetAttribute(attn_kernel, cudaFuncAttributeMaxDynamicSharedMemorySize,
                         ATT_SMEM_BYTES);

    detect_mask_kernel<<<1, 32>>>((const unsigned int*)pre_mask);
    gemm_tf32<0><<<dim3(4, 128), 256>>>(entities, W_in, nullptr, nullptr, nullptr);              // Q
    gemm_tf32<1><<<dim3(8, 512), 256>>>(entities, W_in + 512 * 512, nullptr, nullptr, nullptr);  // K,V
    attn_kernel<<<dim3(8, 128), 256, ATT_SMEM_BYTES>>>(pre_mask, diff_mask);
    gemm_tf32<2><<<dim3(4, 128), 256>>>(nullptr, W_out, b_out, post_mask, out);                  // out
}

// round 10
// speedup vs baseline: 3.0055x; 1.0622x over previous
#include <cuda_runtime.h>
#include <cstdint>

// ---------------- scratch (static device globals; no allocation) ----------------
__device__ float g_Q[128 * 8 * 128 * 64];    // (bs,H,nq,hd)   32 MB
__device__ float g_K[128 * 8 * 512 * 64];    // (bs,H,ne,hd)  128 MB
__device__ float g_V[128 * 8 * 512 * 64];    // (bs,H,ne,hd)  128 MB
__device__ float g_Att[128 * 128 * 512];     // (bs,nq,E)      32 MB
__device__ int   g_mask_kind;                // 0=int32, 1=uint8, 2=float32

// ---------------- mask dtype handling ----------------
__device__ __forceinline__ bool mask_true(const void* p, size_t i, int kind) {
    if (kind == 1) return ((const unsigned char*)p)[i] != 0;
    if (kind == 0) return ((const int*)p)[i] != 0;
    return ((const float*)p)[i] != 0.0f;
}

__global__ void detect_mask_kernel(const unsigned int* __restrict__ pm) {
    if (threadIdx.x == 0) {
        bool is_i32 = true, is_f32 = true;
        for (int i = 0; i < 64; i++) {
            unsigned int w = pm[i];
            if (w != 0u && w != 1u) is_i32 = false;
            if (w != 0u && w != 0x3F800000u) is_f32 = false;
        }
        g_mask_kind = is_i32 ? 0 : (is_f32 ? 2 : 1);
    }
}

// ---------------- tf32 helpers ----------------
__device__ __forceinline__ uint32_t f2tf32(float f) {
    uint32_t r;
    asm("cvt.rna.tf32.f32 %0, %1;" : "=r"(r) : "f"(f));
    return r;
}

__device__ __forceinline__ void mma_tf32(float* c, const uint32_t* a,
                                         uint32_t b0, uint32_t b1) {
    asm volatile(
        "mma.sync.aligned.m16n8k8.row.col.f32.tf32.tf32.f32 "
        "{%0,%1,%2,%3}, {%4,%5,%6,%7}, {%8,%9}, {%0,%1,%2,%3};"
        : "+f"(c[0]), "+f"(c[1]), "+f"(c[2]), "+f"(c[3])
        : "r"(a[0]), "r"(a[1]), "r"(a[2]), "r"(a[3]), "r"(b0), "r"(b1));
}

// ---------------- interleaved-smem tf32 GEMM core ----------------
// smem layout per 128-row tile, pitch KPAD=24 words, 16 k-slots per row.
// k8 block stored as [k0,k4,k1,k5,k2,k6,k3,k7]:
//   slot(kt, j) = kt*8 + (j&3)*2 + (j>>2)
// => thread t reads its fragment pair (k+t, k+t+4) as ONE 64-bit load at kt*8 + 2t,
//    conflict-free for KPAD=24 (g*24 mod 32 = {0,24,16,8}).
#define KPAD 24

// Fused QKV projection:
//   blocks y <  512 : KV mode  C[65536][1024], W offset 512 rows -> g_K/g_V
//   blocks y >= 512 : Q  mode  C[16384][512] (A rows b*512+q)    -> g_Q (x0.125)
__global__ __launch_bounds__(256) void qkv_fused(const float* __restrict__ A,
                                                 const float* __restrict__ Wfull) {
    __shared__ uint32_t As[128 * KPAD];
    __shared__ uint32_t Bs[128 * KPAD];

    const int tid  = threadIdx.x;
    const int lane = tid & 31;
    const int wid  = tid >> 5;
    const int g    = lane >> 2;
    const int t    = lane & 3;
    const int wm   = (wid >> 1) << 5;
    const int wn   = (wid & 1) << 6;

    const bool qm = (blockIdx.y >= 512);
    int bm, bn;
    const float* Wbase;
    if (!qm) {
        bm = blockIdx.y << 7;
        bn = blockIdx.x << 7;
        Wbase = Wfull + (size_t)512 * 512;
    } else {
        const int idx = ((blockIdx.y - 512) << 3) + blockIdx.x;   // 0..511
        bm = (idx >> 2) << 7;
        bn = (idx & 3) << 7;
        Wbase = Wfull;
    }

    const int r  = tid >> 1;
    const int c0 = (tid & 1) << 3;
    int arow = bm + r;
    if (qm) arow = ((arow >> 7) << 9) | (arow & 127);     // b*512 + q
    const float* Aptr = A + (size_t)arow * 512;
    const float* Wptr = Wbase + (size_t)(bn + r) * 512;

    float c[2][8][4];
#pragma unroll
    for (int mt = 0; mt < 2; mt++)
#pragma unroll
        for (int nt = 0; nt < 8; nt++)
#pragma unroll
            for (int i = 0; i < 4; i++) c[mt][nt][i] = 0.f;

    float4 fa0 = *(const float4*)(Aptr + c0);
    float4 fa1 = *(const float4*)(Aptr + c0 + 4);
    float4 fb0 = *(const float4*)(Wptr + c0);
    float4 fb1 = *(const float4*)(Wptr + c0 + 4);

    for (int k0 = 0; k0 < 512; k0 += 16) {
        {   // interleaved staging: pairs (k, k+4) adjacent
            uint32_t* ar = As + r * KPAD + c0;
            ar[0] = f2tf32(fa0.x); ar[1] = f2tf32(fa1.x);
            ar[2] = f2tf32(fa0.y); ar[3] = f2tf32(fa1.y);
            ar[4] = f2tf32(fa0.z); ar[5] = f2tf32(fa1.z);
            ar[6] = f2tf32(fa0.w); ar[7] = f2tf32(fa1.w);
            uint32_t* br = Bs + r * KPAD + c0;
            br[0] = f2tf32(fb0.x); br[1] = f2tf32(fb1.x);
            br[2] = f2tf32(fb0.y); br[3] = f2tf32(fb1.y);
            br[4] = f2tf32(fb0.z); br[5] = f2tf32(fb1.z);
            br[6] = f2tf32(fb0.w); br[7] = f2tf32(fb1.w);
        }
        __syncthreads();

        if (k0 + 16 < 512) {
            fa0 = *(const float4*)(Aptr + k0 + 16 + c0);
            fa1 = *(const float4*)(Aptr + k0 + 16 + c0 + 4);
            fb0 = *(const float4*)(Wptr + k0 + 16 + c0);
            fb1 = *(const float4*)(Wptr + k0 + 16 + c0 + 4);
        }

#pragma unroll
        for (int kt = 0; kt < 2; kt++) {
            uint32_t afr[2][4];
#pragma unroll
            for (int mt = 0; mt < 2; mt++) {
                const uint32_t* ap = As + (wm + (mt << 4) + g) * KPAD + (kt << 3) + (t << 1);
                const uint2 lo = *(const uint2*)ap;
                const uint2 hi = *(const uint2*)(ap + 8 * KPAD);
                afr[mt][0] = lo.x; afr[mt][1] = hi.x;
                afr[mt][2] = lo.y; afr[mt][3] = hi.y;
            }
#pragma unroll
            for (int nt = 0; nt < 8; nt++) {
                const uint2 bb = *(const uint2*)(Bs + (wn + (nt << 3) + g) * KPAD + (kt << 3) + (t << 1));
                mma_tf32(c[0][nt], afr[0], bb.x, bb.y);
                mma_tf32(c[1][nt], afr[1], bb.x, bb.y);
            }
        }
        __syncthreads();
    }

    if (qm) {
        const int h = (bn + wn) >> 6;
#pragma unroll
        for (int mt = 0; mt < 2; mt++) {
            const int m0 = bm + wm + (mt << 4) + g;
            const int m1 = m0 + 8;
            float* p0 = g_Q + (size_t)(((((m0 >> 7) << 3) + h) << 7) + (m0 & 127)) * 64;
            float* p1 = g_Q + (size_t)(((((m1 >> 7) << 3) + h) << 7) + (m1 & 127)) * 64;
#pragma unroll
            for (int nt = 0; nt < 8; nt++) {
                const int d = (nt << 3) + (t << 1);
                *(float2*)(p0 + d) = make_float2(c[mt][nt][0] * 0.125f, c[mt][nt][1] * 0.125f);
                *(float2*)(p1 + d) = make_float2(c[mt][nt][2] * 0.125f, c[mt][nt][3] * 0.125f);
            }
        }
    } else {
        float* base = (bn >= 512) ? g_V : g_K;
        const int h = ((bn + wn) >> 6) & 7;
#pragma unroll
        for (int mt = 0; mt < 2; mt++) {
            const int m0 = bm + wm + (mt << 4) + g;
            const int m1 = m0 + 8;
            float* p0 = base + (size_t)(((((m0 >> 9) << 3) + h) << 9) + (m0 & 511)) * 64;
            float* p1 = base + (size_t)(((((m1 >> 9) << 3) + h) << 9) + (m1 & 511)) * 64;
#pragma unroll
            for (int nt = 0; nt < 8; nt++) {
                const int d = (nt << 3) + (t << 1);
                *(float2*)(p0 + d) = make_float2(c[mt][nt][0], c[mt][nt][1]);
                *(float2*)(p1 + d) = make_float2(c[mt][nt][2], c[mt][nt][3]);
            }
        }
    }
}

// Output projection: C = g_Att[16384][512] @ W_out[512][512]^T + bias, post-mask
__global__ __launch_bounds__(256) void out_gemm(const float* __restrict__ W,
                                                const float* __restrict__ bias,
                                                const void* __restrict__ post_mask,
                                                float* __restrict__ out) {
    __shared__ uint32_t As[128 * KPAD];
    __shared__ uint32_t Bs[128 * KPAD];

    const int tid  = threadIdx.x;
    const int lane = tid & 31;
    const int wid  = tid >> 5;
    const int g    = lane >> 2;
    const int t    = lane & 3;
    const int wm   = (wid >> 1) << 5;
    const int wn   = (wid & 1) << 6;
    const int bm   = blockIdx.y << 7;
    const int bn   = blockIdx.x << 7;

    const int r  = tid >> 1;
    const int c0 = (tid & 1) << 3;
    const float* Aptr = g_Att + (size_t)(bm + r) * 512;
    const float* Wptr = W + (size_t)(bn + r) * 512;

    float c[2][8][4];
#pragma unroll
    for (int mt = 0; mt < 2; mt++)
#pragma unroll
        for (int nt = 0; nt < 8; nt++)
#pragma unroll
            for (int i = 0; i < 4; i++) c[mt][nt][i] = 0.f;

    float4 fa0 = *(const float4*)(Aptr + c0);
    float4 fa1 = *(const float4*)(Aptr + c0 + 4);
    float4 fb0 = *(const float4*)(Wptr + c0);
    float4 fb1 = *(const float4*)(Wptr + c0 + 4);

    for (int k0 = 0; k0 < 512; k0 += 16) {
        {
            uint32_t* ar = As + r * KPAD + c0;
            ar[0] = f2tf32(fa0.x); ar[1] = f2tf32(fa1.x);
            ar[2] = f2tf32(fa0.y); ar[3] = f2tf32(fa1.y);
            ar[4] = f2tf32(fa0.z); ar[5] = f2tf32(fa1.z);
            ar[6] = f2tf32(fa0.w); ar[7] = f2tf32(fa1.w);
            uint32_t* br = Bs + r * KPAD + c0;
            br[0] = f2tf32(fb0.x); br[1] = f2tf32(fb1.x);
            br[2] = f2tf32(fb0.y); br[3] = f2tf32(fb1.y);
            br[4] = f2tf32(fb0.z); br[5] = f2tf32(fb1.z);
            br[6] = f2tf32(fb0.w); br[7] = f2tf32(fb1.w);
        }
        __syncthreads();

        if (k0 + 16 < 512) {
            fa0 = *(const float4*)(Aptr + k0 + 16 + c0);
            fa1 = *(const float4*)(Aptr + k0 + 16 + c0 + 4);
            fb0 = *(const float4*)(Wptr + k0 + 16 + c0);
            fb1 = *(const float4*)(Wptr + k0 + 16 + c0 + 4);
        }

#pragma unroll
        for (int kt = 0; kt < 2; kt++) {
            uint32_t afr[2][4];
#pragma unroll
            for (int mt = 0; mt < 2; mt++) {
                const uint32_t* ap = As + (wm + (mt << 4) + g) * KPAD + (kt << 3) + (t << 1);
                const uint2 lo = *(const uint2*)ap;
                const uint2 hi = *(const uint2*)(ap + 8 * KPAD);
                afr[mt][0] = lo.x; afr[mt][1] = hi.x;
                afr[mt][2] = lo.y; afr[mt][3] = hi.y;
            }
#pragma unroll
            for (int nt = 0; nt < 8; nt++) {
                const uint2 bb = *(const uint2*)(Bs + (wn + (nt << 3) + g) * KPAD + (kt << 3) + (t << 1));
                mma_tf32(c[0][nt], afr[0], bb.x, bb.y);
                mma_tf32(c[1][nt], afr[1], bb.x, bb.y);
            }
        }
        __syncthreads();
    }

    const int kind = g_mask_kind;
#pragma unroll
    for (int mt = 0; mt < 2; mt++) {
        const int m0 = bm + wm + (mt << 4) + g;
        const int m1 = m0 + 8;
        const bool pm0 = mask_true(post_mask, m0, kind);
        const bool pm1 = mask_true(post_mask, m1, kind);
        float* p0 = out + (size_t)m0 * 512 + bn + wn;
        float* p1 = out + (size_t)m1 * 512 + bn + wn;
#pragma unroll
        for (int nt = 0; nt < 8; nt++) {
            const int d = (nt << 3) + (t << 1);
            const float2 bb = *(const float2*)&bias[bn + wn + d];
            *(float2*)(p0 + d) = pm0 ? make_float2(0.f, 0.f)
                                     : make_float2(c[mt][nt][0] + bb.x, c[mt][nt][1] + bb.y);
            *(float2*)(p1 + d) = pm1 ? make_float2(0.f, 0.f)
                                     : make_float2(c[mt][nt][2] + bb.x, c[mt][nt][3] + bb.y);
        }
    }
}

// ---------------- K2: flash-style attention, one CTA per (b,h) ----------------
#define SM_STATS_W 8704
#define SM_KV_W    9728
#define ATT_SMEM_WORDS (9728 + 4 * 8704)
#define ATT_SMEM_BYTES (ATT_SMEM_WORDS * 4)

__global__ __launch_bounds__(256) void attn_kernel(const void* __restrict__ pre_mask,
                                                   const float* __restrict__ diff_mask) {
    extern __shared__ uint32_t smw[];
    uint32_t* Qs    = smw;
    float*    stats = (float*)(smw + SM_STATS_W);
    float*    KVbuf = (float*)(smw + SM_KV_W);

    const int tid  = threadIdx.x;
    const int lane = tid & 31;
    const int w    = tid >> 5;
    const int g    = lane >> 2;
    const int t    = lane & 3;
    const int wm   = (w >> 1) << 5;
    const int wn   = (w & 1) << 6;
    const bool odd = (t & 1);

    const int head = blockIdx.x, b = blockIdx.y;
    const int bh = (b << 3) + head;
    const float* Qg = g_Q + (size_t)bh * 128 * 64;
    const float* Kg = g_K + (size_t)bh * 512 * 64;
    const float* Vg = g_V + (size_t)bh * 512 * 64;
    const int kind = g_mask_kind;
    const size_t qrow0 = (size_t)b * 128;
    const float NEG_INF = __int_as_float(0xff800000u);

    {
        float* Kb = KVbuf;
        float* Vb = KVbuf + 8704;
#pragma unroll
        for (int i = 0; i < 8; i++) {
            const int idx = (i << 8) + tid;
            const int key = idx >> 4, d = (idx & 15) << 2;
            uint32_t sK = (uint32_t)__cvta_generic_to_shared(Kb + key * 68 + d);
            uint32_t sV = (uint32_t)__cvta_generic_to_shared(Vb + key * 68 + d);
            asm volatile("cp.async.cg.shared.global [%0], [%1], 16;" :: "r"(sK), "l"(Kg + (key << 6) + d));
            asm volatile("cp.async.cg.shared.global [%0], [%1], 16;" :: "r"(sV), "l"(Vg + (key << 6) + d));
        }
        asm volatile("cp.async.commit_group;");
    }

#pragma unroll
    for (int i = 0; i < 8; i++) {
        const int idx = (i << 8) + tid;
        const int q = idx >> 4, d = (idx & 15) << 2;
        const float4 v = *(const float4*)(Qg + (q << 6) + d);
        uint4 u;
        u.x = f2tf32(v.x); u.y = f2tf32(v.y); u.z = f2tf32(v.z); u.w = f2tf32(v.w);
        *(uint4*)&Qs[q * 68 + d] = u;
    }

    float m[4], E[4], D[4];
#pragma unroll
    for (int r = 0; r < 4; r++) { m[r] = NEG_INF; E[r] = 0.f; D[r] = 0.f; }
    float o[2][8][4];
#pragma unroll
    for (int mt = 0; mt < 2; mt++)
#pragma unroll
        for (int dn = 0; dn < 8; dn++)
#pragma unroll
            for (int i = 0; i < 4; i++) o[mt][dn][i] = 0.f;

    for (int tile = 0; tile < 4; tile++) {
        if (tile < 3) {
            const int nb = (tile + 1) & 1;
            float* Kb = KVbuf + (size_t)(nb * 2 + 0) * 8704;
            float* Vb = KVbuf + (size_t)(nb * 2 + 1) * 8704;
            const float* Kgt = Kg + (size_t)((tile + 1) << 7) * 64;
            const float* Vgt = Vg + (size_t)((tile + 1) << 7) * 64;
#pragma unroll
            for (int i = 0; i < 8; i++) {
                const int idx = (i << 8) + tid;
                const int key = idx >> 4, d = (idx & 15) << 2;
                uint32_t sK = (uint32_t)__cvta_generic_to_shared(Kb + key * 68 + d);
                uint32_t sV = (uint32_t)__cvta_generic_to_shared(Vb + key * 68 + d);
                asm volatile("cp.async.cg.shared.global [%0], [%1], 16;" :: "r"(sK), "l"(Kgt + (key << 6) + d));
                asm volatile("cp.async.cg.shared.global [%0], [%1], 16;" :: "r"(sV), "l"(Vgt + (key << 6) + d));
            }
            asm volatile("cp.async.commit_group;");
            asm volatile("cp.async.wait_group 1;");
        } else {
            asm volatile("cp.async.wait_group 0;");
        }
        __syncthreads();

        const float* Kb = KVbuf + (size_t)((tile & 1) * 2 + 0) * 8704;
        const float* Vb = KVbuf + (size_t)((tile & 1) * 2 + 1) * 8704;

        float2 dmx[4][8];
#pragma unroll
        for (int mt = 0; mt < 2; mt++)
#pragma unroll
            for (int hh = 0; hh < 2; hh++) {
                const int r = mt * 2 + hh;
                const size_t row = qrow0 + wm + (mt << 4) + (hh << 3) + g;
                const size_t base = row * 512 + (tile << 7) + wn + (t << 1);
#pragma unroll
                for (int nt = 0; nt < 8; nt++) {
                    const size_t ix = base + (nt << 3);
                    const float2 d2 = *(const float2*)(diff_mask + ix);
                    bool p0, p1;
                    if (kind == 1) {
                        const uchar2 u = *(const uchar2*)((const unsigned char*)pre_mask + ix);
                        p0 = u.x != 0; p1 = u.y != 0;
                    } else if (kind == 0) {
                        const int2 u = *(const int2*)((const int*)pre_mask + ix);
                        p0 = u.x != 0; p1 = u.y != 0;
                    } else {
                        const float2 u = *(const float2*)((const float*)pre_mask + ix);
                        p0 = u.x != 0.f; p1 = u.y != 0.f;
                    }
                    dmx[r][nt] = make_float2(p0 ? -1.f : d2.x, p1 ? -1.f : d2.y);
                }
            }

        float c[2][8][4];
#pragma unroll
        for (int mt = 0; mt < 2; mt++)
#pragma unroll
            for (int nt = 0; nt < 8; nt++)
#pragma unroll
                for (int i = 0; i < 4; i++) c[mt][nt][i] = 0.f;

#pragma unroll
        for (int ks = 0; ks < 8; ks++) {
            uint32_t afr[2][4];
#pragma unroll
            for (int mt = 0; mt < 2; mt++) {
                const uint32_t* ap = Qs + (wm + (mt << 4) + g) * 68 + (ks << 3) + t;
                afr[mt][0] = ap[0];
                afr[mt][1] = ap[8 * 68];
                afr[mt][2] = ap[4];
                afr[mt][3] = ap[8 * 68 + 4];
            }
#pragma unroll
            for (int nt = 0; nt < 8; nt++) {
                const float* kp = Kb + (wn + (nt << 3) + g) * 68 + (ks << 3) + t;
                const uint32_t b0 = f2tf32(kp[0]), b1 = f2tf32(kp[4]);
                mma_tf32(c[0][nt], afr[0], b0, b1);
                mma_tf32(c[1][nt], afr[1], b0, b1);
            }
        }

#pragma unroll
        for (int mt = 0; mt < 2; mt++)
#pragma unroll
            for (int hh = 0; hh < 2; hh++) {
                const int r = mt * 2 + hh;
                const int s0i = hh * 2, s1i = hh * 2 + 1;
                float tmax = NEG_INF;
#pragma unroll
                for (int nt = 0; nt < 8; nt++) {
                    const float2 dmv = dmx[r][nt];
                    float s0 = (dmv.x < 0.f) ? NEG_INF : c[mt][nt][s0i];
                    float s1 = (dmv.y < 0.f) ? NEG_INF : c[mt][nt][s1i];
                    c[mt][nt][s0i] = s0; c[mt][nt][s1i] = s1;
                    tmax = fmaxf(tmax, fmaxf(s0, s1));
                }
                tmax = fmaxf(tmax, __shfl_xor_sync(0xffffffffu, tmax, 1));
                tmax = fmaxf(tmax, __shfl_xor_sync(0xffffffffu, tmax, 2));
                const float mnew = fmaxf(m[r], tmax);
                const float sc = (m[r] == NEG_INF) ? 0.f : __expf(m[r] - mnew);
                m[r] = mnew;
                E[r] *= sc; D[r] *= sc;
#pragma unroll
                for (int dn = 0; dn < 8; dn++) { o[mt][dn][s0i] *= sc; o[mt][dn][s1i] *= sc; }
                float eacc = 0.f, dacc = 0.f;
#pragma unroll
                for (int nt = 0; nt < 8; nt++) {
                    const float2 dmv = dmx[r][nt];
                    const float s0 = c[mt][nt][s0i], s1 = c[mt][nt][s1i];
                    const float e0 = (s0 == NEG_INF) ? 0.f : __expf(s0 - mnew);
                    const float e1 = (s1 == NEG_INF) ? 0.f : __expf(s1 - mnew);
                    const float w0 = e0 * dmv.x, w1 = e1 * dmv.y;
                    eacc += e0 + e1; dacc += w0 + w1;
                    c[mt][nt][s0i] = w0; c[mt][nt][s1i] = w1;
                }
                E[r] += eacc; D[r] += dacc;
            }

        const int lo = (lane & ~3) | (t >> 1);
        const int hi = lo + 2;
#pragma unroll
        for (int ks = 0; ks < 8; ks++) {
            uint32_t af2[2][4];
#pragma unroll
            for (int mt = 0; mt < 2; mt++) {
                const float s0 = c[mt][ks][0], s1 = c[mt][ks][1];
                const float s2 = c[mt][ks][2], s3 = c[mt][ks][3];
                const float x0 = __shfl_sync(0xffffffffu, s0, lo);
                const float x1 = __shfl_sync(0xffffffffu, s1, lo);
                const float x2 = __shfl_sync(0xffffffffu, s2, lo);
                const float x3 = __shfl_sync(0xffffffffu, s3, lo);
                const float y0 = __shfl_sync(0xffffffffu, s0, hi);
                const float y1 = __shfl_sync(0xffffffffu, s1, hi);
                const float y2 = __shfl_sync(0xffffffffu, s2, hi);
                const float y3 = __shfl_sync(0xffffffffu, s3, hi);
                af2[mt][0] = f2tf32(odd ? x1 : x0);
                af2[mt][1] = f2tf32(odd ? x3 : x2);
                af2[mt][2] = f2tf32(odd ? y1 : y0);
                af2[mt][3] = f2tf32(odd ? y3 : y2);
            }
#pragma unroll
            for (int dn = 0; dn < 8; dn++) {
                const uint32_t b0 = f2tf32(Vb[(wn + (ks << 3) + t) * 68 + (dn << 3) + g]);
                const uint32_t b1 = f2tf32(Vb[(wn + (ks << 3) + t + 4) * 68 + (dn << 3) + g]);
                mma_tf32(o[0][dn], af2[0], b0, b1);
                mma_tf32(o[1][dn], af2[1], b0, b1);
            }
        }
        __syncthreads();
    }

#pragma unroll
    for (int r = 0; r < 4; r++) {
        E[r] += __shfl_xor_sync(0xffffffffu, E[r], 1);
        E[r] += __shfl_xor_sync(0xffffffffu, E[r], 2);
        D[r] += __shfl_xor_sync(0xffffffffu, D[r], 1);
        D[r] += __shfl_xor_sync(0xffffffffu, D[r], 2);
    }
    if (t == 0) {
#pragma unroll
        for (int mt = 0; mt < 2; mt++)
#pragma unroll
            for (int hh = 0; hh < 2; hh++) {
                const int r = mt * 2 + hh;
                float* sp = stats + ((w << 5) + (mt << 4) + (hh << 3) + g) * 4;
                sp[0] = m[r]; sp[1] = E[r]; sp[2] = D[r];
            }
    }
    __syncthreads();

    float fac[4];
#pragma unroll
    for (int mt = 0; mt < 2; mt++)
#pragma unroll
        for (int hh = 0; hh < 2; hh++) {
            const int r = mt * 2 + hh;
            const float* sp = stats + (((w ^ 1) << 5) + (mt << 4) + (hh << 3) + g) * 4;
            const float pm_ = sp[0], pE = sp[1], pD = sp[2];
            const float mt_ = fmaxf(m[r], pm_);
            const float ss = (m[r] == NEG_INF) ? 0.f : __expf(m[r] - mt_);
            const float sq = (pm_ == NEG_INF) ? 0.f : __expf(pm_ - mt_);
            const float Et = ss * E[r] + sq * pE;
            const float Dt = ss * D[r] + sq * pD;
            const float inv = (Et > 0.f) ? 1.f / (Dt + 1e-8f * Et) : 0.f;
            fac[r] = inv * ss;
        }
#pragma unroll
    for (int mt = 0; mt < 2; mt++)
#pragma unroll
        for (int dn = 0; dn < 8; dn++) {
            o[mt][dn][0] *= fac[mt * 2];     o[mt][dn][1] *= fac[mt * 2];
            o[mt][dn][2] *= fac[mt * 2 + 1]; o[mt][dn][3] *= fac[mt * 2 + 1];
        }

    float* Ored = KVbuf;
    if (w & 1) {
#pragma unroll
        for (int mt = 0; mt < 2; mt++) {
            const int q0 = wm + (mt << 4) + g;
#pragma unroll
            for (int dn = 0; dn < 8; dn++) {
                const int d = (dn << 3) + (t << 1);
                *(float2*)&Ored[q0 * 68 + d]       = make_float2(o[mt][dn][0], o[mt][dn][1]);
                *(float2*)&Ored[(q0 + 8) * 68 + d] = make_float2(o[mt][dn][2], o[mt][dn][3]);
            }
        }
    }
    __syncthreads();
    if (!(w & 1)) {
#pragma unroll
        for (int mt = 0; mt < 2; mt++) {
            const int q0 = wm + (mt << 4) + g;
#pragma unroll
            for (int dn = 0; dn < 8; dn++) {
                const int d = (dn << 3) + (t << 1);
                const float2 p0 = *(const float2*)&Ored[q0 * 68 + d];
                const float2 p1 = *(const float2*)&Ored[(q0 + 8) * 68 + d];
                const size_t ob = (qrow0 + q0) * 512 + (head << 6) + d;
                *(float2*)&g_Att[ob]             = make_float2(o[mt][dn][0] + p0.x, o[mt][dn][1] + p0.y);
                *(float2*)&g_Att[ob + 8 * 512]   = make_float2(o[mt][dn][2] + p1.x, o[mt][dn][3] + p1.y);
            }
        }
    }
}

// ---------------- launcher ----------------
extern "C" void kernel_launch(void* const* d_in, const int* in_sizes, int n_in,
                              void* d_out, int out_size) {
    (void)in_sizes; (void)n_in; (void)out_size;
    const float* entities  = (const float*)d_in[0];
    const void*  pre_mask  = d_in[1];
    const float* diff_mask = (const float*)d_in[2];
    const void*  post_mask = d_in[3];
    const float* W_in      = (const float*)d_in[4];
    const float* W_out     = (const float*)d_in[5];
    const float* b_out     = (const float*)d_in[6];
    float* out = (float*)d_out;

    cudaFuncSetAttribute(attn_kernel, cudaFuncAttributeMaxDynamicSharedMemorySize,
                         ATT_SMEM_BYTES);

    detect_mask_kernel<<<1, 32>>>((const unsigned int*)pre_mask);
    qkv_fused<<<dim3(8, 576), 256>>>(entities, W_in);                    // Q + K + V
    attn_kernel<<<dim3(8, 128), 256, ATT_SMEM_BYTES>>>(pre_mask, diff_mask);
    out_gemm<<<dim3(4, 128), 256>>>(W_out, b_out, post_mask, out);
}

// round 11
// speedup vs baseline: 3.1597x; 1.0513x over previous
#include <cuda_runtime.h>
#include <cstdint>

// ---------------- scratch (static device globals; no allocation) ----------------
__device__ float g_Q[128 * 8 * 128 * 64];    // (bs,H,nq,hd)   32 MB
__device__ float g_K[128 * 8 * 512 * 64];    // (bs,H,ne,hd)  128 MB
__device__ float g_V[128 * 8 * 512 * 64];    // (bs,H,ne,hd)  128 MB
__device__ float g_Att[128 * 128 * 512];     // (bs,nq,E)      32 MB
__device__ int   g_mask_kind;                // 0=int32, 1=uint8, 2=float32

// ---------------- mask dtype handling ----------------
__device__ __forceinline__ bool mask_true(const void* p, size_t i, int kind) {
    if (kind == 1) return ((const unsigned char*)p)[i] != 0;
    if (kind == 0) return ((const int*)p)[i] != 0;
    return ((const float*)p)[i] != 0.0f;
}

__global__ void detect_mask_kernel(const unsigned int* __restrict__ pm) {
    if (threadIdx.x == 0) {
        bool is_i32 = true, is_f32 = true;
        for (int i = 0; i < 64; i++) {
            unsigned int w = pm[i];
            if (w != 0u && w != 1u) is_i32 = false;
            if (w != 0u && w != 0x3F800000u) is_f32 = false;
        }
        g_mask_kind = is_i32 ? 0 : (is_f32 ? 2 : 1);
    }
}

// ---------------- tf32 helpers ----------------
__device__ __forceinline__ uint32_t f2tf32(float f) {
    uint32_t r;
    asm("cvt.rna.tf32.f32 %0, %1;" : "=r"(r) : "f"(f));
    return r;
}

__device__ __forceinline__ void mma_tf32(float* c, const uint32_t* a,
                                         uint32_t b0, uint32_t b1) {
    asm volatile(
        "mma.sync.aligned.m16n8k8.row.col.f32.tf32.tf32.f32 "
        "{%0,%1,%2,%3}, {%4,%5,%6,%7}, {%8,%9}, {%0,%1,%2,%3};"
        : "+f"(c[0]), "+f"(c[1]), "+f"(c[2]), "+f"(c[3])
        : "r"(a[0]), "r"(a[1]), "r"(a[2]), "r"(a[3]), "r"(b0), "r"(b1));
}

// ---------------- interleaved-smem tf32 GEMM core ----------------
// k8 block stored as [k0,k4,k1,k5,k2,k6,k3,k7] (pair (k+t, k+t+4) = one LDS.64 at 2t).
// KPAD=24: per-phase (16 lanes) g*24 mod 32 = {0,24,16,8} -> conflict-free LDS.64.
// Staging: the permutation == {f0.x,f1.x,f0.y,f1.y} / {f0.z,f1.z,f0.w,f1.w} -> 2x STS.128.
#define KPAD 24

// stage one 8-word k-group (fa0 = k[c..c+3], fa1 = k[c+4..c+7]) into interleaved smem
__device__ __forceinline__ void stage_pair(uint32_t* dst, const float4& f0, const float4& f1) {
    uint4 u0, u1;
    u0.x = f2tf32(f0.x); u0.y = f2tf32(f1.x); u0.z = f2tf32(f0.y); u0.w = f2tf32(f1.y);
    u1.x = f2tf32(f0.z); u1.y = f2tf32(f1.z); u1.z = f2tf32(f0.w); u1.w = f2tf32(f1.w);
    *(uint4*)dst       = u0;
    *(uint4*)(dst + 4) = u1;
}

// Fused QKV projection:
//   blocks y <  512 : KV mode  C[65536][1024], W offset 512 rows -> g_K/g_V
//   blocks y >= 512 : Q  mode  C[16384][512] (A rows b*512+q)    -> g_Q (x0.125)
__global__ __launch_bounds__(256, 2) void qkv_fused(const float* __restrict__ A,
                                                    const float* __restrict__ Wfull) {
    __shared__ uint32_t As[2][128 * KPAD];
    __shared__ uint32_t Bs[2][128 * KPAD];

    const int tid  = threadIdx.x;
    const int lane = tid & 31;
    const int wid  = tid >> 5;
    const int g    = lane >> 2;
    const int t    = lane & 3;
    const int wm   = (wid >> 1) << 5;
    const int wn   = (wid & 1) << 6;

    const bool qm = (blockIdx.y >= 512);
    int bm, bn;
    const float* Wbase;
    if (!qm) {
        bm = blockIdx.y << 7;
        bn = blockIdx.x << 7;
        Wbase = Wfull + (size_t)512 * 512;
    } else {
        const int idx = ((blockIdx.y - 512) << 3) + blockIdx.x;   // 0..511
        bm = (idx >> 2) << 7;
        bn = (idx & 3) << 7;
        Wbase = Wfull;
    }

    const int r  = tid >> 1;
    const int c0 = (tid & 1) << 3;
    int arow = bm + r;
    if (qm) arow = ((arow >> 7) << 9) | (arow & 127);     // b*512 + q
    const float* Aptr = A + (size_t)arow * 512;
    const float* Wptr = Wbase + (size_t)(bn + r) * 512;

    float c[2][8][4];
#pragma unroll
    for (int mt = 0; mt < 2; mt++)
#pragma unroll
        for (int nt = 0; nt < 8; nt++)
#pragma unroll
            for (int i = 0; i < 4; i++) c[mt][nt][i] = 0.f;

    float4 fa0 = *(const float4*)(Aptr + c0);
    float4 fa1 = *(const float4*)(Aptr + c0 + 4);
    float4 fb0 = *(const float4*)(Wptr + c0);
    float4 fb1 = *(const float4*)(Wptr + c0 + 4);

    for (int k0 = 0; k0 < 512; k0 += 16) {
        const int buf = (k0 >> 4) & 1;
        stage_pair(As[buf] + r * KPAD + c0, fa0, fa1);
        stage_pair(Bs[buf] + r * KPAD + c0, fb0, fb1);
        __syncthreads();

        if (k0 + 16 < 512) {
            fa0 = *(const float4*)(Aptr + k0 + 16 + c0);
            fa1 = *(const float4*)(Aptr + k0 + 16 + c0 + 4);
            fb0 = *(const float4*)(Wptr + k0 + 16 + c0);
            fb1 = *(const float4*)(Wptr + k0 + 16 + c0 + 4);
        }

#pragma unroll
        for (int kt = 0; kt < 2; kt++) {
            uint32_t afr[2][4];
#pragma unroll
            for (int mt = 0; mt < 2; mt++) {
                const uint32_t* ap = As[buf] + (wm + (mt << 4) + g) * KPAD + (kt << 3) + (t << 1);
                const uint2 lo = *(const uint2*)ap;
                const uint2 hi = *(const uint2*)(ap + 8 * KPAD);
                afr[mt][0] = lo.x; afr[mt][1] = hi.x;
                afr[mt][2] = lo.y; afr[mt][3] = hi.y;
            }
#pragma unroll
            for (int nt = 0; nt < 8; nt++) {
                const uint2 bb = *(const uint2*)(Bs[buf] + (wn + (nt << 3) + g) * KPAD + (kt << 3) + (t << 1));
                mma_tf32(c[0][nt], afr[0], bb.x, bb.y);
                mma_tf32(c[1][nt], afr[1], bb.x, bb.y);
            }
        }
        // no trailing sync: next iter stages the OTHER buffer; its sync orders reuse
    }

    if (qm) {
        const int h = (bn + wn) >> 6;
#pragma unroll
        for (int mt = 0; mt < 2; mt++) {
            const int m0 = bm + wm + (mt << 4) + g;
            const int m1 = m0 + 8;
            float* p0 = g_Q + (size_t)(((((m0 >> 7) << 3) + h) << 7) + (m0 & 127)) * 64;
            float* p1 = g_Q + (size_t)(((((m1 >> 7) << 3) + h) << 7) + (m1 & 127)) * 64;
#pragma unroll
            for (int nt = 0; nt < 8; nt++) {
                const int d = (nt << 3) + (t << 1);
                *(float2*)(p0 + d) = make_float2(c[mt][nt][0] * 0.125f, c[mt][nt][1] * 0.125f);
                *(float2*)(p1 + d) = make_float2(c[mt][nt][2] * 0.125f, c[mt][nt][3] * 0.125f);
            }
        }
    } else {
        float* base = (bn >= 512) ? g_V : g_K;
        const int h = ((bn + wn) >> 6) & 7;
#pragma unroll
        for (int mt = 0; mt < 2; mt++) {
            const int m0 = bm + wm + (mt << 4) + g;
            const int m1 = m0 + 8;
            float* p0 = base + (size_t)(((((m0 >> 9) << 3) + h) << 9) + (m0 & 511)) * 64;
            float* p1 = base + (size_t)(((((m1 >> 9) << 3) + h) << 9) + (m1 & 511)) * 64;
#pragma unroll
            for (int nt = 0; nt < 8; nt++) {
                const int d = (nt << 3) + (t << 1);
                *(float2*)(p0 + d) = make_float2(c[mt][nt][0], c[mt][nt][1]);
                *(float2*)(p1 + d) = make_float2(c[mt][nt][2], c[mt][nt][3]);
            }
        }
    }
}

// Output projection: C = g_Att[16384][512] @ W_out[512][512]^T + bias, post-mask
__global__ __launch_bounds__(256, 2) void out_gemm(const float* __restrict__ W,
                                                   const float* __restrict__ bias,
                                                   const void* __restrict__ post_mask,
                                                   float* __restrict__ out) {
    __shared__ uint32_t As[2][128 * KPAD];
    __shared__ uint32_t Bs[2][128 * KPAD];

    const int tid  = threadIdx.x;
    const int lane = tid & 31;
    const int wid  = tid >> 5;
    const int g    = lane >> 2;
    const int t    = lane & 3;
    const int wm   = (wid >> 1) << 5;
    const int wn   = (wid & 1) << 6;
    const int bm   = blockIdx.y << 7;
    const int bn   = blockIdx.x << 7;

    const int r  = tid >> 1;
    const int c0 = (tid & 1) << 3;
    const float* Aptr = g_Att + (size_t)(bm + r) * 512;
    const float* Wptr = W + (size_t)(bn + r) * 512;

    float c[2][8][4];
#pragma unroll
    for (int mt = 0; mt < 2; mt++)
#pragma unroll
        for (int nt = 0; nt < 8; nt++)
#pragma unroll
            for (int i = 0; i < 4; i++) c[mt][nt][i] = 0.f;

    float4 fa0 = *(const float4*)(Aptr + c0);
    float4 fa1 = *(const float4*)(Aptr + c0 + 4);
    float4 fb0 = *(const float4*)(Wptr + c0);
    float4 fb1 = *(const float4*)(Wptr + c0 + 4);

    for (int k0 = 0; k0 < 512; k0 += 16) {
        const int buf = (k0 >> 4) & 1;
        stage_pair(As[buf] + r * KPAD + c0, fa0, fa1);
        stage_pair(Bs[buf] + r * KPAD + c0, fb0, fb1);
        __syncthreads();

        if (k0 + 16 < 512) {
            fa0 = *(const float4*)(Aptr + k0 + 16 + c0);
            fa1 = *(const float4*)(Aptr + k0 + 16 + c0 + 4);
            fb0 = *(const float4*)(Wptr + k0 + 16 + c0);
            fb1 = *(const float4*)(Wptr + k0 + 16 + c0 + 4);
        }

#pragma unroll
        for (int kt = 0; kt < 2; kt++) {
            uint32_t afr[2][4];
#pragma unroll
            for (int mt = 0; mt < 2; mt++) {
                const uint32_t* ap = As[buf] + (wm + (mt << 4) + g) * KPAD + (kt << 3) + (t << 1);
                const uint2 lo = *(const uint2*)ap;
                const uint2 hi = *(const uint2*)(ap + 8 * KPAD);
                afr[mt][0] = lo.x; afr[mt][1] = hi.x;
                afr[mt][2] = lo.y; afr[mt][3] = hi.y;
            }
#pragma unroll
            for (int nt = 0; nt < 8; nt++) {
                const uint2 bb = *(const uint2*)(Bs[buf] + (wn + (nt << 3) + g) * KPAD + (kt << 3) + (t << 1));
                mma_tf32(c[0][nt], afr[0], bb.x, bb.y);
                mma_tf32(c[1][nt], afr[1], bb.x, bb.y);
            }
        }
    }

    const int kind = g_mask_kind;
#pragma unroll
    for (int mt = 0; mt < 2; mt++) {
        const int m0 = bm + wm + (mt << 4) + g;
        const int m1 = m0 + 8;
        const bool pm0 = mask_true(post_mask, m0, kind);
        const bool pm1 = mask_true(post_mask, m1, kind);
        float* p0 = out + (size_t)m0 * 512 + bn + wn;
        float* p1 = out + (size_t)m1 * 512 + bn + wn;
#pragma unroll
        for (int nt = 0; nt < 8; nt++) {
            const int d = (nt << 3) + (t << 1);
            const float2 bb = *(const float2*)&bias[bn + wn + d];
            *(float2*)(p0 + d) = pm0 ? make_float2(0.f, 0.f)
                                     : make_float2(c[mt][nt][0] + bb.x, c[mt][nt][1] + bb.y);
            *(float2*)(p1 + d) = pm1 ? make_float2(0.f, 0.f)
                                     : make_float2(c[mt][nt][2] + bb.x, c[mt][nt][3] + bb.y);
        }
    }
}

// ---------------- K2: flash-style attention, one CTA per (b,h) ----------------
#define SM_STATS_W 8704
#define SM_KV_W    9728
#define ATT_SMEM_WORDS (9728 + 4 * 8704)
#define ATT_SMEM_BYTES (ATT_SMEM_WORDS * 4)

__global__ __launch_bounds__(256) void attn_kernel(const void* __restrict__ pre_mask,
                                                   const float* __restrict__ diff_mask) {
    extern __shared__ uint32_t smw[];
    uint32_t* Qs    = smw;
    float*    stats = (float*)(smw + SM_STATS_W);
    float*    KVbuf = (float*)(smw + SM_KV_W);

    const int tid  = threadIdx.x;
    const int lane = tid & 31;
    const int w    = tid >> 5;
    const int g    = lane >> 2;
    const int t    = lane & 3;
    const int wm   = (w >> 1) << 5;
    const int wn   = (w & 1) << 6;
    const bool odd = (t & 1);

    const int head = blockIdx.x, b = blockIdx.y;
    const int bh = (b << 3) + head;
    const float* Qg = g_Q + (size_t)bh * 128 * 64;
    const float* Kg = g_K + (size_t)bh * 512 * 64;
    const float* Vg = g_V + (size_t)bh * 512 * 64;
    const int kind = g_mask_kind;
    const size_t qrow0 = (size_t)b * 128;
    const float NEG_INF = __int_as_float(0xff800000u);

    {
        float* Kb = KVbuf;
        float* Vb = KVbuf + 8704;
#pragma unroll
        for (int i = 0; i < 8; i++) {
            const int idx = (i << 8) + tid;
            const int key = idx >> 4, d = (idx & 15) << 2;
            uint32_t sK = (uint32_t)__cvta_generic_to_shared(Kb + key * 68 + d);
            uint32_t sV = (uint32_t)__cvta_generic_to_shared(Vb + key * 68 + d);
            asm volatile("cp.async.cg.shared.global [%0], [%1], 16;" :: "r"(sK), "l"(Kg + (key << 6) + d));
            asm volatile("cp.async.cg.shared.global [%0], [%1], 16;" :: "r"(sV), "l"(Vg + (key << 6) + d));
        }
        asm volatile("cp.async.commit_group;");
    }

#pragma unroll
    for (int i = 0; i < 8; i++) {
        const int idx = (i << 8) + tid;
        const int q = idx >> 4, d = (idx & 15) << 2;
        const float4 v = *(const float4*)(Qg + (q << 6) + d);
        uint4 u;
        u.x = f2tf32(v.x); u.y = f2tf32(v.y); u.z = f2tf32(v.z); u.w = f2tf32(v.w);
        *(uint4*)&Qs[q * 68 + d] = u;
    }

    float m[4], E[4], D[4];
#pragma unroll
    for (int r = 0; r < 4; r++) { m[r] = NEG_INF; E[r] = 0.f; D[r] = 0.f; }
    float o[2][8][4];
#pragma unroll
    for (int mt = 0; mt < 2; mt++)
#pragma unroll
        for (int dn = 0; dn < 8; dn++)
#pragma unroll
            for (int i = 0; i < 4; i++) o[mt][dn][i] = 0.f;

    for (int tile = 0; tile < 4; tile++) {
        if (tile < 3) {
            const int nb = (tile + 1) & 1;
            float* Kb = KVbuf + (size_t)(nb * 2 + 0) * 8704;
            float* Vb = KVbuf + (size_t)(nb * 2 + 1) * 8704;
            const float* Kgt = Kg + (size_t)((tile + 1) << 7) * 64;
            const float* Vgt = Vg + (size_t)((tile + 1) << 7) * 64;
#pragma unroll
            for (int i = 0; i < 8; i++) {
                const int idx = (i << 8) + tid;
                const int key = idx >> 4, d = (idx & 15) << 2;
                uint32_t sK = (uint32_t)__cvta_generic_to_shared(Kb + key * 68 + d);
                uint32_t sV = (uint32_t)__cvta_generic_to_shared(Vb + key * 68 + d);
                asm volatile("cp.async.cg.shared.global [%0], [%1], 16;" :: "r"(sK), "l"(Kgt + (key << 6) + d));
                asm volatile("cp.async.cg.shared.global [%0], [%1], 16;" :: "r"(sV), "l"(Vgt + (key << 6) + d));
            }
            asm volatile("cp.async.commit_group;");
            asm volatile("cp.async.wait_group 1;");
        } else {
            asm volatile("cp.async.wait_group 0;");
        }
        __syncthreads();

        const float* Kb = KVbuf + (size_t)((tile & 1) * 2 + 0) * 8704;
        const float* Vb = KVbuf + (size_t)((tile & 1) * 2 + 1) * 8704;

        float2 dmx[4][8];
#pragma unroll
        for (int mt = 0; mt < 2; mt++)
#pragma unroll
            for (int hh = 0; hh < 2; hh++) {
                const int r = mt * 2 + hh;
                const size_t row = qrow0 + wm + (mt << 4) + (hh << 3) + g;
                const size_t base = row * 512 + (tile << 7) + wn + (t << 1);
#pragma unroll
                for (int nt = 0; nt < 8; nt++) {
                    const size_t ix = base + (nt << 3);
                    const float2 d2 = *(const float2*)(diff_mask + ix);
                    bool p0, p1;
                    if (kind == 1) {
                        const uchar2 u = *(const uchar2*)((const unsigned char*)pre_mask + ix);
                        p0 = u.x != 0; p1 = u.y != 0;
                    } else if (kind == 0) {
                        const int2 u = *(const int2*)((const int*)pre_mask + ix);
                        p0 = u.x != 0; p1 = u.y != 0;
                    } else {
                        const float2 u = *(const float2*)((const float*)pre_mask + ix);
                        p0 = u.x != 0.f; p1 = u.y != 0.f;
                    }
                    dmx[r][nt] = make_float2(p0 ? -1.f : d2.x, p1 ? -1.f : d2.y);
                }
            }

        float c[2][8][4];
#pragma unroll
        for (int mt = 0; mt < 2; mt++)
#pragma unroll
            for (int nt = 0; nt < 8; nt++)
#pragma unroll
                for (int i = 0; i < 4; i++) c[mt][nt][i] = 0.f;

#pragma unroll
        for (int ks = 0; ks < 8; ks++) {
            uint32_t afr[2][4];
#pragma unroll
            for (int mt = 0; mt < 2; mt++) {
                const uint32_t* ap = Qs + (wm + (mt << 4) + g) * 68 + (ks << 3) + t;
                afr[mt][0] = ap[0];
                afr[mt][1] = ap[8 * 68];
                afr[mt][2] = ap[4];
                afr[mt][3] = ap[8 * 68 + 4];
            }
#pragma unroll
            for (int nt = 0; nt < 8; nt++) {
                const float* kp = Kb + (wn + (nt << 3) + g) * 68 + (ks << 3) + t;
                const uint32_t b0 = f2tf32(kp[0]), b1 = f2tf32(kp[4]);
                mma_tf32(c[0][nt], afr[0], b0, b1);
                mma_tf32(c[1][nt], afr[1], b0, b1);
            }
        }

#pragma unroll
        for (int mt = 0; mt < 2; mt++)
#pragma unroll
            for (int hh = 0; hh < 2; hh++) {
                const int r = mt * 2 + hh;
                const int s0i = hh * 2, s1i = hh * 2 + 1;
                float tmax = NEG_INF;
#pragma unroll
                for (int nt = 0; nt < 8; nt++) {
                    const float2 dmv = dmx[r][nt];
                    float s0 = (dmv.x < 0.f) ? NEG_INF : c[mt][nt][s0i];
                    float s1 = (dmv.y < 0.f) ? NEG_INF : c[mt][nt][s1i];
                    c[mt][nt][s0i] = s0; c[mt][nt][s1i] = s1;
                    tmax = fmaxf(tmax, fmaxf(s0, s1));
                }
                tmax = fmaxf(tmax, __shfl_xor_sync(0xffffffffu, tmax, 1));
                tmax = fmaxf(tmax, __shfl_xor_sync(0xffffffffu, tmax, 2));
                const float mnew = fmaxf(m[r], tmax);
                const float sc = (m[r] == NEG_INF) ? 0.f : __expf(m[r] - mnew);
                m[r] = mnew;
                E[r] *= sc; D[r] *= sc;
#pragma unroll
                for (int dn = 0; dn < 8; dn++) { o[mt][dn][s0i] *= sc; o[mt][dn][s1i] *= sc; }
                float eacc = 0.f, dacc = 0.f;
#pragma unroll
                for (int nt = 0; nt < 8; nt++) {
                    const float2 dmv = dmx[r][nt];
                    const float s0 = c[mt][nt][s0i], s1 = c[mt][nt][s1i];
                    const float e0 = (s0 == NEG_INF) ? 0.f : __expf(s0 - mnew);
                    const float e1 = (s1 == NEG_INF) ? 0.f : __expf(s1 - mnew);
                    const float w0 = e0 * dmv.x, w1 = e1 * dmv.y;
                    eacc += e0 + e1; dacc += w0 + w1;
                    c[mt][nt][s0i] = w0; c[mt][nt][s1i] = w1;
                }
                E[r] += eacc; D[r] += dacc;
            }

        const int lo = (lane & ~3) | (t >> 1);
        const int hi = lo + 2;
#pragma unroll
        for (int ks = 0; ks < 8; ks++) {
            uint32_t af2[2][4];
#pragma unroll
            for (int mt = 0; mt < 2; mt++) {
                const float s0 = c[mt][ks][0], s1 = c[mt][ks][1];
                const float s2 = c[mt][ks][2], s3 = c[mt][ks][3];
                const float x0 = __shfl_sync(0xffffffffu, s0, lo);
                const float x1 = __shfl_sync(0xffffffffu, s1, lo);
                const float x2 = __shfl_sync(0xffffffffu, s2, lo);
                const float x3 = __shfl_sync(0xffffffffu, s3, lo);
                const float y0 = __shfl_sync(0xffffffffu, s0, hi);
                const float y1 = __shfl_sync(0xffffffffu, s1, hi);
                const float y2 = __shfl_sync(0xffffffffu, s2, hi);
                const float y3 = __shfl_sync(0xffffffffu, s3, hi);
                af2[mt][0] = f2tf32(odd ? x1 : x0);
                af2[mt][1] = f2tf32(odd ? x3 : x2);
                af2[mt][2] = f2tf32(odd ? y1 : y0);
                af2[mt][3] = f2tf32(odd ? y3 : y2);
            }
#pragma unroll
            for (int dn = 0; dn < 8; dn++) {
                const uint32_t b0 = f2tf32(Vb[(wn + (ks << 3) + t) * 68 + (dn << 3) + g]);
                const uint32_t b1 = f2tf32(Vb[(wn + (ks << 3) + t + 4) * 68 + (dn << 3) + g]);
                mma_tf32(o[0][dn], af2[0], b0, b1);
                mma_tf32(o[1][dn], af2[1], b0, b1);
            }
        }
        __syncthreads();
    }

#pragma unroll
    for (int r = 0; r < 4; r++) {
        E[r] += __shfl_xor_sync(0xffffffffu, E[r], 1);
        E[r] += __shfl_xor_sync(0xffffffffu, E[r], 2);
        D[r] += __shfl_xor_sync(0xffffffffu, D[r], 1);
        D[r] += __shfl_xor_sync(0xffffffffu, D[r], 2);
    }
    if (t == 0) {
#pragma unroll
        for (int mt = 0; mt < 2; mt++)
#pragma unroll
            for (int hh = 0; hh < 2; hh++) {
                const int r = mt * 2 + hh;
                float* sp = stats + ((w << 5) + (mt << 4) + (hh << 3) + g) * 4;
                sp[0] = m[r]; sp[1] = E[r]; sp[2] = D[r];
            }
    }
    __syncthreads();

    float fac[4];
#pragma unroll
    for (int mt = 0; mt < 2; mt++)
#pragma unroll
        for (int hh = 0; hh < 2; hh++) {
            const int r = mt * 2 + hh;
            const float* sp = stats + (((w ^ 1) << 5) + (mt << 4) + (hh << 3) + g) * 4;
            const float pm_ = sp[0], pE = sp[1], pD = sp[2];
            const float mt_ = fmaxf(m[r], pm_);
            const float ss = (m[r] == NEG_INF) ? 0.f : __expf(m[r] - mt_);
            const float sq = (pm_ == NEG_INF) ? 0.f : __expf(pm_ - mt_);
            const float Et = ss * E[r] + sq * pE;
            const float Dt = ss * D[r] + sq * pD;
            const float inv = (Et > 0.f) ? 1.f / (Dt + 1e-8f * Et) : 0.f;
            fac[r] = inv * ss;
        }
#pragma unroll
    for (int mt = 0; mt < 2; mt++)
#pragma unroll
        for (int dn = 0; dn < 8; dn++) {
            o[mt][dn][0] *= fac[mt * 2];     o[mt][dn][1] *= fac[mt * 2];
            o[mt][dn][2] *= fac[mt * 2 + 1]; o[mt][dn][3] *= fac[mt * 2 + 1];
        }

    float* Ored = KVbuf;
    if (w & 1) {
#pragma unroll
        for (int mt = 0; mt < 2; mt++) {
            const int q0 = wm + (mt << 4) + g;
#pragma unroll
            for (int dn = 0; dn < 8; dn++) {
                const int d = (dn << 3) + (t << 1);
                *(float2*)&Ored[q0 * 68 + d]       = make_float2(o[mt][dn][0], o[mt][dn][1]);
                *(float2*)&Ored[(q0 + 8) * 68 + d] = make_float2(o[mt][dn][2], o[mt][dn][3]);
            }
        }
    }
    __syncthreads();
    if (!(w & 1)) {
#pragma unroll
        for (int mt = 0; mt < 2; mt++) {
            const int q0 = wm + (mt << 4) + g;
#pragma unroll
            for (int dn = 0; dn < 8; dn++) {
                const int d = (dn << 3) + (t << 1);
                const float2 p0 = *(const float2*)&Ored[q0 * 68 + d];
                const float2 p1 = *(const float2*)&Ored[(q0 + 8) * 68 + d];
                const size_t ob = (qrow0 + q0) * 512 + (head << 6) + d;
                *(float2*)&g_Att[ob]             = make_float2(o[mt][dn][0] + p0.x, o[mt][dn][1] + p0.y);
                *(float2*)&g_Att[ob + 8 * 512]   = make_float2(o[mt][dn][2] + p1.x, o[mt][dn][3] + p1.y);
            }
        }
    }
}

// ---------------- launcher ----------------
extern "C" void kernel_launch(void* const* d_in, const int* in_sizes, int n_in,
                              void* d_out, int out_size) {
    (void)in_sizes; (void)n_in; (void)out_size;
    const float* entities  = (const float*)d_in[0];
    const void*  pre_mask  = d_in[1];
    const float* diff_mask = (const float*)d_in[2];
    const void*  post_mask = d_in[3];
    const float* W_in      = (const float*)d_in[4];
    const float* W_out     = (const float*)d_in[5];
    const float* b_out     = (const float*)d_in[6];
    float* out = (float*)d_out;

    cudaFuncSetAttribute(attn_kernel, cudaFuncAttributeMaxDynamicSharedMemorySize,
                         ATT_SMEM_BYTES);

    detect_mask_kernel<<<1, 32>>>((const unsigned int*)pre_mask);
    qkv_fused<<<dim3(8, 576), 256>>>(entities, W_in);                    // Q + K + V
    attn_kernel<<<dim3(8, 128), 256, ATT_SMEM_BYTES>>>(pre_mask, diff_mask);
    out_gemm<<<dim3(4, 128), 256>>>(W_out, b_out, post_mask, out);
}

// round 12
// speedup vs baseline: 4.0566x; 1.2839x over previous
#include <cuda_runtime.h>
#include <cuda_fp16.h>
#include <cstdint>

// ---------------- scratch (static device globals; no allocation) ----------------
__device__ float g_Q[128 * 8 * 128 * 64];    // (bs,H,nq,hd)   32 MB
__device__ float g_K[128 * 8 * 512 * 64];    // (bs,H,ne,hd)  128 MB
__device__ float g_V[128 * 8 * 512 * 64];    // (bs,H,ne,hd)  128 MB
__device__ float g_Att[128 * 128 * 512];     // (bs,nq,E)      32 MB
__device__ int   g_mask_kind;                // 0=int32, 1=uint8, 2=float32

// ---------------- mask dtype handling ----------------
__device__ __forceinline__ bool mask_true(const void* p, size_t i, int kind) {
    if (kind == 1) return ((const unsigned char*)p)[i] != 0;
    if (kind == 0) return ((const int*)p)[i] != 0;
    return ((const float*)p)[i] != 0.0f;
}

__global__ void detect_mask_kernel(const unsigned int* __restrict__ pm) {
    if (threadIdx.x == 0) {
        bool is_i32 = true, is_f32 = true;
        for (int i = 0; i < 64; i++) {
            unsigned int w = pm[i];
            if (w != 0u && w != 1u) is_i32 = false;
            if (w != 0u && w != 0x3F800000u) is_f32 = false;
        }
        g_mask_kind = is_i32 ? 0 : (is_f32 ? 2 : 1);
    }
}

// ---------------- tf32 helpers (attention kernel) ----------------
__device__ __forceinline__ uint32_t f2tf32(float f) {
    uint32_t r;
    asm("cvt.rna.tf32.f32 %0, %1;" : "=r"(r) : "f"(f));
    return r;
}

__device__ __forceinline__ void mma_tf32(float* c, const uint32_t* a,
                                         uint32_t b0, uint32_t b1) {
    asm volatile(
        "mma.sync.aligned.m16n8k8.row.col.f32.tf32.tf32.f32 "
        "{%0,%1,%2,%3}, {%4,%5,%6,%7}, {%8,%9}, {%0,%1,%2,%3};"
        : "+f"(c[0]), "+f"(c[1]), "+f"(c[2]), "+f"(c[3])
        : "r"(a[0]), "r"(a[1]), "r"(a[2]), "r"(a[3]), "r"(b0), "r"(b1));
}

// ---------------- fp16 helpers (GEMMs) ----------------
// pack2(a,b): low half = a (even k), high half = b (odd k)
__device__ __forceinline__ uint32_t pack2(float a, float b) {
    uint32_t r;
    asm("cvt.rn.f16x2.f32 %0, %1, %2;" : "=r"(r) : "f"(b), "f"(a));
    return r;
}

__device__ __forceinline__ void mma_f16(float* c, uint32_t a0, uint32_t a1,
                                        uint32_t a2, uint32_t a3,
                                        uint32_t b0, uint32_t b1) {
    asm volatile(
        "mma.sync.aligned.m16n8k16.row.col.f32.f16.f16.f32 "
        "{%0,%1,%2,%3}, {%4,%5,%6,%7}, {%8,%9}, {%0,%1,%2,%3};"
        : "+f"(c[0]), "+f"(c[1]), "+f"(c[2]), "+f"(c[3])
        : "r"(a0), "r"(a1), "r"(a2), "r"(a3), "r"(b0), "r"(b1));
}

// ---------------- fp16 GEMM smem layout ----------------
// Per k16 stage: row = 16 halves = 32B = 8 words, pitch 8 words (no pad).
// Pair-interleaved order per row: words = [(k0,k1),(k8,k9),(k2,k3),(k10,k11),
//                                          (k4,k5),(k12,k13),(k6,k7),(k14,k15)]
// => fragment pair (2t,2t+1)&(2t+8,2t+9) = one LDS.64 at word 2t.
// LDS.64 16-lane phase: 4 rows x 32B = 128B disjoint -> conflict-free.
// STS.128 8-lane phase: 4 rows x 2 chunks x 16B = 128B disjoint -> conflict-free.

// stage one row's k16 from two float4 (q0 = k[c..c+3], q1 = k[c+8..c+11])
__device__ __forceinline__ void stage16(uint32_t* dst, const float4& q0, const float4& q1) {
    uint4 u;
    u.x = pack2(q0.x, q0.y);
    u.y = pack2(q1.x, q1.y);
    u.z = pack2(q0.z, q0.w);
    u.w = pack2(q1.z, q1.w);
    *(uint4*)dst = u;
}

// Fused QKV projection:
//   blocks y <  512 : KV mode  C[65536][1024], W offset 512 rows -> g_K/g_V
//   blocks y >= 512 : Q  mode  C[16384][512] (A rows b*512+q)    -> g_Q (x0.125)
__global__ __launch_bounds__(256, 2) void qkv_fused(const float* __restrict__ A,
                                                    const float* __restrict__ Wfull) {
    __shared__ uint32_t As[2][128 * 8];
    __shared__ uint32_t Bs[2][128 * 8];

    const int tid  = threadIdx.x;
    const int lane = tid & 31;
    const int wid  = tid >> 5;
    const int g    = lane >> 2;
    const int t    = lane & 3;
    const int wm   = (wid >> 1) << 5;
    const int wn   = (wid & 1) << 6;

    const bool qm = (blockIdx.y >= 512);
    int bm, bn;
    const float* Wbase;
    if (!qm) {
        bm = blockIdx.y << 7;
        bn = blockIdx.x << 7;
        Wbase = Wfull + (size_t)512 * 512;
    } else {
        const int idx = ((blockIdx.y - 512) << 3) + blockIdx.x;   // 0..511
        bm = (idx >> 2) << 7;
        bn = (idx & 3) << 7;
        Wbase = Wfull;
    }

    const int r = tid >> 1;          // staged row
    const int h = tid & 1;           // chunk half: k-cols {h*4..h*4+3, h*4+8..h*4+11}
    int arow = bm + r;
    if (qm) arow = ((arow >> 7) << 9) | (arow & 127);     // b*512 + q
    const float* Aptr = A + (size_t)arow * 512 + (h << 2);
    const float* Wptr = Wbase + (size_t)(bn + r) * 512 + (h << 2);

    float c[2][8][4];
#pragma unroll
    for (int mt = 0; mt < 2; mt++)
#pragma unroll
        for (int nt = 0; nt < 8; nt++)
#pragma unroll
            for (int i = 0; i < 4; i++) c[mt][nt][i] = 0.f;

    float4 qa0 = *(const float4*)(Aptr);
    float4 qa1 = *(const float4*)(Aptr + 8);
    float4 qb0 = *(const float4*)(Wptr);
    float4 qb1 = *(const float4*)(Wptr + 8);

    const int stw = r * 8 + h * 4;   // staging word offset

    for (int k0 = 0; k0 < 512; k0 += 16) {
        const int buf = (k0 >> 4) & 1;
        stage16(As[buf] + stw, qa0, qa1);
        stage16(Bs[buf] + stw, qb0, qb1);
        __syncthreads();

        if (k0 + 16 < 512) {
            qa0 = *(const float4*)(Aptr + k0 + 16);
            qa1 = *(const float4*)(Aptr + k0 + 24);
            qb0 = *(const float4*)(Wptr + k0 + 16);
            qb1 = *(const float4*)(Wptr + k0 + 24);
        }

        uint2 alo[2], ahi[2];
#pragma unroll
        for (int mt = 0; mt < 2; mt++) {
            const uint32_t* ap = As[buf] + (wm + (mt << 4) + g) * 8 + (t << 1);
            alo[mt] = *(const uint2*)ap;
            ahi[mt] = *(const uint2*)(ap + 8 * 8);
        }
#pragma unroll
        for (int nt = 0; nt < 8; nt++) {
            const uint2 bb = *(const uint2*)(Bs[buf] + (wn + (nt << 3) + g) * 8 + (t << 1));
            mma_f16(c[0][nt], alo[0].x, ahi[0].x, alo[0].y, ahi[0].y, bb.x, bb.y);
            mma_f16(c[1][nt], alo[1].x, ahi[1].x, alo[1].y, ahi[1].y, bb.x, bb.y);
        }
        // no trailing sync: next iter stages the OTHER buffer; its sync orders reuse
    }

    if (qm) {
        const int hh = (bn + wn) >> 6;
#pragma unroll
        for (int mt = 0; mt < 2; mt++) {
            const int m0 = bm + wm + (mt << 4) + g;
            const int m1 = m0 + 8;
            float* p0 = g_Q + (size_t)(((((m0 >> 7) << 3) + hh) << 7) + (m0 & 127)) * 64;
            float* p1 = g_Q + (size_t)(((((m1 >> 7) << 3) + hh) << 7) + (m1 & 127)) * 64;
#pragma unroll
            for (int nt = 0; nt < 8; nt++) {
                const int d = (nt << 3) + (t << 1);
                *(float2*)(p0 + d) = make_float2(c[mt][nt][0] * 0.125f, c[mt][nt][1] * 0.125f);
                *(float2*)(p1 + d) = make_float2(c[mt][nt][2] * 0.125f, c[mt][nt][3] * 0.125f);
            }
        }
    } else {
        float* base = (bn >= 512) ? g_V : g_K;
        const int hh = ((bn + wn) >> 6) & 7;
#pragma unroll
        for (int mt = 0; mt < 2; mt++) {
            const int m0 = bm + wm + (mt << 4) + g;
            const int m1 = m0 + 8;
            float* p0 = base + (size_t)(((((m0 >> 9) << 3) + hh) << 9) + (m0 & 511)) * 64;
            float* p1 = base + (size_t)(((((m1 >> 9) << 3) + hh) << 9) + (m1 & 511)) * 64;
#pragma unroll
            for (int nt = 0; nt < 8; nt++) {
                const int d = (nt << 3) + (t << 1);
                *(float2*)(p0 + d) = make_float2(c[mt][nt][0], c[mt][nt][1]);
                *(float2*)(p1 + d) = make_float2(c[mt][nt][2], c[mt][nt][3]);
            }
        }
    }
}

// Output projection: C = g_Att[16384][512] @ W_out[512][512]^T + bias, post-mask
__global__ __launch_bounds__(256, 2) void out_gemm(const float* __restrict__ W,
                                                   const float* __restrict__ bias,
                                                   const void* __restrict__ post_mask,
                                                   float* __restrict__ out) {
    __shared__ uint32_t As[2][128 * 8];
    __shared__ uint32_t Bs[2][128 * 8];

    const int tid  = threadIdx.x;
    const int lane = tid & 31;
    const int wid  = tid >> 5;
    const int g    = lane >> 2;
    const int t    = lane & 3;
    const int wm   = (wid >> 1) << 5;
    const int wn   = (wid & 1) << 6;
    const int bm   = blockIdx.y << 7;
    const int bn   = blockIdx.x << 7;

    const int r = tid >> 1;
    const int h = tid & 1;
    const float* Aptr = g_Att + (size_t)(bm + r) * 512 + (h << 2);
    const float* Wptr = W + (size_t)(bn + r) * 512 + (h << 2);

    float c[2][8][4];
#pragma unroll
    for (int mt = 0; mt < 2; mt++)
#pragma unroll
        for (int nt = 0; nt < 8; nt++)
#pragma unroll
            for (int i = 0; i < 4; i++) c[mt][nt][i] = 0.f;

    float4 qa0 = *(const float4*)(Aptr);
    float4 qa1 = *(const float4*)(Aptr + 8);
    float4 qb0 = *(const float4*)(Wptr);
    float4 qb1 = *(const float4*)(Wptr + 8);

    const int stw = r * 8 + h * 4;

    for (int k0 = 0; k0 < 512; k0 += 16) {
        const int buf = (k0 >> 4) & 1;
        stage16(As[buf] + stw, qa0, qa1);
        stage16(Bs[buf] + stw, qb0, qb1);
        __syncthreads();

        if (k0 + 16 < 512) {
            qa0 = *(const float4*)(Aptr + k0 + 16);
            qa1 = *(const float4*)(Aptr + k0 + 24);
            qb0 = *(const float4*)(Wptr + k0 + 16);
            qb1 = *(const float4*)(Wptr + k0 + 24);
        }

        uint2 alo[2], ahi[2];
#pragma unroll
        for (int mt = 0; mt < 2; mt++) {
            const uint32_t* ap = As[buf] + (wm + (mt << 4) + g) * 8 + (t << 1);
            alo[mt] = *(const uint2*)ap;
            ahi[mt] = *(const uint2*)(ap + 8 * 8);
        }
#pragma unroll
        for (int nt = 0; nt < 8; nt++) {
            const uint2 bb = *(const uint2*)(Bs[buf] + (wn + (nt << 3) + g) * 8 + (t << 1));
            mma_f16(c[0][nt], alo[0].x, ahi[0].x, alo[0].y, ahi[0].y, bb.x, bb.y);
            mma_f16(c[1][nt], alo[1].x, ahi[1].x, alo[1].y, ahi[1].y, bb.x, bb.y);
        }
    }

    const int kind = g_mask_kind;
#pragma unroll
    for (int mt = 0; mt < 2; mt++) {
        const int m0 = bm + wm + (mt << 4) + g;
        const int m1 = m0 + 8;
        const bool pm0 = mask_true(post_mask, m0, kind);
        const bool pm1 = mask_true(post_mask, m1, kind);
        float* p0 = out + (size_t)m0 * 512 + bn + wn;
        float* p1 = out + (size_t)m1 * 512 + bn + wn;
#pragma unroll
        for (int nt = 0; nt < 8; nt++) {
            const int d = (nt << 3) + (t << 1);
            const float2 bb = *(const float2*)&bias[bn + wn + d];
            *(float2*)(p0 + d) = pm0 ? make_float2(0.f, 0.f)
                                     : make_float2(c[mt][nt][0] + bb.x, c[mt][nt][1] + bb.y);
            *(float2*)(p1 + d) = pm1 ? make_float2(0.f, 0.f)
                                     : make_float2(c[mt][nt][2] + bb.x, c[mt][nt][3] + bb.y);
        }
    }
}

// ---------------- K2: flash-style attention, one CTA per (b,h) ----------------
#define SM_STATS_W 8704
#define SM_KV_W    9728
#define ATT_SMEM_WORDS (9728 + 4 * 8704)
#define ATT_SMEM_BYTES (ATT_SMEM_WORDS * 4)

__global__ __launch_bounds__(256) void attn_kernel(const void* __restrict__ pre_mask,
                                                   const float* __restrict__ diff_mask) {
    extern __shared__ uint32_t smw[];
    uint32_t* Qs    = smw;
    float*    stats = (float*)(smw + SM_STATS_W);
    float*    KVbuf = (float*)(smw + SM_KV_W);

    const int tid  = threadIdx.x;
    const int lane = tid & 31;
    const int w    = tid >> 5;
    const int g    = lane >> 2;
    const int t    = lane & 3;
    const int wm   = (w >> 1) << 5;
    const int wn   = (w & 1) << 6;
    const bool odd = (t & 1);

    const int head = blockIdx.x, b = blockIdx.y;
    const int bh = (b << 3) + head;
    const float* Qg = g_Q + (size_t)bh * 128 * 64;
    const float* Kg = g_K + (size_t)bh * 512 * 64;
    const float* Vg = g_V + (size_t)bh * 512 * 64;
    const int kind = g_mask_kind;
    const size_t qrow0 = (size_t)b * 128;
    const float NEG_INF = __int_as_float(0xff800000u);

    {
        float* Kb = KVbuf;
        float* Vb = KVbuf + 8704;
#pragma unroll
        for (int i = 0; i < 8; i++) {
            const int idx = (i << 8) + tid;
            const int key = idx >> 4, d = (idx & 15) << 2;
            uint32_t sK = (uint32_t)__cvta_generic_to_shared(Kb + key * 68 + d);
            uint32_t sV = (uint32_t)__cvta_generic_to_shared(Vb + key * 68 + d);
            asm volatile("cp.async.cg.shared.global [%0], [%1], 16;" :: "r"(sK), "l"(Kg + (key << 6) + d));
            asm volatile("cp.async.cg.shared.global [%0], [%1], 16;" :: "r"(sV), "l"(Vg + (key << 6) + d));
        }
        asm volatile("cp.async.commit_group;");
    }

#pragma unroll
    for (int i = 0; i < 8; i++) {
        const int idx = (i << 8) + tid;
        const int q = idx >> 4, d = (idx & 15) << 2;
        const float4 v = *(const float4*)(Qg + (q << 6) + d);
        uint4 u;
        u.x = f2tf32(v.x); u.y = f2tf32(v.y); u.z = f2tf32(v.z); u.w = f2tf32(v.w);
        *(uint4*)&Qs[q * 68 + d] = u;
    }

    float m[4], E[4], D[4];
#pragma unroll
    for (int r = 0; r < 4; r++) { m[r] = NEG_INF; E[r] = 0.f; D[r] = 0.f; }
    float o[2][8][4];
#pragma unroll
    for (int mt = 0; mt < 2; mt++)
#pragma unroll
        for (int dn = 0; dn < 8; dn++)
#pragma unroll
            for (int i = 0; i < 4; i++) o[mt][dn][i] = 0.f;

    for (int tile = 0; tile < 4; tile++) {
        if (tile < 3) {
            const int nb = (tile + 1) & 1;
            float* Kb = KVbuf + (size_t)(nb * 2 + 0) * 8704;
            float* Vb = KVbuf + (size_t)(nb * 2 + 1) * 8704;
            const float* Kgt = Kg + (size_t)((tile + 1) << 7) * 64;
            const float* Vgt = Vg + (size_t)((tile + 1) << 7) * 64;
#pragma unroll
            for (int i = 0; i < 8; i++) {
                const int idx = (i << 8) + tid;
                const int key = idx >> 4, d = (idx & 15) << 2;
                uint32_t sK = (uint32_t)__cvta_generic_to_shared(Kb + key * 68 + d);
                uint32_t sV = (uint32_t)__cvta_generic_to_shared(Vb + key * 68 + d);
                asm volatile("cp.async.cg.shared.global [%0], [%1], 16;" :: "r"(sK), "l"(Kgt + (key << 6) + d));
                asm volatile("cp.async.cg.shared.global [%0], [%1], 16;" :: "r"(sV), "l"(Vgt + (key << 6) + d));
            }
            asm volatile("cp.async.commit_group;");
            asm volatile("cp.async.wait_group 1;");
        } else {
            asm volatile("cp.async.wait_group 0;");
        }
        __syncthreads();

        const float* Kb = KVbuf + (size_t)((tile & 1) * 2 + 0) * 8704;
        const float* Vb = KVbuf + (size_t)((tile & 1) * 2 + 1) * 8704;

        float2 dmx[4][8];
#pragma unroll
        for (int mt = 0; mt < 2; mt++)
#pragma unroll
            for (int hh = 0; hh < 2; hh++) {
                const int r = mt * 2 + hh;
                const size_t row = qrow0 + wm + (mt << 4) + (hh << 3) + g;
                const size_t base = row * 512 + (tile << 7) + wn + (t << 1);
#pragma unroll
                for (int nt = 0; nt < 8; nt++) {
                    const size_t ix = base + (nt << 3);
                    const float2 d2 = *(const float2*)(diff_mask + ix);
                    bool p0, p1;
                    if (kind == 1) {
                        const uchar2 u = *(const uchar2*)((const unsigned char*)pre_mask + ix);
                        p0 = u.x != 0; p1 = u.y != 0;
                    } else if (kind == 0) {
                        const int2 u = *(const int2*)((const int*)pre_mask + ix);
                        p0 = u.x != 0; p1 = u.y != 0;
                    } else {
                        const float2 u = *(const float2*)((const float*)pre_mask + ix);
                        p0 = u.x != 0.f; p1 = u.y != 0.f;
                    }
                    dmx[r][nt] = make_float2(p0 ? -1.f : d2.x, p1 ? -1.f : d2.y);
                }
            }

        float c[2][8][4];
#pragma unroll
        for (int mt = 0; mt < 2; mt++)
#pragma unroll
            for (int nt = 0; nt < 8; nt++)
#pragma unroll
                for (int i = 0; i < 4; i++) c[mt][nt][i] = 0.f;

#pragma unroll
        for (int ks = 0; ks < 8; ks++) {
            uint32_t afr[2][4];
#pragma unroll
            for (int mt = 0; mt < 2; mt++) {
                const uint32_t* ap = Qs + (wm + (mt << 4) + g) * 68 + (ks << 3) + t;
                afr[mt][0] = ap[0];
                afr[mt][1] = ap[8 * 68];
                afr[mt][2] = ap[4];
                afr[mt][3] = ap[8 * 68 + 4];
            }
#pragma unroll
            for (int nt = 0; nt < 8; nt++) {
                const float* kp = Kb + (wn + (nt << 3) + g) * 68 + (ks << 3) + t;
                const uint32_t b0 = f2tf32(kp[0]), b1 = f2tf32(kp[4]);
                mma_tf32(c[0][nt], afr[0], b0, b1);
                mma_tf32(c[1][nt], afr[1], b0, b1);
            }
        }

#pragma unroll
        for (int mt = 0; mt < 2; mt++)
#pragma unroll
            for (int hh = 0; hh < 2; hh++) {
                const int r = mt * 2 + hh;
                const int s0i = hh * 2, s1i = hh * 2 + 1;
                float tmax = NEG_INF;
#pragma unroll
                for (int nt = 0; nt < 8; nt++) {
                    const float2 dmv = dmx[r][nt];
                    float s0 = (dmv.x < 0.f) ? NEG_INF : c[mt][nt][s0i];
                    float s1 = (dmv.y < 0.f) ? NEG_INF : c[mt][nt][s1i];
                    c[mt][nt][s0i] = s0; c[mt][nt][s1i] = s1;
                    tmax = fmaxf(tmax, fmaxf(s0, s1));
                }
                tmax = fmaxf(tmax, __shfl_xor_sync(0xffffffffu, tmax, 1));
                tmax = fmaxf(tmax, __shfl_xor_sync(0xffffffffu, tmax, 2));
                const float mnew = fmaxf(m[r], tmax);
                const float sc = (m[r] == NEG_INF) ? 0.f : __expf(m[r] - mnew);
                m[r] = mnew;
                E[r] *= sc; D[r] *= sc;
#pragma unroll
                for (int dn = 0; dn < 8; dn++) { o[mt][dn][s0i] *= sc; o[mt][dn][s1i] *= sc; }
                float eacc = 0.f, dacc = 0.f;
#pragma unroll
                for (int nt = 0; nt < 8; nt++) {
                    const float2 dmv = dmx[r][nt];
                    const float s0 = c[mt][nt][s0i], s1 = c[mt][nt][s1i];
                    const float e0 = (s0 == NEG_INF) ? 0.f : __expf(s0 - mnew);
                    const float e1 = (s1 == NEG_INF) ? 0.f : __expf(s1 - mnew);
                    const float w0 = e0 * dmv.x, w1 = e1 * dmv.y;
                    eacc += e0 + e1; dacc += w0 + w1;
                    c[mt][nt][s0i] = w0; c[mt][nt][s1i] = w1;
                }
                E[r] += eacc; D[r] += dacc;
            }

        const int lo = (lane & ~3) | (t >> 1);
        const int hi = lo + 2;
#pragma unroll
        for (int ks = 0; ks < 8; ks++) {
            uint32_t af2[2][4];
#pragma unroll
            for (int mt = 0; mt < 2; mt++) {
                const float s0 = c[mt][ks][0], s1 = c[mt][ks][1];
                const float s2 = c[mt][ks][2], s3 = c[mt][ks][3];
                const float x0 = __shfl_sync(0xffffffffu, s0, lo);
                const float x1 = __shfl_sync(0xffffffffu, s1, lo);
                const float x2 = __shfl_sync(0xffffffffu, s2, lo);
                const float x3 = __shfl_sync(0xffffffffu, s3, lo);
                const float y0 = __shfl_sync(0xffffffffu, s0, hi);
                const float y1 = __shfl_sync(0xffffffffu, s1, hi);
                const float y2 = __shfl_sync(0xffffffffu, s2, hi);
                const float y3 = __shfl_sync(0xffffffffu, s3, hi);
                af2[mt][0] = f2tf32(odd ? x1 : x0);
                af2[mt][1] = f2tf32(odd ? x3 : x2);
                af2[mt][2] = f2tf32(odd ? y1 : y0);
                af2[mt][3] = f2tf32(odd ? y3 : y2);
            }
#pragma unroll
            for (int dn = 0; dn < 8; dn++) {
                const uint32_t b0 = f2tf32(Vb[(wn + (ks << 3) + t) * 68 + (dn << 3) + g]);
                const uint32_t b1 = f2tf32(Vb[(wn + (ks << 3) + t + 4) * 68 + (dn << 3) + g]);
                mma_tf32(o[0][dn], af2[0], b0, b1);
                mma_tf32(o[1][dn], af2[1], b0, b1);
            }
        }
        __syncthreads();
    }

#pragma unroll
    for (int r = 0; r < 4; r++) {
        E[r] += __shfl_xor_sync(0xffffffffu, E[r], 1);
        E[r] += __shfl_xor_sync(0xffffffffu, E[r], 2);
        D[r] += __shfl_xor_sync(0xffffffffu, D[r], 1);
        D[r] += __shfl_xor_sync(0xffffffffu, D[r], 2);
    }
    if (t == 0) {
#pragma unroll
        for (int mt = 0; mt < 2; mt++)
#pragma unroll
            for (int hh = 0; hh < 2; hh++) {
                const int r = mt * 2 + hh;
                float* sp = stats + ((w << 5) + (mt << 4) + (hh << 3) + g) * 4;
                sp[0] = m[r]; sp[1] = E[r]; sp[2] = D[r];
            }
    }
    __syncthreads();

    float fac[4];
#pragma unroll
    for (int mt = 0; mt < 2; mt++)
#pragma unroll
        for (int hh = 0; hh < 2; hh++) {
            const int r = mt * 2 + hh;
            const float* sp = stats + (((w ^ 1) << 5) + (mt << 4) + (hh << 3) + g) * 4;
            const float pm_ = sp[0], pE = sp[1], pD = sp[2];
            const float mt_ = fmaxf(m[r], pm_);
            const float ss = (m[r] == NEG_INF) ? 0.f : __expf(m[r] - mt_);
            const float sq = (pm_ == NEG_INF) ? 0.f : __expf(pm_ - mt_);
            const float Et = ss * E[r] + sq * pE;
            const float Dt = ss * D[r] + sq * pD;
            const float inv = (Et > 0.f) ? 1.f / (Dt + 1e-8f * Et) : 0.f;
            fac[r] = inv * ss;
        }
#pragma unroll
    for (int mt = 0; mt < 2; mt++)
#pragma unroll
        for (int dn = 0; dn < 8; dn++) {
            o[mt][dn][0] *= fac[mt * 2];     o[mt][dn][1] *= fac[mt * 2];
            o[mt][dn][2] *= fac[mt * 2 + 1]; o[mt][dn][3] *= fac[mt * 2 + 1];
        }

    float* Ored = KVbuf;
    if (w & 1) {
#pragma unroll
        for (int mt = 0; mt < 2; mt++) {
            const int q0 = wm + (mt << 4) + g;
#pragma unroll
            for (int dn = 0; dn < 8; dn++) {
                const int d = (dn << 3) + (t << 1);
                *(float2*)&Ored[q0 * 68 + d]       = make_float2(o[mt][dn][0], o[mt][dn][1]);
                *(float2*)&Ored[(q0 + 8) * 68 + d] = make_float2(o[mt][dn][2], o[mt][dn][3]);
            }
        }
    }
    __syncthreads();
    if (!(w & 1)) {
#pragma unroll
        for (int mt = 0; mt < 2; mt++) {
            const int q0 = wm + (mt << 4) + g;
#pragma unroll
            for (int dn = 0; dn < 8; dn++) {
                const int d = (dn << 3) + (t << 1);
                const float2 p0 = *(const float2*)&Ored[q0 * 68 + d];
                const float2 p1 = *(const float2*)&Ored[(q0 + 8) * 68 + d];
                const size_t ob = (qrow0 + q0) * 512 + (head << 6) + d;
                *(float2*)&g_Att[ob]             = make_float2(o[mt][dn][0] + p0.x, o[mt][dn][1] + p0.y);
                *(float2*)&g_Att[ob + 8 * 512]   = make_float2(o[mt][dn][2] + p1.x, o[mt][dn][3] + p1.y);
            }
        }
    }
}

// ---------------- launcher ----------------
extern "C" void kernel_launch(void* const* d_in, const int* in_sizes, int n_in,
                              void* d_out, int out_size) {
    (void)in_sizes; (void)n_in; (void)out_size;
    const float* entities  = (const float*)d_in[0];
    const void*  pre_mask  = d_in[1];
    const float* diff_mask = (const float*)d_in[2];
    const void*  post_mask = d_in[3];
    const float* W_in      = (const float*)d_in[4];
    const float* W_out     = (const float*)d_in[5];
    const float* b_out     = (const float*)d_in[6];
    float* out = (float*)d_out;

    cudaFuncSetAttribute(attn_kernel, cudaFuncAttributeMaxDynamicSharedMemorySize,
                         ATT_SMEM_BYTES);

    detect_mask_kernel<<<1, 32>>>((const unsigned int*)pre_mask);
    qkv_fused<<<dim3(8, 576), 256>>>(entities, W_in);                    // Q + K + V
    attn_kernel<<<dim3(8, 128), 256, ATT_SMEM_BYTES>>>(pre_mask, diff_mask);
    out_gemm<<<dim3(4, 128), 256>>>(W_out, b_out, post_mask, out);
}

// round 13
// speedup vs baseline: 4.4827x; 1.1050x over previous
#include <cuda_runtime.h>
#include <cuda_fp16.h>
#include <cstdint>

// ---------------- scratch (static device globals; no allocation) ----------------
__device__ float  g_Q[128 * 8 * 128 * 64];    // (bs,H,nq,hd)   32 MB
__device__ float  g_K[128 * 8 * 512 * 64];    // (bs,H,ne,hd)  128 MB
__device__ float  g_V[128 * 8 * 512 * 64];    // (bs,H,ne,hd)  128 MB
__device__ __half g_Eh[65536 * 512];          // entities fp16   64 MB
__device__ __half g_Wih[1536 * 512];          // W_in fp16
__device__ __half g_Woh[512 * 512];           // W_out fp16
__device__ __half g_Atth[16384 * 512];        // attn out fp16   16 MB
__device__ int    g_mask_kind;                // 0=int32, 1=uint8, 2=float32

// ---------------- mask dtype handling ----------------
__device__ __forceinline__ bool mask_true(const void* p, size_t i, int kind) {
    if (kind == 1) return ((const unsigned char*)p)[i] != 0;
    if (kind == 0) return ((const int*)p)[i] != 0;
    return ((const float*)p)[i] != 0.0f;
}

__global__ void detect_mask_kernel(const unsigned int* __restrict__ pm) {
    if (threadIdx.x == 0) {
        bool is_i32 = true, is_f32 = true;
        for (int i = 0; i < 64; i++) {
            unsigned int w = pm[i];
            if (w != 0u && w != 1u) is_i32 = false;
            if (w != 0u && w != 0x3F800000u) is_f32 = false;
        }
        g_mask_kind = is_i32 ? 0 : (is_f32 ? 2 : 1);
    }
}

// ---------------- tf32 helpers (attention kernel) ----------------
__device__ __forceinline__ uint32_t f2tf32(float f) {
    uint32_t r;
    asm("cvt.rna.tf32.f32 %0, %1;" : "=r"(r) : "f"(f));
    return r;
}

__device__ __forceinline__ void mma_tf32(float* c, const uint32_t* a,
                                         uint32_t b0, uint32_t b1) {
    asm volatile(
        "mma.sync.aligned.m16n8k8.row.col.f32.tf32.tf32.f32 "
        "{%0,%1,%2,%3}, {%4,%5,%6,%7}, {%8,%9}, {%0,%1,%2,%3};"
        : "+f"(c[0]), "+f"(c[1]), "+f"(c[2]), "+f"(c[3])
        : "r"(a[0]), "r"(a[1]), "r"(a[2]), "r"(a[3]), "r"(b0), "r"(b1));
}

// ---------------- fp16 helpers ----------------
// pack2(a,b): low half = a, high half = b
__device__ __forceinline__ uint32_t pack2(float a, float b) {
    uint32_t r;
    asm("cvt.rn.f16x2.f32 %0, %1, %2;" : "=r"(r) : "f"(b), "f"(a));
    return r;
}

__device__ __forceinline__ void mma_f16(float* c, uint32_t a0, uint32_t a1,
                                        uint32_t a2, uint32_t a3,
                                        uint32_t b0, uint32_t b1) {
    asm volatile(
        "mma.sync.aligned.m16n8k16.row.col.f32.f16.f16.f32 "
        "{%0,%1,%2,%3}, {%4,%5,%6,%7}, {%8,%9}, {%0,%1,%2,%3};"
        : "+f"(c[0]), "+f"(c[1]), "+f"(c[2]), "+f"(c[3])
        : "r"(a0), "r"(a1), "r"(a2), "r"(a3), "r"(b0), "r"(b1));
}

__device__ __forceinline__ void cp16(uint32_t smem_dst, const void* gsrc) {
    asm volatile("cp.async.ca.shared.global [%0], [%1], 16;" :: "r"(smem_dst), "l"(gsrc));
}

// ---------------- pre-pass: fp32 -> fp16 conversion ----------------
#define NE_ELEMS (65536 * 512)
#define WI_ELEMS (1536 * 512)
#define WO_ELEMS (512 * 512)
#define CVT_BLOCKS ((NE_ELEMS + WI_ELEMS + WO_ELEMS) / 8 / 256)

__global__ __launch_bounds__(256) void convert_fp16(const float* __restrict__ ent,
                                                    const float* __restrict__ wi,
                                                    const float* __restrict__ wo) {
    const size_t i = ((size_t)blockIdx.x * 256 + threadIdx.x) * 8;
    const float* src;
    __half* dst;
    if (i < NE_ELEMS)                   { src = ent + i;                       dst = g_Eh  + i; }
    else if (i < NE_ELEMS + WI_ELEMS)   { src = wi + (i - NE_ELEMS);           dst = g_Wih + (i - NE_ELEMS); }
    else                                { src = wo + (i - NE_ELEMS - WI_ELEMS); dst = g_Woh + (i - NE_ELEMS - WI_ELEMS); }
    const float4 f0 = *(const float4*)src;
    const float4 f1 = *(const float4*)(src + 4);
    uint4 u;
    u.x = pack2(f0.x, f0.y); u.y = pack2(f0.z, f0.w);
    u.z = pack2(f1.x, f1.y); u.w = pack2(f1.z, f1.w);
    *(uint4*)dst = u;
}

// ---------------- async fp16 GEMM (natural k-major layout, pitch 12 words) ----------------
// smem row = 16 halves = 8 words, padded to 12 -> LDS.32 conflict-free (row*12 mod 32
// distinct for g=0..7 at both word t and t+4); cp.async dst r*48+h*16 is 16B-aligned.
// 4-stage pipeline, wait_group 2 => 3 stages in flight.

// Fused QKV projection:
//   blocks y <  512 : KV mode  C[65536][1024], W rows 512.. -> g_K/g_V
//   blocks y >= 512 : Q  mode  C[16384][512] (A rows b*512+q) -> g_Q (x0.125)
__global__ __launch_bounds__(256, 2) void qkv_fused(int dummy) {
    __shared__ uint32_t S[4][2][128 * 12];

    const int tid  = threadIdx.x;
    const int lane = tid & 31;
    const int wid  = tid >> 5;
    const int g    = lane >> 2;
    const int t    = lane & 3;
    const int wm   = (wid >> 1) << 5;
    const int wn   = (wid & 1) << 6;

    const bool qm = (blockIdx.y >= 512);
    int bm, bn;
    size_t woff;
    if (!qm) {
        bm = blockIdx.y << 7;
        bn = blockIdx.x << 7;
        woff = (size_t)512 * 512;
    } else {
        const int idx = ((blockIdx.y - 512) << 3) + blockIdx.x;   // 0..511
        bm = (idx >> 2) << 7;
        bn = (idx & 3) << 7;
        woff = 0;
    }

    const int r = tid >> 1;          // staged row
    const int h = tid & 1;           // 16B half of the row's k16
    int arow = bm + r;
    if (qm) arow = ((arow >> 7) << 9) | (arow & 127);     // b*512 + q
    const __half* Ag = g_Eh + (size_t)arow * 512 + (h << 3);
    const __half* Wg = g_Wih + woff + (size_t)(bn + r) * 512 + (h << 3);
    const int dstw = r * 12 + h * 4;

    uint32_t dA[4], dB[4];
#pragma unroll
    for (int b_ = 0; b_ < 4; b_++) {
        dA[b_] = (uint32_t)__cvta_generic_to_shared(&S[b_][0][dstw]);
        dB[b_] = (uint32_t)__cvta_generic_to_shared(&S[b_][1][dstw]);
    }

    // prologue: stages 0..2
#pragma unroll
    for (int s = 0; s < 3; s++) {
        cp16(dA[s], Ag + s * 16);
        cp16(dB[s], Wg + s * 16);
        asm volatile("cp.async.commit_group;");
    }

    float c[2][8][4];
#pragma unroll
    for (int mt = 0; mt < 2; mt++)
#pragma unroll
        for (int nt = 0; nt < 8; nt++)
#pragma unroll
            for (int i = 0; i < 4; i++) c[mt][nt][i] = 0.f;

    for (int s = 0; s < 32; s++) {
        asm volatile("cp.async.wait_group 2;");
        __syncthreads();
        if (s < 29) {
            const int ns = s + 3;
            cp16(dA[ns & 3], Ag + ns * 16);
            cp16(dB[ns & 3], Wg + ns * 16);
        }
        asm volatile("cp.async.commit_group;");   // empty group at tail keeps count uniform

        const uint32_t* Ab = S[s & 3][0];
        const uint32_t* Bb = S[s & 3][1];
        uint32_t a0[2], a1[2], a2[2], a3[2];
#pragma unroll
        for (int mt = 0; mt < 2; mt++) {
            const uint32_t* ap = Ab + (wm + (mt << 4) + g) * 12 + t;
            a0[mt] = ap[0];
            a2[mt] = ap[4];
            a1[mt] = ap[96];       // +8 rows
            a3[mt] = ap[100];
        }
#pragma unroll
        for (int nt = 0; nt < 8; nt++) {
            const uint32_t* bp = Bb + (wn + (nt << 3) + g) * 12 + t;
            const uint32_t b0 = bp[0], b1 = bp[4];
            mma_f16(c[0][nt], a0[0], a1[0], a2[0], a3[0], b0, b1);
            mma_f16(c[1][nt], a0[1], a1[1], a2[1], a3[1], b0, b1);
        }
    }

    if (qm) {
        const int hh = (bn + wn) >> 6;
#pragma unroll
        for (int mt = 0; mt < 2; mt++) {
            const int m0 = bm + wm + (mt << 4) + g;
            const int m1 = m0 + 8;
            float* p0 = g_Q + (size_t)(((((m0 >> 7) << 3) + hh) << 7) + (m0 & 127)) * 64;
            float* p1 = g_Q + (size_t)(((((m1 >> 7) << 3) + hh) << 7) + (m1 & 127)) * 64;
#pragma unroll
            for (int nt = 0; nt < 8; nt++) {
                const int d = (nt << 3) + (t << 1);
                *(float2*)(p0 + d) = make_float2(c[mt][nt][0] * 0.125f, c[mt][nt][1] * 0.125f);
                *(float2*)(p1 + d) = make_float2(c[mt][nt][2] * 0.125f, c[mt][nt][3] * 0.125f);
            }
        }
    } else {
        float* base = (bn >= 512) ? g_V : g_K;
        const int hh = ((bn + wn) >> 6) & 7;
#pragma unroll
        for (int mt = 0; mt < 2; mt++) {
            const int m0 = bm + wm + (mt << 4) + g;
            const int m1 = m0 + 8;
            float* p0 = base + (size_t)(((((m0 >> 9) << 3) + hh) << 9) + (m0 & 511)) * 64;
            float* p1 = base + (size_t)(((((m1 >> 9) << 3) + hh) << 9) + (m1 & 511)) * 64;
#pragma unroll
            for (int nt = 0; nt < 8; nt++) {
                const int d = (nt << 3) + (t << 1);
                *(float2*)(p0 + d) = make_float2(c[mt][nt][0], c[mt][nt][1]);
                *(float2*)(p1 + d) = make_float2(c[mt][nt][2], c[mt][nt][3]);
            }
        }
    }
    (void)dummy;
}

// Output projection: C = g_Atth[16384][512] @ g_Woh[512][512]^T + bias, post-mask
__global__ __launch_bounds__(256, 2) void out_gemm(const float* __restrict__ bias,
                                                   const void* __restrict__ post_mask,
                                                   float* __restrict__ out) {
    __shared__ uint32_t S[4][2][128 * 12];

    const int tid  = threadIdx.x;
    const int lane = tid & 31;
    const int wid  = tid >> 5;
    const int g    = lane >> 2;
    const int t    = lane & 3;
    const int wm   = (wid >> 1) << 5;
    const int wn   = (wid & 1) << 6;
    const int bm   = blockIdx.y << 7;
    const int bn   = blockIdx.x << 7;

    const int r = tid >> 1;
    const int h = tid & 1;
    const __half* Ag = g_Atth + (size_t)(bm + r) * 512 + (h << 3);
    const __half* Wg = g_Woh + (size_t)(bn + r) * 512 + (h << 3);
    const int dstw = r * 12 + h * 4;

    uint32_t dA[4], dB[4];
#pragma unroll
    for (int b_ = 0; b_ < 4; b_++) {
        dA[b_] = (uint32_t)__cvta_generic_to_shared(&S[b_][0][dstw]);
        dB[b_] = (uint32_t)__cvta_generic_to_shared(&S[b_][1][dstw]);
    }

#pragma unroll
    for (int s = 0; s < 3; s++) {
        cp16(dA[s], Ag + s * 16);
        cp16(dB[s], Wg + s * 16);
        asm volatile("cp.async.commit_group;");
    }

    float c[2][8][4];
#pragma unroll
    for (int mt = 0; mt < 2; mt++)
#pragma unroll
        for (int nt = 0; nt < 8; nt++)
#pragma unroll
            for (int i = 0; i < 4; i++) c[mt][nt][i] = 0.f;

    for (int s = 0; s < 32; s++) {
        asm volatile("cp.async.wait_group 2;");
        __syncthreads();
        if (s < 29) {
            const int ns = s + 3;
            cp16(dA[ns & 3], Ag + ns * 16);
            cp16(dB[ns & 3], Wg + ns * 16);
        }
        asm volatile("cp.async.commit_group;");

        const uint32_t* Ab = S[s & 3][0];
        const uint32_t* Bb = S[s & 3][1];
        uint32_t a0[2], a1[2], a2[2], a3[2];
#pragma unroll
        for (int mt = 0; mt < 2; mt++) {
            const uint32_t* ap = Ab + (wm + (mt << 4) + g) * 12 + t;
            a0[mt] = ap[0];
            a2[mt] = ap[4];
            a1[mt] = ap[96];
            a3[mt] = ap[100];
        }
#pragma unroll
        for (int nt = 0; nt < 8; nt++) {
            const uint32_t* bp = Bb + (wn + (nt << 3) + g) * 12 + t;
            const uint32_t b0 = bp[0], b1 = bp[4];
            mma_f16(c[0][nt], a0[0], a1[0], a2[0], a3[0], b0, b1);
            mma_f16(c[1][nt], a0[1], a1[1], a2[1], a3[1], b0, b1);
        }
    }

    const int kind = g_mask_kind;
#pragma unroll
    for (int mt = 0; mt < 2; mt++) {
        const int m0 = bm + wm + (mt << 4) + g;
        const int m1 = m0 + 8;
        const bool pm0 = mask_true(post_mask, m0, kind);
        const bool pm1 = mask_true(post_mask, m1, kind);
        float* p0 = out + (size_t)m0 * 512 + bn + wn;
        float* p1 = out + (size_t)m1 * 512 + bn + wn;
#pragma unroll
        for (int nt = 0; nt < 8; nt++) {
            const int d = (nt << 3) + (t << 1);
            const float2 bb = *(const float2*)&bias[bn + wn + d];
            *(float2*)(p0 + d) = pm0 ? make_float2(0.f, 0.f)
                                     : make_float2(c[mt][nt][0] + bb.x, c[mt][nt][1] + bb.y);
            *(float2*)(p1 + d) = pm1 ? make_float2(0.f, 0.f)
                                     : make_float2(c[mt][nt][2] + bb.x, c[mt][nt][3] + bb.y);
        }
    }
}

// ---------------- K2: flash-style attention, one CTA per (b,h) ----------------
#define SM_STATS_W 8704
#define SM_KV_W    9728
#define ATT_SMEM_WORDS (9728 + 4 * 8704)
#define ATT_SMEM_BYTES (ATT_SMEM_WORDS * 4)

__global__ __launch_bounds__(256) void attn_kernel(const void* __restrict__ pre_mask,
                                                   const float* __restrict__ diff_mask) {
    extern __shared__ uint32_t smw[];
    uint32_t* Qs    = smw;
    float*    stats = (float*)(smw + SM_STATS_W);
    float*    KVbuf = (float*)(smw + SM_KV_W);

    const int tid  = threadIdx.x;
    const int lane = tid & 31;
    const int w    = tid >> 5;
    const int g    = lane >> 2;
    const int t    = lane & 3;
    const int wm   = (w >> 1) << 5;
    const int wn   = (w & 1) << 6;
    const bool odd = (t & 1);

    const int head = blockIdx.x, b = blockIdx.y;
    const int bh = (b << 3) + head;
    const float* Qg = g_Q + (size_t)bh * 128 * 64;
    const float* Kg = g_K + (size_t)bh * 512 * 64;
    const float* Vg = g_V + (size_t)bh * 512 * 64;
    const int kind = g_mask_kind;
    const size_t qrow0 = (size_t)b * 128;
    const float NEG_INF = __int_as_float(0xff800000u);

    {
        float* Kb = KVbuf;
        float* Vb = KVbuf + 8704;
#pragma unroll
        for (int i = 0; i < 8; i++) {
            const int idx = (i << 8) + tid;
            const int key = idx >> 4, d = (idx & 15) << 2;
            uint32_t sK = (uint32_t)__cvta_generic_to_shared(Kb + key * 68 + d);
            uint32_t sV = (uint32_t)__cvta_generic_to_shared(Vb + key * 68 + d);
            asm volatile("cp.async.cg.shared.global [%0], [%1], 16;" :: "r"(sK), "l"(Kg + (key << 6) + d));
            asm volatile("cp.async.cg.shared.global [%0], [%1], 16;" :: "r"(sV), "l"(Vg + (key << 6) + d));
        }
        asm volatile("cp.async.commit_group;");
    }

#pragma unroll
    for (int i = 0; i < 8; i++) {
        const int idx = (i << 8) + tid;
        const int q = idx >> 4, d = (idx & 15) << 2;
        const float4 v = *(const float4*)(Qg + (q << 6) + d);
        uint4 u;
        u.x = f2tf32(v.x); u.y = f2tf32(v.y); u.z = f2tf32(v.z); u.w = f2tf32(v.w);
        *(uint4*)&Qs[q * 68 + d] = u;
    }

    float m[4], E[4], D[4];
#pragma unroll
    for (int r = 0; r < 4; r++) { m[r] = NEG_INF; E[r] = 0.f; D[r] = 0.f; }
    float o[2][8][4];
#pragma unroll
    for (int mt = 0; mt < 2; mt++)
#pragma unroll
        for (int dn = 0; dn < 8; dn++)
#pragma unroll
            for (int i = 0; i < 4; i++) o[mt][dn][i] = 0.f;

    for (int tile = 0; tile < 4; tile++) {
        if (tile < 3) {
            const int nb = (tile + 1) & 1;
            float* Kb = KVbuf + (size_t)(nb * 2 + 0) * 8704;
            float* Vb = KVbuf + (size_t)(nb * 2 + 1) * 8704;
            const float* Kgt = Kg + (size_t)((tile + 1) << 7) * 64;
            const float* Vgt = Vg + (size_t)((tile + 1) << 7) * 64;
#pragma unroll
            for (int i = 0; i < 8; i++) {
                const int idx = (i << 8) + tid;
                const int key = idx >> 4, d = (idx & 15) << 2;
                uint32_t sK = (uint32_t)__cvta_generic_to_shared(Kb + key * 68 + d);
                uint32_t sV = (uint32_t)__cvta_generic_to_shared(Vb + key * 68 + d);
                asm volatile("cp.async.cg.shared.global [%0], [%1], 16;" :: "r"(sK), "l"(Kgt + (key << 6) + d));
                asm volatile("cp.async.cg.shared.global [%0], [%1], 16;" :: "r"(sV), "l"(Vgt + (key << 6) + d));
            }
            asm volatile("cp.async.commit_group;");
            asm volatile("cp.async.wait_group 1;");
        } else {
            asm volatile("cp.async.wait_group 0;");
        }
        __syncthreads();

        const float* Kb = KVbuf + (size_t)((tile & 1) * 2 + 0) * 8704;
        const float* Vb = KVbuf + (size_t)((tile & 1) * 2 + 1) * 8704;

        float2 dmx[4][8];
#pragma unroll
        for (int mt = 0; mt < 2; mt++)
#pragma unroll
            for (int hh = 0; hh < 2; hh++) {
                const int r = mt * 2 + hh;
                const size_t row = qrow0 + wm + (mt << 4) + (hh << 3) + g;
                const size_t base = row * 512 + (tile << 7) + wn + (t << 1);
#pragma unroll
                for (int nt = 0; nt < 8; nt++) {
                    const size_t ix = base + (nt << 3);
                    const float2 d2 = *(const float2*)(diff_mask + ix);
                    bool p0, p1;
                    if (kind == 1) {
                        const uchar2 u = *(const uchar2*)((const unsigned char*)pre_mask + ix);
                        p0 = u.x != 0; p1 = u.y != 0;
                    } else if (kind == 0) {
                        const int2 u = *(const int2*)((const int*)pre_mask + ix);
                        p0 = u.x != 0; p1 = u.y != 0;
                    } else {
                        const float2 u = *(const float2*)((const float*)pre_mask + ix);
                        p0 = u.x != 0.f; p1 = u.y != 0.f;
                    }
                    dmx[r][nt] = make_float2(p0 ? -1.f : d2.x, p1 ? -1.f : d2.y);
                }
            }

        float c[2][8][4];
#pragma unroll
        for (int mt = 0; mt < 2; mt++)
#pragma unroll
            for (int nt = 0; nt < 8; nt++)
#pragma unroll
                for (int i = 0; i < 4; i++) c[mt][nt][i] = 0.f;

#pragma unroll
        for (int ks = 0; ks < 8; ks++) {
            uint32_t afr[2][4];
#pragma unroll
            for (int mt = 0; mt < 2; mt++) {
                const uint32_t* ap = Qs + (wm + (mt << 4) + g) * 68 + (ks << 3) + t;
                afr[mt][0] = ap[0];
                afr[mt][1] = ap[8 * 68];
                afr[mt][2] = ap[4];
                afr[mt][3] = ap[8 * 68 + 4];
            }
#pragma unroll
            for (int nt = 0; nt < 8; nt++) {
                const float* kp = Kb + (wn + (nt << 3) + g) * 68 + (ks << 3) + t;
                const uint32_t b0 = f2tf32(kp[0]), b1 = f2tf32(kp[4]);
                mma_tf32(c[0][nt], afr[0], b0, b1);
                mma_tf32(c[1][nt], afr[1], b0, b1);
            }
        }

#pragma unroll
        for (int mt = 0; mt < 2; mt++)
#pragma unroll
            for (int hh = 0; hh < 2; hh++) {
                const int r = mt * 2 + hh;
                const int s0i = hh * 2, s1i = hh * 2 + 1;
                float tmax = NEG_INF;
#pragma unroll
                for (int nt = 0; nt < 8; nt++) {
                    const float2 dmv = dmx[r][nt];
                    float s0 = (dmv.x < 0.f) ? NEG_INF : c[mt][nt][s0i];
                    float s1 = (dmv.y < 0.f) ? NEG_INF : c[mt][nt][s1i];
                    c[mt][nt][s0i] = s0; c[mt][nt][s1i] = s1;
                    tmax = fmaxf(tmax, fmaxf(s0, s1));
                }
                tmax = fmaxf(tmax, __shfl_xor_sync(0xffffffffu, tmax, 1));
                tmax = fmaxf(tmax, __shfl_xor_sync(0xffffffffu, tmax, 2));
                const float mnew = fmaxf(m[r], tmax);
                const float sc = (m[r] == NEG_INF) ? 0.f : __expf(m[r] - mnew);
                m[r] = mnew;
                E[r] *= sc; D[r] *= sc;
#pragma unroll
                for (int dn = 0; dn < 8; dn++) { o[mt][dn][s0i] *= sc; o[mt][dn][s1i] *= sc; }
                float eacc = 0.f, dacc = 0.f;
#pragma unroll
                for (int nt = 0; nt < 8; nt++) {
                    const float2 dmv = dmx[r][nt];
                    const float s0 = c[mt][nt][s0i], s1 = c[mt][nt][s1i];
                    const float e0 = (s0 == NEG_INF) ? 0.f : __expf(s0 - mnew);
                    const float e1 = (s1 == NEG_INF) ? 0.f : __expf(s1 - mnew);
                    const float w0 = e0 * dmv.x, w1 = e1 * dmv.y;
                    eacc += e0 + e1; dacc += w0 + w1;
                    c[mt][nt][s0i] = w0; c[mt][nt][s1i] = w1;
                }
                E[r] += eacc; D[r] += dacc;
            }

        const int lo = (lane & ~3) | (t >> 1);
        const int hi = lo + 2;
#pragma unroll
        for (int ks = 0; ks < 8; ks++) {
            uint32_t af2[2][4];
#pragma unroll
            for (int mt = 0; mt < 2; mt++) {
                const float s0 = c[mt][ks][0], s1 = c[mt][ks][1];
                const float s2 = c[mt][ks][2], s3 = c[mt][ks][3];
                const float x0 = __shfl_sync(0xffffffffu, s0, lo);
                const float x1 = __shfl_sync(0xffffffffu, s1, lo);
                const float x2 = __shfl_sync(0xffffffffu, s2, lo);
                const float x3 = __shfl_sync(0xffffffffu, s3, lo);
                const float y0 = __shfl_sync(0xffffffffu, s0, hi);
                const float y1 = __shfl_sync(0xffffffffu, s1, hi);
                const float y2 = __shfl_sync(0xffffffffu, s2, hi);
                const float y3 = __shfl_sync(0xffffffffu, s3, hi);
                af2[mt][0] = f2tf32(odd ? x1 : x0);
                af2[mt][1] = f2tf32(odd ? x3 : x2);
                af2[mt][2] = f2tf32(odd ? y1 : y0);
                af2[mt][3] = f2tf32(odd ? y3 : y2);
            }
#pragma unroll
            for (int dn = 0; dn < 8; dn++) {
                const uint32_t b0 = f2tf32(Vb[(wn + (ks << 3) + t) * 68 + (dn << 3) + g]);
                const uint32_t b1 = f2tf32(Vb[(wn + (ks << 3) + t + 4) * 68 + (dn << 3) + g]);
                mma_tf32(o[0][dn], af2[0], b0, b1);
                mma_tf32(o[1][dn], af2[1], b0, b1);
            }
        }
        __syncthreads();
    }

#pragma unroll
    for (int r = 0; r < 4; r++) {
        E[r] += __shfl_xor_sync(0xffffffffu, E[r], 1);
        E[r] += __shfl_xor_sync(0xffffffffu, E[r], 2);
        D[r] += __shfl_xor_sync(0xffffffffu, D[r], 1);
        D[r] += __shfl_xor_sync(0xffffffffu, D[r], 2);
    }
    if (t == 0) {
#pragma unroll
        for (int mt = 0; mt < 2; mt++)
#pragma unroll
            for (int hh = 0; hh < 2; hh++) {
                const int r = mt * 2 + hh;
                float* sp = stats + ((w << 5) + (mt << 4) + (hh << 3) + g) * 4;
                sp[0] = m[r]; sp[1] = E[r]; sp[2] = D[r];
            }
    }
    __syncthreads();

    float fac[4];
#pragma unroll
    for (int mt = 0; mt < 2; mt++)
#pragma unroll
        for (int hh = 0; hh < 2; hh++) {
            const int r = mt * 2 + hh;
            const float* sp = stats + (((w ^ 1) << 5) + (mt << 4) + (hh << 3) + g) * 4;
            const float pm_ = sp[0], pE = sp[1], pD = sp[2];
            const float mt_ = fmaxf(m[r], pm_);
            const float ss = (m[r] == NEG_INF) ? 0.f : __expf(m[r] - mt_);
            const float sq = (pm_ == NEG_INF) ? 0.f : __expf(pm_ - mt_);
            const float Et = ss * E[r] + sq * pE;
            const float Dt = ss * D[r] + sq * pD;
            const float inv = (Et > 0.f) ? 1.f / (Dt + 1e-8f * Et) : 0.f;
            fac[r] = inv * ss;
        }
#pragma unroll
    for (int mt = 0; mt < 2; mt++)
#pragma unroll
        for (int dn = 0; dn < 8; dn++) {
            o[mt][dn][0] *= fac[mt * 2];     o[mt][dn][1] *= fac[mt * 2];
            o[mt][dn][2] *= fac[mt * 2 + 1]; o[mt][dn][3] *= fac[mt * 2 + 1];
        }

    float* Ored = KVbuf;
    if (w & 1) {
#pragma unroll
        for (int mt = 0; mt < 2; mt++) {
            const int q0 = wm + (mt << 4) + g;
#pragma unroll
            for (int dn = 0; dn < 8; dn++) {
                const int d = (dn << 3) + (t << 1);
                *(float2*)&Ored[q0 * 68 + d]       = make_float2(o[mt][dn][0], o[mt][dn][1]);
                *(float2*)&Ored[(q0 + 8) * 68 + d] = make_float2(o[mt][dn][2], o[mt][dn][3]);
            }
        }
    }
    __syncthreads();
    if (!(w & 1)) {
        uint32_t* Ah = (uint32_t*)g_Atth;
#pragma unroll
        for (int mt = 0; mt < 2; mt++) {
            const int q0 = wm + (mt << 4) + g;
#pragma unroll
            for (int dn = 0; dn < 8; dn++) {
                const int d = (dn << 3) + (t << 1);
                const float2 p0 = *(const float2*)&Ored[q0 * 68 + d];
                const float2 p1 = *(const float2*)&Ored[(q0 + 8) * 68 + d];
                const size_t ob = (qrow0 + q0) * 512 + (head << 6) + d;   // even
                Ah[ob >> 1]            = pack2(o[mt][dn][0] + p0.x, o[mt][dn][1] + p0.y);
                Ah[(ob + 4096) >> 1]   = pack2(o[mt][dn][2] + p1.x, o[mt][dn][3] + p1.y);
            }
        }
    }
}

// ---------------- launcher ----------------
extern "C" void kernel_launch(void* const* d_in, const int* in_sizes, int n_in,
                              void* d_out, int out_size) {
    (void)in_sizes; (void)n_in; (void)out_size;
    const float* entities  = (const float*)d_in[0];
    const void*  pre_mask  = d_in[1];
    const float* diff_mask = (const float*)d_in[2];
    const void*  post_mask = d_in[3];
    const float* W_in      = (const float*)d_in[4];
    const float* W_out     = (const float*)d_in[5];
    const float* b_out     = (const float*)d_in[6];
    float* out = (float*)d_out;

    cudaFuncSetAttribute(attn_kernel, cudaFuncAttributeMaxDynamicSharedMemorySize,
                         ATT_SMEM_BYTES);

    detect_mask_kernel<<<1, 32>>>((const unsigned int*)pre_mask);
    convert_fp16<<<CVT_BLOCKS, 256>>>(entities, W_in, W_out);
    qkv_fused<<<dim3(8, 576), 256>>>(0);                                  // Q + K + V
    attn_kernel<<<dim3(8, 128), 256, ATT_SMEM_BYTES>>>(pre_mask, diff_mask);
    out_gemm<<<dim3(4, 128), 256>>>(b_out, post_mask, out);
}

// round 14
// speedup vs baseline: 5.0444x; 1.1253x over previous
#include <cuda_runtime.h>
#include <cuda_fp16.h>
#include <cstdint>

// ---------------- scratch (static device globals; no allocation) ----------------
__device__ __half g_Qh[128 * 8 * 128 * 64];   // (bs,H,nq,hd)  16 MB
__device__ __half g_Kh[128 * 8 * 512 * 64];   // (bs,H,ne,hd)  64 MB
__device__ __half g_Vh[128 * 8 * 512 * 64];   // (bs,H,ne,hd)  64 MB
__device__ __half g_Eh[65536 * 512];          // entities fp16  64 MB
__device__ __half g_Wih[1536 * 512];          // W_in fp16
__device__ __half g_Woh[512 * 512];           // W_out fp16
__device__ __half g_Atth[16384 * 512];        // attn out fp16  16 MB
__device__ int    g_mask_kind;                // 0=int32, 1=uint8, 2=float32

// ---------------- mask dtype handling ----------------
__device__ __forceinline__ bool mask_true(const void* p, size_t i, int kind) {
    if (kind == 1) return ((const unsigned char*)p)[i] != 0;
    if (kind == 0) return ((const int*)p)[i] != 0;
    return ((const float*)p)[i] != 0.0f;
}

__global__ void detect_mask_kernel(const unsigned int* __restrict__ pm) {
    if (threadIdx.x == 0) {
        bool is_i32 = true, is_f32 = true;
        for (int i = 0; i < 64; i++) {
            unsigned int w = pm[i];
            if (w != 0u && w != 1u) is_i32 = false;
            if (w != 0u && w != 0x3F800000u) is_f32 = false;
        }
        g_mask_kind = is_i32 ? 0 : (is_f32 ? 2 : 1);
    }
}

// ---------------- fp16 helpers ----------------
// pack2(a,b): low half = a, high half = b
__device__ __forceinline__ uint32_t pack2(float a, float b) {
    uint32_t r;
    asm("cvt.rn.f16x2.f32 %0, %1, %2;" : "=r"(r) : "f"(b), "f"(a));
    return r;
}

__device__ __forceinline__ void mma_f16(float* c, uint32_t a0, uint32_t a1,
                                        uint32_t a2, uint32_t a3,
                                        uint32_t b0, uint32_t b1) {
    asm volatile(
        "mma.sync.aligned.m16n8k16.row.col.f32.f16.f16.f32 "
        "{%0,%1,%2,%3}, {%4,%5,%6,%7}, {%8,%9}, {%0,%1,%2,%3};"
        : "+f"(c[0]), "+f"(c[1]), "+f"(c[2]), "+f"(c[3])
        : "r"(a0), "r"(a1), "r"(a2), "r"(a3), "r"(b0), "r"(b1));
}

__device__ __forceinline__ void cp16(uint32_t smem_dst, const void* gsrc) {
    asm volatile("cp.async.ca.shared.global [%0], [%1], 16;" :: "r"(smem_dst), "l"(gsrc));
}

// ---------------- pre-pass: fp32 -> fp16 conversion ----------------
#define NE_ELEMS (65536 * 512)
#define WI_ELEMS (1536 * 512)
#define WO_ELEMS (512 * 512)
#define CVT_BLOCKS ((NE_ELEMS + WI_ELEMS + WO_ELEMS) / 8 / 256)

__global__ __launch_bounds__(256) void convert_fp16(const float* __restrict__ ent,
                                                    const float* __restrict__ wi,
                                                    const float* __restrict__ wo) {
    const size_t i = ((size_t)blockIdx.x * 256 + threadIdx.x) * 8;
    const float* src;
    __half* dst;
    if (i < NE_ELEMS)                   { src = ent + i;                        dst = g_Eh  + i; }
    else if (i < NE_ELEMS + WI_ELEMS)   { src = wi + (i - NE_ELEMS);            dst = g_Wih + (i - NE_ELEMS); }
    else                                { src = wo + (i - NE_ELEMS - WI_ELEMS); dst = g_Woh + (i - NE_ELEMS - WI_ELEMS); }
    const float4 f0 = *(const float4*)src;
    const float4 f1 = *(const float4*)(src + 4);
    uint4 u;
    u.x = pack2(f0.x, f0.y); u.y = pack2(f0.z, f0.w);
    u.z = pack2(f1.x, f1.y); u.w = pack2(f1.z, f1.w);
    *(uint4*)dst = u;
}

// ---------------- async fp16 GEMM (natural k-major layout, pitch 12 words) ----------------
// Fused QKV projection:
//   blocks y <  512 : KV mode  C[65536][1024] -> g_Kh/g_Vh (fp16)
//   blocks y >= 512 : Q  mode  C[16384][512] (A rows b*512+q) -> g_Qh (x0.125, fp16)
__global__ __launch_bounds__(256, 2) void qkv_fused(int dummy) {
    __shared__ uint32_t S[4][2][128 * 12];

    const int tid  = threadIdx.x;
    const int lane = tid & 31;
    const int wid  = tid >> 5;
    const int g    = lane >> 2;
    const int t    = lane & 3;
    const int wm   = (wid >> 1) << 5;
    const int wn   = (wid & 1) << 6;

    const bool qm = (blockIdx.y >= 512);
    int bm, bn;
    size_t woff;
    if (!qm) {
        bm = blockIdx.y << 7;
        bn = blockIdx.x << 7;
        woff = (size_t)512 * 512;
    } else {
        const int idx = ((blockIdx.y - 512) << 3) + blockIdx.x;   // 0..511
        bm = (idx >> 2) << 7;
        bn = (idx & 3) << 7;
        woff = 0;
    }

    const int r = tid >> 1;
    const int h = tid & 1;
    int arow = bm + r;
    if (qm) arow = ((arow >> 7) << 9) | (arow & 127);     // b*512 + q
    const __half* Ag = g_Eh + (size_t)arow * 512 + (h << 3);
    const __half* Wg = g_Wih + woff + (size_t)(bn + r) * 512 + (h << 3);
    const int dstw = r * 12 + h * 4;

    uint32_t dA[4], dB[4];
#pragma unroll
    for (int b_ = 0; b_ < 4; b_++) {
        dA[b_] = (uint32_t)__cvta_generic_to_shared(&S[b_][0][dstw]);
        dB[b_] = (uint32_t)__cvta_generic_to_shared(&S[b_][1][dstw]);
    }

#pragma unroll
    for (int s = 0; s < 3; s++) {
        cp16(dA[s], Ag + s * 16);
        cp16(dB[s], Wg + s * 16);
        asm volatile("cp.async.commit_group;");
    }

    float c[2][8][4];
#pragma unroll
    for (int mt = 0; mt < 2; mt++)
#pragma unroll
        for (int nt = 0; nt < 8; nt++)
#pragma unroll
            for (int i = 0; i < 4; i++) c[mt][nt][i] = 0.f;

    for (int s = 0; s < 32; s++) {
        asm volatile("cp.async.wait_group 2;");
        __syncthreads();
        if (s < 29) {
            const int ns = s + 3;
            cp16(dA[ns & 3], Ag + ns * 16);
            cp16(dB[ns & 3], Wg + ns * 16);
        }
        asm volatile("cp.async.commit_group;");

        const uint32_t* Ab = S[s & 3][0];
        const uint32_t* Bb = S[s & 3][1];
        uint32_t a0[2], a1[2], a2[2], a3[2];
#pragma unroll
        for (int mt = 0; mt < 2; mt++) {
            const uint32_t* ap = Ab + (wm + (mt << 4) + g) * 12 + t;
            a0[mt] = ap[0];
            a2[mt] = ap[4];
            a1[mt] = ap[96];
            a3[mt] = ap[100];
        }
#pragma unroll
        for (int nt = 0; nt < 8; nt++) {
            const uint32_t* bp = Bb + (wn + (nt << 3) + g) * 12 + t;
            const uint32_t b0 = bp[0], b1 = bp[4];
            mma_f16(c[0][nt], a0[0], a1[0], a2[0], a3[0], b0, b1);
            mma_f16(c[1][nt], a0[1], a1[1], a2[1], a3[1], b0, b1);
        }
    }

    if (qm) {
        const int hh = (bn + wn) >> 6;
        uint32_t* Qw = (uint32_t*)g_Qh;
#pragma unroll
        for (int mt = 0; mt < 2; mt++) {
            const int m0 = bm + wm + (mt << 4) + g;
            const int m1 = m0 + 8;
            const size_t i0 = (size_t)(((((m0 >> 7) << 3) + hh) << 7) + (m0 & 127)) * 64;
            const size_t i1 = (size_t)(((((m1 >> 7) << 3) + hh) << 7) + (m1 & 127)) * 64;
#pragma unroll
            for (int nt = 0; nt < 8; nt++) {
                const int d = (nt << 3) + (t << 1);
                Qw[(i0 + d) >> 1] = pack2(c[mt][nt][0] * 0.125f, c[mt][nt][1] * 0.125f);
                Qw[(i1 + d) >> 1] = pack2(c[mt][nt][2] * 0.125f, c[mt][nt][3] * 0.125f);
            }
        }
    } else {
        uint32_t* basew = (uint32_t*)((bn >= 512) ? g_Vh : g_Kh);
        const int hh = ((bn + wn) >> 6) & 7;
#pragma unroll
        for (int mt = 0; mt < 2; mt++) {
            const int m0 = bm + wm + (mt << 4) + g;
            const int m1 = m0 + 8;
            const size_t i0 = (size_t)(((((m0 >> 9) << 3) + hh) << 9) + (m0 & 511)) * 64;
            const size_t i1 = (size_t)(((((m1 >> 9) << 3) + hh) << 9) + (m1 & 511)) * 64;
#pragma unroll
            for (int nt = 0; nt < 8; nt++) {
                const int d = (nt << 3) + (t << 1);
                basew[(i0 + d) >> 1] = pack2(c[mt][nt][0], c[mt][nt][1]);
                basew[(i1 + d) >> 1] = pack2(c[mt][nt][2], c[mt][nt][3]);
            }
        }
    }
    (void)dummy;
}

// Output projection: C = g_Atth[16384][512] @ g_Woh[512][512]^T + bias, post-mask
__global__ __launch_bounds__(256, 2) void out_gemm(const float* __restrict__ bias,
                                                   const void* __restrict__ post_mask,
                                                   float* __restrict__ out) {
    __shared__ uint32_t S[4][2][128 * 12];

    const int tid  = threadIdx.x;
    const int lane = tid & 31;
    const int wid  = tid >> 5;
    const int g    = lane >> 2;
    const int t    = lane & 3;
    const int wm   = (wid >> 1) << 5;
    const int wn   = (wid & 1) << 6;
    const int bm   = blockIdx.y << 7;
    const int bn   = blockIdx.x << 7;

    const int r = tid >> 1;
    const int h = tid & 1;
    const __half* Ag = g_Atth + (size_t)(bm + r) * 512 + (h << 3);
    const __half* Wg = g_Woh + (size_t)(bn + r) * 512 + (h << 3);
    const int dstw = r * 12 + h * 4;

    uint32_t dA[4], dB[4];
#pragma unroll
    for (int b_ = 0; b_ < 4; b_++) {
        dA[b_] = (uint32_t)__cvta_generic_to_shared(&S[b_][0][dstw]);
        dB[b_] = (uint32_t)__cvta_generic_to_shared(&S[b_][1][dstw]);
    }

#pragma unroll
    for (int s = 0; s < 3; s++) {
        cp16(dA[s], Ag + s * 16);
        cp16(dB[s], Wg + s * 16);
        asm volatile("cp.async.commit_group;");
    }

    float c[2][8][4];
#pragma unroll
    for (int mt = 0; mt < 2; mt++)
#pragma unroll
        for (int nt = 0; nt < 8; nt++)
#pragma unroll
            for (int i = 0; i < 4; i++) c[mt][nt][i] = 0.f;

    for (int s = 0; s < 32; s++) {
        asm volatile("cp.async.wait_group 2;");
        __syncthreads();
        if (s < 29) {
            const int ns = s + 3;
            cp16(dA[ns & 3], Ag + ns * 16);
            cp16(dB[ns & 3], Wg + ns * 16);
        }
        asm volatile("cp.async.commit_group;");

        const uint32_t* Ab = S[s & 3][0];
        const uint32_t* Bb = S[s & 3][1];
        uint32_t a0[2], a1[2], a2[2], a3[2];
#pragma unroll
        for (int mt = 0; mt < 2; mt++) {
            const uint32_t* ap = Ab + (wm + (mt << 4) + g) * 12 + t;
            a0[mt] = ap[0];
            a2[mt] = ap[4];
            a1[mt] = ap[96];
            a3[mt] = ap[100];
        }
#pragma unroll
        for (int nt = 0; nt < 8; nt++) {
            const uint32_t* bp = Bb + (wn + (nt << 3) + g) * 12 + t;
            const uint32_t b0 = bp[0], b1 = bp[4];
            mma_f16(c[0][nt], a0[0], a1[0], a2[0], a3[0], b0, b1);
            mma_f16(c[1][nt], a0[1], a1[1], a2[1], a3[1], b0, b1);
        }
    }

    const int kind = g_mask_kind;
#pragma unroll
    for (int mt = 0; mt < 2; mt++) {
        const int m0 = bm + wm + (mt << 4) + g;
        const int m1 = m0 + 8;
        const bool pm0 = mask_true(post_mask, m0, kind);
        const bool pm1 = mask_true(post_mask, m1, kind);
        float* p0 = out + (size_t)m0 * 512 + bn + wn;
        float* p1 = out + (size_t)m1 * 512 + bn + wn;
#pragma unroll
        for (int nt = 0; nt < 8; nt++) {
            const int d = (nt << 3) + (t << 1);
            const float2 bb = *(const float2*)&bias[bn + wn + d];
            *(float2*)(p0 + d) = pm0 ? make_float2(0.f, 0.f)
                                     : make_float2(c[mt][nt][0] + bb.x, c[mt][nt][1] + bb.y);
            *(float2*)(p1 + d) = pm1 ? make_float2(0.f, 0.f)
                                     : make_float2(c[mt][nt][2] + bb.x, c[mt][nt][3] + bb.y);
        }
    }
}

// ---------------- K2: fp16 flash attention, one CTA per (b,h) ----------------
// smem (words): Qs [128][36] fp16 rows (64 halves + pad)  4608
//               stats [8][32][4] f32                      1024
//               KVbuf [2 bufs][K,V][128][36]             18432
#define AQ_W   0
#define AST_W  4608
#define AKV_W  5632
#define ATT_SMEM_WORDS (5632 + 4 * 4608)
#define ATT_SMEM_BYTES (ATT_SMEM_WORDS * 4)

__global__ __launch_bounds__(256) void attn_kernel(const void* __restrict__ pre_mask,
                                                   const float* __restrict__ diff_mask) {
    extern __shared__ uint32_t smw[];
    uint32_t* Qs    = smw + AQ_W;
    float*    stats = (float*)(smw + AST_W);
    uint32_t* KVbuf = smw + AKV_W;

    const int tid  = threadIdx.x;
    const int lane = tid & 31;
    const int w    = tid >> 5;
    const int g    = lane >> 2;
    const int t    = lane & 3;
    const int wm   = (w >> 1) << 5;    // query offset 0/32/64/96
    const int wn   = (w & 1) << 6;     // key offset within tile 0/64

    const int head = blockIdx.x, b = blockIdx.y;
    const int bh = (b << 3) + head;
    const __half* Qg = g_Qh + (size_t)bh * 128 * 64;
    const __half* Kg = g_Kh + (size_t)bh * 512 * 64;
    const __half* Vg = g_Vh + (size_t)bh * 512 * 64;
    const int kind = g_mask_kind;
    const size_t qrow0 = (size_t)b * 128;
    const float NEG_INF = __int_as_float(0xff800000u);

    // smem u32 base addresses of the 4 tile buffers (each 4608 words; order K0,V0,K1,V1)
    uint32_t bufa[4];
#pragma unroll
    for (int i = 0; i < 4; i++)
        bufa[i] = (uint32_t)__cvta_generic_to_shared(KVbuf + i * 4608);

    // ---- prologue: tile 0 K/V via cp.async (4 chunks each per thread) ----
#pragma unroll
    for (int i = 0; i < 4; i++) {
        const int idx = (i << 8) + tid;           // 0..1023
        const int key = idx >> 3, ch = idx & 7;
        const int dw = (key * 36 + (ch << 2)) << 2;
        cp16(bufa[0] + dw, Kg + (key << 6) + (ch << 3));
        cp16(bufa[1] + dw, Vg + (key << 6) + (ch << 3));
    }
    asm volatile("cp.async.commit_group;");

    // ---- stage Q (plain loads; one-time) ----
#pragma unroll
    for (int i = 0; i < 4; i++) {
        const int idx = (i << 8) + tid;
        const int q = idx >> 3, ch = idx & 7;
        const uint4 v = *(const uint4*)(Qg + (q << 6) + (ch << 3));
        *(uint4*)&Qs[q * 36 + (ch << 2)] = v;
    }

    float m[4], E[4], D[4];
#pragma unroll
    for (int r = 0; r < 4; r++) { m[r] = NEG_INF; E[r] = 0.f; D[r] = 0.f; }
    float o[2][8][4];
#pragma unroll
    for (int mt = 0; mt < 2; mt++)
#pragma unroll
        for (int dn = 0; dn < 8; dn++)
#pragma unroll
            for (int i = 0; i < 4; i++) o[mt][dn][i] = 0.f;

    for (int tile = 0; tile < 4; tile++) {
        if (tile < 3) {
            const int nb = (tile + 1) & 1;
            const __half* Kgt = Kg + (size_t)((tile + 1) << 7) * 64;
            const __half* Vgt = Vg + (size_t)((tile + 1) << 7) * 64;
#pragma unroll
            for (int i = 0; i < 4; i++) {
                const int idx = (i << 8) + tid;
                const int key = idx >> 3, ch = idx & 7;
                const int dw = (key * 36 + (ch << 2)) << 2;
                cp16(bufa[nb * 2 + 0] + dw, Kgt + (key << 6) + (ch << 3));
                cp16(bufa[nb * 2 + 1] + dw, Vgt + (key << 6) + (ch << 3));
            }
            asm volatile("cp.async.commit_group;");
            asm volatile("cp.async.wait_group 1;");
        } else {
            asm volatile("cp.async.wait_group 0;");
        }
        __syncthreads();

        const uint32_t* Kb = KVbuf + (size_t)((tile & 1) * 2 + 0) * 4608;
        const uint32_t  Vb_base = bufa[(tile & 1) * 2 + 1]
                                + (((wn + (lane & 15)) * 36 + ((lane & 16) ? 4 : 0)) << 2);

        // ---- preload masks ----
        float2 dmx[4][8];
#pragma unroll
        for (int mt = 0; mt < 2; mt++)
#pragma unroll
            for (int hh = 0; hh < 2; hh++) {
                const int r = mt * 2 + hh;
                const size_t row = qrow0 + wm + (mt << 4) + (hh << 3) + g;
                const size_t base = row * 512 + (tile << 7) + wn + (t << 1);
#pragma unroll
                for (int nt = 0; nt < 8; nt++) {
                    const size_t ix = base + (nt << 3);
                    const float2 d2 = *(const float2*)(diff_mask + ix);
                    bool p0, p1;
                    if (kind == 1) {
                        const uchar2 u = *(const uchar2*)((const unsigned char*)pre_mask + ix);
                        p0 = u.x != 0; p1 = u.y != 0;
                    } else if (kind == 0) {
                        const int2 u = *(const int2*)((const int*)pre_mask + ix);
                        p0 = u.x != 0; p1 = u.y != 0;
                    } else {
                        const float2 u = *(const float2*)((const float*)pre_mask + ix);
                        p0 = u.x != 0.f; p1 = u.y != 0.f;
                    }
                    dmx[r][nt] = make_float2(p0 ? -1.f : d2.x, p1 ? -1.f : d2.y);
                }
            }

        // ---- S = Q @ K^T (fp16 m16n8k16, 4 k-steps over d=64) ----
        float c[2][8][4];
#pragma unroll
        for (int mt = 0; mt < 2; mt++)
#pragma unroll
            for (int nt = 0; nt < 8; nt++)
#pragma unroll
                for (int i = 0; i < 4; i++) c[mt][nt][i] = 0.f;

#pragma unroll
        for (int ks = 0; ks < 4; ks++) {
            uint32_t a0[2], a1[2], a2[2], a3[2];
#pragma unroll
            for (int mt = 0; mt < 2; mt++) {
                const uint32_t* ap = Qs + (wm + (mt << 4) + g) * 36 + (ks << 3) + t;
                a0[mt] = ap[0];
                a2[mt] = ap[4];
                a1[mt] = ap[288];      // +8 rows * 36
                a3[mt] = ap[292];
            }
#pragma unroll
            for (int nt = 0; nt < 8; nt++) {
                const uint32_t* bp = Kb + (wn + (nt << 3) + g) * 36 + (ks << 3) + t;
                const uint32_t b0 = bp[0], b1 = bp[4];
                mma_f16(c[0][nt], a0[0], a1[0], a2[0], a3[0], b0, b1);
                mma_f16(c[1][nt], a0[1], a1[1], a2[1], a3[1], b0, b1);
            }
        }

        // ---- online softmax update ----
#pragma unroll
        for (int mt = 0; mt < 2; mt++)
#pragma unroll
            for (int hh = 0; hh < 2; hh++) {
                const int r = mt * 2 + hh;
                const int s0i = hh * 2, s1i = hh * 2 + 1;
                float tmax = NEG_INF;
#pragma unroll
                for (int nt = 0; nt < 8; nt++) {
                    const float2 dmv = dmx[r][nt];
                    float s0 = (dmv.x < 0.f) ? NEG_INF : c[mt][nt][s0i];
                    float s1 = (dmv.y < 0.f) ? NEG_INF : c[mt][nt][s1i];
                    c[mt][nt][s0i] = s0; c[mt][nt][s1i] = s1;
                    tmax = fmaxf(tmax, fmaxf(s0, s1));
                }
                tmax = fmaxf(tmax, __shfl_xor_sync(0xffffffffu, tmax, 1));
                tmax = fmaxf(tmax, __shfl_xor_sync(0xffffffffu, tmax, 2));
                const float mnew = fmaxf(m[r], tmax);
                const float sc = (m[r] == NEG_INF) ? 0.f : __expf(m[r] - mnew);
                m[r] = mnew;
                E[r] *= sc; D[r] *= sc;
#pragma unroll
                for (int dn = 0; dn < 8; dn++) { o[mt][dn][s0i] *= sc; o[mt][dn][s1i] *= sc; }
                float eacc = 0.f, dacc = 0.f;
#pragma unroll
                for (int nt = 0; nt < 8; nt++) {
                    const float2 dmv = dmx[r][nt];
                    const float s0 = c[mt][nt][s0i], s1 = c[mt][nt][s1i];
                    const float e0 = (s0 == NEG_INF) ? 0.f : __expf(s0 - mnew);
                    const float e1 = (s1 == NEG_INF) ? 0.f : __expf(s1 - mnew);
                    const float w0 = e0 * dmv.x, w1 = e1 * dmv.y;
                    eacc += e0 + e1; dacc += w0 + w1;
                    c[mt][nt][s0i] = w0; c[mt][nt][s1i] = w1;
                }
                E[r] += eacc; D[r] += dacc;
            }

        // ---- O += wd @ V : S-accum fragments ARE the A-fragments; V via ldmatrix.trans ----
#pragma unroll
        for (int ks = 0; ks < 4; ks++) {
            uint32_t aa[2][4];
#pragma unroll
            for (int mt = 0; mt < 2; mt++) {
                aa[mt][0] = pack2(c[mt][2 * ks][0],     c[mt][2 * ks][1]);
                aa[mt][1] = pack2(c[mt][2 * ks][2],     c[mt][2 * ks][3]);
                aa[mt][2] = pack2(c[mt][2 * ks + 1][0], c[mt][2 * ks + 1][1]);
                aa[mt][3] = pack2(c[mt][2 * ks + 1][2], c[mt][2 * ks + 1][3]);
            }
#pragma unroll
            for (int dn2 = 0; dn2 < 4; dn2++) {
                uint32_t r0, r1, r2, r3;
                const uint32_t addr = Vb_base + (((ks << 4) * 36 + (dn2 << 3)) << 2);
                asm volatile(
                    "ldmatrix.sync.aligned.m8n8.x4.trans.shared.b16 {%0,%1,%2,%3}, [%4];"
                    : "=r"(r0), "=r"(r1), "=r"(r2), "=r"(r3) : "r"(addr));
                mma_f16(o[0][2 * dn2],     aa[0][0], aa[0][1], aa[0][2], aa[0][3], r0, r1);
                mma_f16(o[0][2 * dn2 + 1], aa[0][0], aa[0][1], aa[0][2], aa[0][3], r2, r3);
                mma_f16(o[1][2 * dn2],     aa[1][0], aa[1][1], aa[1][2], aa[1][3], r0, r1);
                mma_f16(o[1][2 * dn2 + 1], aa[1][0], aa[1][1], aa[1][2], aa[1][3], r2, r3);
            }
        }
        __syncthreads();
    }

    // ---- merge stats across the two warp columns ----
#pragma unroll
    for (int r = 0; r < 4; r++) {
        E[r] += __shfl_xor_sync(0xffffffffu, E[r], 1);
        E[r] += __shfl_xor_sync(0xffffffffu, E[r], 2);
        D[r] += __shfl_xor_sync(0xffffffffu, D[r], 1);
        D[r] += __shfl_xor_sync(0xffffffffu, D[r], 2);
    }
    if (t == 0) {
#pragma unroll
        for (int mt = 0; mt < 2; mt++)
#pragma unroll
            for (int hh = 0; hh < 2; hh++) {
                const int r = mt * 2 + hh;
                float* sp = stats + ((w << 5) + (mt << 4) + (hh << 3) + g) * 4;
                sp[0] = m[r]; sp[1] = E[r]; sp[2] = D[r];
            }
    }
    __syncthreads();

    float fac[4];
#pragma unroll
    for (int mt = 0; mt < 2; mt++)
#pragma unroll
        for (int hh = 0; hh < 2; hh++) {
            const int r = mt * 2 + hh;
            const float* sp = stats + (((w ^ 1) << 5) + (mt << 4) + (hh << 3) + g) * 4;
            const float pm_ = sp[0], pE = sp[1], pD = sp[2];
            const float mt_ = fmaxf(m[r], pm_);
            const float ss = (m[r] == NEG_INF) ? 0.f : __expf(m[r] - mt_);
            const float sq = (pm_ == NEG_INF) ? 0.f : __expf(pm_ - mt_);
            const float Et = ss * E[r] + sq * pE;
            const float Dt = ss * D[r] + sq * pD;
            const float inv = (Et > 0.f) ? 1.f / (Dt + 1e-8f * Et) : 0.f;
            fac[r] = inv * ss;
        }
#pragma unroll
    for (int mt = 0; mt < 2; mt++)
#pragma unroll
        for (int dn = 0; dn < 8; dn++) {
            o[mt][dn][0] *= fac[mt * 2];     o[mt][dn][1] *= fac[mt * 2];
            o[mt][dn][2] *= fac[mt * 2 + 1]; o[mt][dn][3] *= fac[mt * 2 + 1];
        }

    // ---- reduce O across the warp-column pair; write g_Atth (fp16) ----
    float* Ored = (float*)KVbuf;   // [128][68] f32 fits in KVbuf
    if (w & 1) {
#pragma unroll
        for (int mt = 0; mt < 2; mt++) {
            const int q0 = wm + (mt << 4) + g;
#pragma unroll
            for (int dn = 0; dn < 8; dn++) {
                const int d = (dn << 3) + (t << 1);
                *(float2*)&Ored[q0 * 68 + d]       = make_float2(o[mt][dn][0], o[mt][dn][1]);
                *(float2*)&Ored[(q0 + 8) * 68 + d] = make_float2(o[mt][dn][2], o[mt][dn][3]);
            }
        }
    }
    __syncthreads();
    if (!(w & 1)) {
        uint32_t* Ah = (uint32_t*)g_Atth;
#pragma unroll
        for (int mt = 0; mt < 2; mt++) {
            const int q0 = wm + (mt << 4) + g;
#pragma unroll
            for (int dn = 0; dn < 8; dn++) {
                const int d = (dn << 3) + (t << 1);
                const float2 p0 = *(const float2*)&Ored[q0 * 68 + d];
                const float2 p1 = *(const float2*)&Ored[(q0 + 8) * 68 + d];
                const size_t ob = (qrow0 + q0) * 512 + (head << 6) + d;
                Ah[ob >> 1]          = pack2(o[mt][dn][0] + p0.x, o[mt][dn][1] + p0.y);
                Ah[(ob + 4096) >> 1] = pack2(o[mt][dn][2] + p1.x, o[mt][dn][3] + p1.y);
            }
        }
    }
}

// ---------------- launcher ----------------
extern "C" void kernel_launch(void* const* d_in, const int* in_sizes, int n_in,
                              void* d_out, int out_size) {
    (void)in_sizes; (void)n_in; (void)out_size;
    const float* entities  = (const float*)d_in[0];
    const void*  pre_mask  = d_in[1];
    const float* diff_mask = (const float*)d_in[2];
    const void*  post_mask = d_in[3];
    const float* W_in      = (const float*)d_in[4];
    const float* W_out     = (const float*)d_in[5];
    const float* b_out     = (const float*)d_in[6];
    float* out = (float*)d_out;

    cudaFuncSetAttribute(attn_kernel, cudaFuncAttributeMaxDynamicSharedMemorySize,
                         ATT_SMEM_BYTES);

    detect_mask_kernel<<<1, 32>>>((const unsigned int*)pre_mask);
    convert_fp16<<<CVT_BLOCKS, 256>>>(entities, W_in, W_out);
    qkv_fused<<<dim3(8, 576), 256>>>(0);                                  // Q + K + V
    attn_kernel<<<dim3(8, 128), 256, ATT_SMEM_BYTES>>>(pre_mask, diff_mask);
    out_gemm<<<dim3(4, 128), 256>>>(b_out, post_mask, out);
}